// round 1
// baseline (speedup 1.0000x reference)
#include <cuda_runtime.h>
#include <math.h>

#define BB 16
#define INC 512
#define OUTC 256
#define HH 32
#define WW 32
#define FD 1024
#define DK 128
#define NS 14          // interior samples (B-2)
#define OH 64
#define OW 64

// ---------------- scratch (static device memory; no allocation) ----------------
__device__ float g_mid[NS * INC * FD];        // rotatory outputs for batches 1..14
__device__ float g_q[NS * INC * DK];
__device__ float g_kl[NS * INC * DK];
__device__ float g_kr[NS * INC * DK];
__device__ float g_kvl[NS * DK * FD];
__device__ float g_kvr[NS * DK * FD];
__device__ float g_z[2 * NS * INC];           // [side][sample][row]
__device__ float g_gate[BB * OUTC * OH * OW]; // gated branch (first 256 channels of cat)
__device__ float g_y[BB * OUTC * OH * OW];    // conv3x3 pre-BN output
__device__ float g_bnsum[OUTC];
__device__ float g_bnsq[OUTC];
__device__ float g_bnscale[OUTC];
__device__ float g_bnshift[OUTC];

// ---------------- kernel 1: projections q/kl/kr = phi(A @ W) ----------------
// A: (512,1024) slice of x; W: (1024,128). Tile 64x64, K-chunk 16, 4x4 per thread.
__global__ __launch_bounds__(256) void proj_kernel(
    const float* __restrict__ x, const float* __restrict__ wq,
    const float* __restrict__ wkl, const float* __restrict__ wkr) {
    int zi = blockIdx.z;
    int sample = zi / 3, p = zi % 3;
    const float* A;
    const float* Wm;
    float* C;
    if (p == 0)      { A = x + (size_t)(sample + 1) * INC * FD; Wm = wq;  C = g_q  + (size_t)sample * INC * DK; }
    else if (p == 1) { A = x + (size_t)(sample + 0) * INC * FD; Wm = wkl; C = g_kl + (size_t)sample * INC * DK; }
    else             { A = x + (size_t)(sample + 2) * INC * FD; Wm = wkr; C = g_kr + (size_t)sample * INC * DK; }

    __shared__ float As[16][68];
    __shared__ float Bs[16][64];
    int m0 = blockIdx.x * 64;
    int n0 = blockIdx.y * 64;
    int tid = threadIdx.y * 16 + threadIdx.x;
    float acc[4][4] = {};
    for (int k0 = 0; k0 < FD; k0 += 16) {
#pragma unroll
        for (int it = 0; it < 4; it++) {
            int idx = it * 256 + tid;
            int m = idx >> 4, kk = idx & 15;
            As[kk][m] = A[(m0 + m) * FD + k0 + kk];
        }
#pragma unroll
        for (int it = 0; it < 4; it++) {
            int idx = it * 256 + tid;
            int kk = idx >> 6, n = idx & 63;
            Bs[kk][n] = Wm[(k0 + kk) * DK + n0 + n];
        }
        __syncthreads();
#pragma unroll
        for (int kk = 0; kk < 16; kk++) {
            float4 a4 = *(const float4*)&As[kk][threadIdx.y * 4];
            float4 b4 = *(const float4*)&Bs[kk][threadIdx.x * 4];
            float a[4] = {a4.x, a4.y, a4.z, a4.w};
            float b[4] = {b4.x, b4.y, b4.z, b4.w};
#pragma unroll
            for (int i = 0; i < 4; i++)
#pragma unroll
                for (int j = 0; j < 4; j++) acc[i][j] += a[i] * b[j];
        }
        __syncthreads();
    }
#pragma unroll
    for (int i = 0; i < 4; i++) {
        int m = m0 + threadIdx.y * 4 + i;
#pragma unroll
        for (int j = 0; j < 4; j++) {
            int n = n0 + threadIdx.x * 4 + j;
            float v = acc[i][j];
            C[m * DK + n] = (v > 0.f) ? (v + 1.f) : expf(v);  // elu(v)+1
        }
    }
}

// ---------------- kernel 2: column sums + z = q @ ksum + 1e-6 ----------------
__global__ void sumz_kernel() {
    int sample = blockIdx.x;
    int side = blockIdx.y;  // 0=l, 1=r
    const float* K = (side == 0 ? g_kl : g_kr) + (size_t)sample * INC * DK;
    const float* Q = g_q + (size_t)sample * INC * DK;
    __shared__ float ssum[DK];
    int t = threadIdx.x;  // 128 threads
    float s = 0.f;
    for (int n = 0; n < INC; n++) s += K[n * DK + t];
    ssum[t] = s;
    __syncthreads();
    float* Z = g_z + (size_t)(side * NS + sample) * INC;
    for (int rr = 0; rr < 4; rr++) {
        int row = rr * 128 + t;
        float d = 0.f;
        for (int k = 0; k < DK; k++) d += Q[row * DK + k] * ssum[k];
        Z[row] = d + 1e-6f;
    }
}

// ---------------- kernel 3: kv[k][d] = sum_n K[n][k] * V[n][d] ----------------
__global__ __launch_bounds__(256) void kv_kernel(const float* __restrict__ x) {
    int zi = blockIdx.z;
    int sample = zi >> 1, side = zi & 1;
    const float* K = (side == 0 ? g_kl : g_kr) + (size_t)sample * INC * DK;
    const float* V = x + (size_t)(sample + (side == 0 ? 0 : 2)) * INC * FD;
    float* C = (side == 0 ? g_kvl : g_kvr) + (size_t)sample * DK * FD;
    __shared__ float As[16][68];  // [nn][k]
    __shared__ float Bs[16][64];  // [nn][d]
    int m0 = blockIdx.x * 64;  // k dim (128)
    int n0 = blockIdx.y * 64;  // d dim (1024)
    int tid = threadIdx.y * 16 + threadIdx.x;
    float acc[4][4] = {};
    for (int c0 = 0; c0 < INC; c0 += 16) {
#pragma unroll
        for (int it = 0; it < 4; it++) {
            int idx = it * 256 + tid;
            int nn = idx >> 6, k = idx & 63;
            As[nn][k] = K[(c0 + nn) * DK + m0 + k];
        }
#pragma unroll
        for (int it = 0; it < 4; it++) {
            int idx = it * 256 + tid;
            int nn = idx >> 6, d = idx & 63;
            Bs[nn][d] = V[(c0 + nn) * FD + n0 + d];
        }
        __syncthreads();
#pragma unroll
        for (int nn = 0; nn < 16; nn++) {
            float4 a4 = *(const float4*)&As[nn][threadIdx.y * 4];
            float4 b4 = *(const float4*)&Bs[nn][threadIdx.x * 4];
            float a[4] = {a4.x, a4.y, a4.z, a4.w};
            float b[4] = {b4.x, b4.y, b4.z, b4.w};
#pragma unroll
            for (int i = 0; i < 4; i++)
#pragma unroll
                for (int j = 0; j < 4; j++) acc[i][j] += a[i] * b[j];
        }
        __syncthreads();
    }
#pragma unroll
    for (int i = 0; i < 4; i++) {
        int m = m0 + threadIdx.y * 4 + i;
#pragma unroll
        for (int j = 0; j < 4; j++) {
            int d = n0 + threadIdx.x * 4 + j;
            C[m * FD + d] = acc[i][j];
        }
    }
}

// ------ kernel 4: out = x + (q@kvl)/zl + (q@kvr)/zr  (dual-B GEMM, K=128) ------
__global__ __launch_bounds__(256) void attnout_kernel(const float* __restrict__ x) {
    int sample = blockIdx.z;
    const float* Q = g_q + (size_t)sample * INC * DK;
    const float* KVL = g_kvl + (size_t)sample * DK * FD;
    const float* KVR = g_kvr + (size_t)sample * DK * FD;
    const float* Zl = g_z + (size_t)sample * INC;
    const float* Zr = g_z + (size_t)(NS + sample) * INC;
    const float* X = x + (size_t)(sample + 1) * INC * FD;
    float* C = g_mid + (size_t)sample * INC * FD;
    __shared__ float As[16][68];
    __shared__ float Bl[16][64];
    __shared__ float Br[16][64];
    int m0 = blockIdx.x * 64;
    int n0 = blockIdx.y * 64;
    int tid = threadIdx.y * 16 + threadIdx.x;
    float accl[4][4] = {}, accr[4][4] = {};
    for (int k0 = 0; k0 < DK; k0 += 16) {
#pragma unroll
        for (int it = 0; it < 4; it++) {
            int idx = it * 256 + tid;
            int m = idx >> 4, kk = idx & 15;
            As[kk][m] = Q[(m0 + m) * DK + k0 + kk];
        }
#pragma unroll
        for (int it = 0; it < 4; it++) {
            int idx = it * 256 + tid;
            int kk = idx >> 6, n = idx & 63;
            Bl[kk][n] = KVL[(k0 + kk) * FD + n0 + n];
            Br[kk][n] = KVR[(k0 + kk) * FD + n0 + n];
        }
        __syncthreads();
#pragma unroll
        for (int kk = 0; kk < 16; kk++) {
            float4 a4 = *(const float4*)&As[kk][threadIdx.y * 4];
            float4 bl4 = *(const float4*)&Bl[kk][threadIdx.x * 4];
            float4 br4 = *(const float4*)&Br[kk][threadIdx.x * 4];
            float a[4] = {a4.x, a4.y, a4.z, a4.w};
            float bl[4] = {bl4.x, bl4.y, bl4.z, bl4.w};
            float br[4] = {br4.x, br4.y, br4.z, br4.w};
#pragma unroll
            for (int i = 0; i < 4; i++)
#pragma unroll
                for (int j = 0; j < 4; j++) {
                    accl[i][j] += a[i] * bl[j];
                    accr[i][j] += a[i] * br[j];
                }
        }
        __syncthreads();
    }
#pragma unroll
    for (int i = 0; i < 4; i++) {
        int m = m0 + threadIdx.y * 4 + i;
        float zl = Zl[m], zr = Zr[m];
#pragma unroll
        for (int j = 0; j < 4; j++) {
            int d = n0 + threadIdx.x * 4 + j;
            C[m * FD + d] = X[m * FD + d] + accl[i][j] / zl + accr[i][j] / zr;
        }
    }
}

// ------ kernel 5: ConvTranspose 2x2 s2 as GEMM + fused gate sigmoid(relu(up+s)) ------
// C[(o,ab)][ij] = sum_c upw[c][(o,ab)] * src[c][ij]
__global__ __launch_bounds__(256) void convt_kernel(
    const float* __restrict__ x, const float* __restrict__ upw,
    const float* __restrict__ upb, const float* __restrict__ s) {
    int n = blockIdx.z;
    const float* src = (n == 0) ? x
                     : (n == BB - 1) ? (x + (size_t)(BB - 1) * INC * FD)
                     : (g_mid + (size_t)(n - 1) * INC * FD);
    __shared__ float As[16][68];  // [cc][wcol]
    __shared__ float Bs[16][64];  // [cc][ij]
    int m0 = blockIdx.x * 64;  // wcol over 1024 = o*4+ab
    int n0 = blockIdx.y * 64;  // ij over 1024
    int tid = threadIdx.y * 16 + threadIdx.x;
    float acc[4][4] = {};
    for (int c0 = 0; c0 < INC; c0 += 16) {
#pragma unroll
        for (int it = 0; it < 4; it++) {
            int idx = it * 256 + tid;
            int cc = idx >> 6, m = idx & 63;
            As[cc][m] = upw[(c0 + cc) * 1024 + m0 + m];
        }
#pragma unroll
        for (int it = 0; it < 4; it++) {
            int idx = it * 256 + tid;
            int cc = idx >> 6, d = idx & 63;
            Bs[cc][d] = src[(c0 + cc) * FD + n0 + d];
        }
        __syncthreads();
#pragma unroll
        for (int cc = 0; cc < 16; cc++) {
            float4 a4 = *(const float4*)&As[cc][threadIdx.y * 4];
            float4 b4 = *(const float4*)&Bs[cc][threadIdx.x * 4];
            float a[4] = {a4.x, a4.y, a4.z, a4.w};
            float b[4] = {b4.x, b4.y, b4.z, b4.w};
#pragma unroll
            for (int i = 0; i < 4; i++)
#pragma unroll
                for (int j = 0; j < 4; j++) acc[i][j] += a[i] * b[j];
        }
        __syncthreads();
    }
#pragma unroll
    for (int i = 0; i < 4; i++) {
        int row = m0 + threadIdx.y * 4 + i;
        int o = row >> 2, ab = row & 3, a = ab >> 1, bq = ab & 1;
        float bias = upb[o];
#pragma unroll
        for (int j = 0; j < 4; j++) {
            int col = n0 + threadIdx.x * 4 + j;
            int isp = col >> 5, jsp = col & 31;
            int oy = 2 * isp + a, ox = 2 * jsp + bq;
            size_t gi = (((size_t)n * OUTC + o) * OH + oy) * OW + ox;
            float v = acc[i][j] + bias + s[gi];
            v = v > 0.f ? v : 0.f;
            g_gate[gi] = 1.f / (1.f + expf(-v));
        }
    }
}

// ---------------- kernel 6: conv3x3(cat=[gate,s]) + bias + BN partial sums ----------------
#define ICCH 8
__global__ __launch_bounds__(256) void conv_kernel(
    const float* __restrict__ sskip, const float* __restrict__ cw,
    const float* __restrict__ cb) {
    int n = blockIdx.z;
    int oc0 = blockIdx.y * 64;
    int st = blockIdx.x;                 // 64 spatial tiles (8x8 px each)
    int y0 = (st >> 3) * 8, x0 = (st & 7) * 8;
    __shared__ float in_s[ICCH][10][13];
    __shared__ float w_s[ICCH * 9 * 68];  // (icc*9+k)*68 + oc
    __shared__ float rs[64], rq[64];
    int tx = threadIdx.x, ty = threadIdx.y;
    int tid = ty * 16 + tx;
    int p = tx * 4;
    int dy = p >> 3, dx = p & 7;  // dy 0..7, dx in {0,4}
    float acc[4][4] = {};
    for (int ic0 = 0; ic0 < 2 * OUTC; ic0 += ICCH) {
        // input patch: ICCH ic x 10x10 (halo 1, zero pad)
        for (int e = tid; e < ICCH * 100; e += 256) {
            int icc = e / 100, rem = e % 100;
            int yy = rem / 10, xx = rem % 10;
            int gy = y0 + yy - 1, gx = x0 + xx - 1;
            int ic = ic0 + icc;
            float v = 0.f;
            if (gy >= 0 && gy < OH && gx >= 0 && gx < OW) {
                v = (ic < OUTC)
                    ? g_gate[(((size_t)n * OUTC + ic) * OH + gy) * OW + gx]
                    : sskip[(((size_t)n * OUTC + (ic - OUTC)) * OH + gy) * OW + gx];
            }
            in_s[icc][yy][xx] = v;
        }
        // weights: 64 oc x ICCH x 9 (contiguous 72-float run per oc)
        for (int e = tid; e < 64 * ICCH * 9; e += 256) {
            int oc = e / (ICCH * 9), rem = e % (ICCH * 9);
            w_s[rem * 68 + oc] = cw[((size_t)(oc0 + oc) * (2 * OUTC) + ic0) * 9 + rem];
        }
        __syncthreads();
#pragma unroll
        for (int icc = 0; icc < ICCH; icc++) {
#pragma unroll
            for (int ky = 0; ky < 3; ky++) {
                float xin[6];
#pragma unroll
                for (int t = 0; t < 6; t++) xin[t] = in_s[icc][dy + ky][dx + t];
#pragma unroll
                for (int kx = 0; kx < 3; kx++) {
                    float4 w4 = *(const float4*)&w_s[(icc * 9 + ky * 3 + kx) * 68 + ty * 4];
                    float wv[4] = {w4.x, w4.y, w4.z, w4.w};
#pragma unroll
                    for (int i = 0; i < 4; i++)
#pragma unroll
                        for (int j = 0; j < 4; j++)
                            acc[i][j] += wv[i] * xin[kx + j];
                }
            }
        }
        __syncthreads();
    }
    if (tid < 64) { rs[tid] = 0.f; rq[tid] = 0.f; }
    __syncthreads();
#pragma unroll
    for (int i = 0; i < 4; i++) {
        int oc = oc0 + ty * 4 + i;
        float bias = cb[oc];
        float s0 = 0.f, s1 = 0.f;
#pragma unroll
        for (int j = 0; j < 4; j++) {
            float v = acc[i][j] + bias;
            int gy = y0 + dy, gx = x0 + dx + j;
            g_y[(((size_t)n * OUTC + oc) * OH + gy) * OW + gx] = v;
            s0 += v;
            s1 += v * v;
        }
        atomicAdd(&rs[ty * 4 + i], s0);
        atomicAdd(&rq[ty * 4 + i], s1);
    }
    __syncthreads();
    if (tid < 64) {
        atomicAdd(&g_bnsum[oc0 + tid], rs[tid]);
        atomicAdd(&g_bnsq[oc0 + tid], rq[tid]);
    }
}

// ---------------- small kernels ----------------
__global__ void zero_kernel() {
    int t = threadIdx.x;
    g_bnsum[t] = 0.f;
    g_bnsq[t] = 0.f;
}

__global__ void bnstats_kernel(const float* __restrict__ bn_g, const float* __restrict__ bn_b) {
    int c = threadIdx.x;
    float cnt = (float)(BB * OH * OW);
    float mean = g_bnsum[c] / cnt;
    float var = g_bnsq[c] / cnt - mean * mean;
    float inv = rsqrtf(var + 1e-5f);
    float sc = bn_g[c] * inv;
    g_bnscale[c] = sc;
    g_bnshift[c] = bn_b[c] - mean * sc;
}

__global__ void bnorm_kernel(float* __restrict__ out) {
    int i4 = blockIdx.x * blockDim.x + threadIdx.x;
    const int total4 = BB * OUTC * OH * OW / 4;
    if (i4 >= total4) return;
    int base = i4 * 4;
    int oc = (base >> 12) & (OUTC - 1);  // OH*OW = 4096
    float sc = g_bnscale[oc], sh = g_bnshift[oc];
    float4 v = *(const float4*)&g_y[base];
    float4 r;
    r.x = fmaxf(v.x * sc + sh, 0.f);
    r.y = fmaxf(v.y * sc + sh, 0.f);
    r.z = fmaxf(v.z * sc + sh, 0.f);
    r.w = fmaxf(v.w * sc + sh, 0.f);
    *(float4*)&out[base] = r;
}

// ---------------- launcher ----------------
extern "C" void kernel_launch(void* const* d_in, const int* in_sizes, int n_in,
                              void* d_out, int out_size) {
    const float* x    = (const float*)d_in[0];
    const float* s    = (const float*)d_in[1];
    const float* up_w = (const float*)d_in[2];
    const float* up_b = (const float*)d_in[3];
    const float* wq   = (const float*)d_in[4];
    const float* wkl  = (const float*)d_in[5];
    const float* wkr  = (const float*)d_in[6];
    const float* c1_w = (const float*)d_in[7];
    const float* c1_b = (const float*)d_in[8];
    const float* bn_g = (const float*)d_in[9];
    const float* bn_b = (const float*)d_in[10];
    float* out = (float*)d_out;

    dim3 blk(16, 16);
    proj_kernel<<<dim3(8, 2, NS * 3), blk>>>(x, wq, wkl, wkr);
    sumz_kernel<<<dim3(NS, 2), 128>>>();
    kv_kernel<<<dim3(2, 16, NS * 2), blk>>>(x);
    attnout_kernel<<<dim3(8, 16, NS), blk>>>(x);
    convt_kernel<<<dim3(16, 16, BB), blk>>>(x, up_w, up_b, s);
    zero_kernel<<<1, OUTC>>>();
    conv_kernel<<<dim3(64, 4, BB), blk>>>(s, c1_w, c1_b);
    bnstats_kernel<<<1, OUTC>>>(bn_g, bn_b);
    int total4 = BB * OUTC * OH * OW / 4;
    bnorm_kernel<<<(total4 + 255) / 256, 256>>>(out);
}

// round 2
// speedup vs baseline: 1.6990x; 1.6990x over previous
#include <cuda_runtime.h>
#include <math.h>

#define BB 16
#define INC 512
#define OUTC 256
#define HH 32
#define WW 32
#define FD 1024
#define DK 128
#define NS 14          // interior samples (B-2)
#define OH 64
#define OW 64

// ---------------- scratch (static device memory; no allocation) ----------------
__device__ float g_mid[NS * INC * FD];        // rotatory outputs for batches 1..14
__device__ float g_q[NS * INC * DK];
__device__ float g_kl[NS * INC * DK];
__device__ float g_kr[NS * INC * DK];
__device__ float g_kvl[NS * DK * FD];
__device__ float g_kvr[NS * DK * FD];
__device__ float g_z[2 * NS * INC];           // [side][sample][row]
__device__ float g_gate[BB * OUTC * OH * OW]; // gated branch (first 256 channels of cat)
__device__ float g_y[BB * OUTC * OH * OW];    // conv3x3 pre-BN output
__device__ float g_bnsum[OUTC];
__device__ float g_bnsq[OUTC];
__device__ float g_bnscale[OUTC];
__device__ float g_bnshift[OUTC];

// ---------------- tf32 mma helpers ----------------
__device__ __forceinline__ unsigned f2tf(float f) {
    unsigned r;
    asm("cvt.rna.tf32.f32 %0, %1;" : "=r"(r) : "f"(f));
    return r;
}

__device__ __forceinline__ void mma_tf32(float (&d)[4], const unsigned (&a)[4], const unsigned (&b)[2]) {
    asm("mma.sync.aligned.m16n8k8.row.col.f32.tf32.tf32.f32 "
        "{%0,%1,%2,%3}, {%4,%5,%6,%7}, {%8,%9}, {%0,%1,%2,%3};"
        : "+f"(d[0]), "+f"(d[1]), "+f"(d[2]), "+f"(d[3])
        : "r"(a[0]), "r"(a[1]), "r"(a[2]), "r"(a[3]), "r"(b[0]), "r"(b[1]));
}

// ---------------- kernel 1: projections q/kl/kr = phi(A @ W) ----------------
__global__ __launch_bounds__(256) void proj_kernel(
    const float* __restrict__ x, const float* __restrict__ wq,
    const float* __restrict__ wkl, const float* __restrict__ wkr) {
    int zi = blockIdx.z;
    int sample = zi / 3, p = zi % 3;
    const float* A;
    const float* Wm;
    float* C;
    if (p == 0)      { A = x + (size_t)(sample + 1) * INC * FD; Wm = wq;  C = g_q  + (size_t)sample * INC * DK; }
    else if (p == 1) { A = x + (size_t)(sample + 0) * INC * FD; Wm = wkl; C = g_kl + (size_t)sample * INC * DK; }
    else             { A = x + (size_t)(sample + 2) * INC * FD; Wm = wkr; C = g_kr + (size_t)sample * INC * DK; }

    __shared__ float As[16][68];
    __shared__ float Bs[16][64];
    int m0 = blockIdx.x * 64;
    int n0 = blockIdx.y * 64;
    int tid = threadIdx.y * 16 + threadIdx.x;
    float acc[4][4] = {};
    for (int k0 = 0; k0 < FD; k0 += 16) {
#pragma unroll
        for (int it = 0; it < 4; it++) {
            int idx = it * 256 + tid;
            int m = idx >> 4, kk = idx & 15;
            As[kk][m] = A[(m0 + m) * FD + k0 + kk];
        }
#pragma unroll
        for (int it = 0; it < 4; it++) {
            int idx = it * 256 + tid;
            int kk = idx >> 6, n = idx & 63;
            Bs[kk][n] = Wm[(k0 + kk) * DK + n0 + n];
        }
        __syncthreads();
#pragma unroll
        for (int kk = 0; kk < 16; kk++) {
            float4 a4 = *(const float4*)&As[kk][threadIdx.y * 4];
            float4 b4 = *(const float4*)&Bs[kk][threadIdx.x * 4];
            float a[4] = {a4.x, a4.y, a4.z, a4.w};
            float b[4] = {b4.x, b4.y, b4.z, b4.w};
#pragma unroll
            for (int i = 0; i < 4; i++)
#pragma unroll
                for (int j = 0; j < 4; j++) acc[i][j] += a[i] * b[j];
        }
        __syncthreads();
    }
#pragma unroll
    for (int i = 0; i < 4; i++) {
        int m = m0 + threadIdx.y * 4 + i;
#pragma unroll
        for (int j = 0; j < 4; j++) {
            int n = n0 + threadIdx.x * 4 + j;
            float v = acc[i][j];
            C[m * DK + n] = (v > 0.f) ? (v + 1.f) : expf(v);  // elu(v)+1
        }
    }
}

// ---------------- kernel 2: column sums + z = q @ ksum + 1e-6 ----------------
__global__ void sumz_kernel() {
    int sample = blockIdx.x;
    int side = blockIdx.y;  // 0=l, 1=r
    const float* K = (side == 0 ? g_kl : g_kr) + (size_t)sample * INC * DK;
    const float* Q = g_q + (size_t)sample * INC * DK;
    __shared__ float ssum[DK];
    int t = threadIdx.x;  // 128 threads
    float s = 0.f;
    for (int n = 0; n < INC; n++) s += K[n * DK + t];
    ssum[t] = s;
    __syncthreads();
    float* Z = g_z + (size_t)(side * NS + sample) * INC;
    for (int rr = 0; rr < 4; rr++) {
        int row = rr * 128 + t;
        float d = 0.f;
        for (int k = 0; k < DK; k++) d += Q[row * DK + k] * ssum[k];
        Z[row] = d + 1e-6f;
    }
}

// ---------------- kernel 3: kv[k][d] = sum_n K[n][k] * V[n][d] ----------------
__global__ __launch_bounds__(256) void kv_kernel(const float* __restrict__ x) {
    int zi = blockIdx.z;
    int sample = zi >> 1, side = zi & 1;
    const float* K = (side == 0 ? g_kl : g_kr) + (size_t)sample * INC * DK;
    const float* V = x + (size_t)(sample + (side == 0 ? 0 : 2)) * INC * FD;
    float* C = (side == 0 ? g_kvl : g_kvr) + (size_t)sample * DK * FD;
    __shared__ float As[16][68];  // [nn][k]
    __shared__ float Bs[16][64];  // [nn][d]
    int m0 = blockIdx.x * 64;  // k dim (128)
    int n0 = blockIdx.y * 64;  // d dim (1024)
    int tid = threadIdx.y * 16 + threadIdx.x;
    float acc[4][4] = {};
    for (int c0 = 0; c0 < INC; c0 += 16) {
#pragma unroll
        for (int it = 0; it < 4; it++) {
            int idx = it * 256 + tid;
            int nn = idx >> 6, k = idx & 63;
            As[nn][k] = K[(c0 + nn) * DK + m0 + k];
        }
#pragma unroll
        for (int it = 0; it < 4; it++) {
            int idx = it * 256 + tid;
            int nn = idx >> 6, d = idx & 63;
            Bs[nn][d] = V[(c0 + nn) * FD + n0 + d];
        }
        __syncthreads();
#pragma unroll
        for (int nn = 0; nn < 16; nn++) {
            float4 a4 = *(const float4*)&As[nn][threadIdx.y * 4];
            float4 b4 = *(const float4*)&Bs[nn][threadIdx.x * 4];
            float a[4] = {a4.x, a4.y, a4.z, a4.w};
            float b[4] = {b4.x, b4.y, b4.z, b4.w};
#pragma unroll
            for (int i = 0; i < 4; i++)
#pragma unroll
                for (int j = 0; j < 4; j++) acc[i][j] += a[i] * b[j];
        }
        __syncthreads();
    }
#pragma unroll
    for (int i = 0; i < 4; i++) {
        int m = m0 + threadIdx.y * 4 + i;
#pragma unroll
        for (int j = 0; j < 4; j++) {
            int d = n0 + threadIdx.x * 4 + j;
            C[m * FD + d] = acc[i][j];
        }
    }
}

// ------ kernel 4: out = x + (q@kvl)/zl + (q@kvr)/zr  (dual-B GEMM, K=128) ------
__global__ __launch_bounds__(256) void attnout_kernel(const float* __restrict__ x) {
    int sample = blockIdx.z;
    const float* Q = g_q + (size_t)sample * INC * DK;
    const float* KVL = g_kvl + (size_t)sample * DK * FD;
    const float* KVR = g_kvr + (size_t)sample * DK * FD;
    const float* Zl = g_z + (size_t)sample * INC;
    const float* Zr = g_z + (size_t)(NS + sample) * INC;
    const float* X = x + (size_t)(sample + 1) * INC * FD;
    float* C = g_mid + (size_t)sample * INC * FD;
    __shared__ float As[16][68];
    __shared__ float Bl[16][64];
    __shared__ float Br[16][64];
    int m0 = blockIdx.x * 64;
    int n0 = blockIdx.y * 64;
    int tid = threadIdx.y * 16 + threadIdx.x;
    float accl[4][4] = {}, accr[4][4] = {};
    for (int k0 = 0; k0 < DK; k0 += 16) {
#pragma unroll
        for (int it = 0; it < 4; it++) {
            int idx = it * 256 + tid;
            int m = idx >> 4, kk = idx & 15;
            As[kk][m] = Q[(m0 + m) * DK + k0 + kk];
        }
#pragma unroll
        for (int it = 0; it < 4; it++) {
            int idx = it * 256 + tid;
            int kk = idx >> 6, n = idx & 63;
            Bl[kk][n] = KVL[(k0 + kk) * FD + n0 + n];
            Br[kk][n] = KVR[(k0 + kk) * FD + n0 + n];
        }
        __syncthreads();
#pragma unroll
        for (int kk = 0; kk < 16; kk++) {
            float4 a4 = *(const float4*)&As[kk][threadIdx.y * 4];
            float4 bl4 = *(const float4*)&Bl[kk][threadIdx.x * 4];
            float4 br4 = *(const float4*)&Br[kk][threadIdx.x * 4];
            float a[4] = {a4.x, a4.y, a4.z, a4.w};
            float bl[4] = {bl4.x, bl4.y, bl4.z, bl4.w};
            float br[4] = {br4.x, br4.y, br4.z, br4.w};
#pragma unroll
            for (int i = 0; i < 4; i++)
#pragma unroll
                for (int j = 0; j < 4; j++) {
                    accl[i][j] += a[i] * bl[j];
                    accr[i][j] += a[i] * br[j];
                }
        }
        __syncthreads();
    }
#pragma unroll
    for (int i = 0; i < 4; i++) {
        int m = m0 + threadIdx.y * 4 + i;
        float zl = Zl[m], zr = Zr[m];
#pragma unroll
        for (int j = 0; j < 4; j++) {
            int d = n0 + threadIdx.x * 4 + j;
            C[m * FD + d] = X[m * FD + d] + accl[i][j] / zl + accr[i][j] / zr;
        }
    }
}

// ------ kernel 5: ConvTranspose 2x2 s2 as GEMM + fused gate sigmoid(relu(up+s)) ------
__global__ __launch_bounds__(256) void convt_kernel(
    const float* __restrict__ x, const float* __restrict__ upw,
    const float* __restrict__ upb, const float* __restrict__ s) {
    int n = blockIdx.z;
    const float* src = (n == 0) ? x
                     : (n == BB - 1) ? (x + (size_t)(BB - 1) * INC * FD)
                     : (g_mid + (size_t)(n - 1) * INC * FD);
    __shared__ float As[16][68];  // [cc][wcol]
    __shared__ float Bs[16][64];  // [cc][ij]
    int m0 = blockIdx.x * 64;  // wcol over 1024 = o*4+ab
    int n0 = blockIdx.y * 64;  // ij over 1024
    int tid = threadIdx.y * 16 + threadIdx.x;
    float acc[4][4] = {};
    for (int c0 = 0; c0 < INC; c0 += 16) {
#pragma unroll
        for (int it = 0; it < 4; it++) {
            int idx = it * 256 + tid;
            int cc = idx >> 6, m = idx & 63;
            As[cc][m] = upw[(c0 + cc) * 1024 + m0 + m];
        }
#pragma unroll
        for (int it = 0; it < 4; it++) {
            int idx = it * 256 + tid;
            int cc = idx >> 6, d = idx & 63;
            Bs[cc][d] = src[(c0 + cc) * FD + n0 + d];
        }
        __syncthreads();
#pragma unroll
        for (int cc = 0; cc < 16; cc++) {
            float4 a4 = *(const float4*)&As[cc][threadIdx.y * 4];
            float4 b4 = *(const float4*)&Bs[cc][threadIdx.x * 4];
            float a[4] = {a4.x, a4.y, a4.z, a4.w};
            float b[4] = {b4.x, b4.y, b4.z, b4.w};
#pragma unroll
            for (int i = 0; i < 4; i++)
#pragma unroll
                for (int j = 0; j < 4; j++) acc[i][j] += a[i] * b[j];
        }
        __syncthreads();
    }
#pragma unroll
    for (int i = 0; i < 4; i++) {
        int row = m0 + threadIdx.y * 4 + i;
        int o = row >> 2, ab = row & 3, a = ab >> 1, bq = ab & 1;
        float bias = upb[o];
#pragma unroll
        for (int j = 0; j < 4; j++) {
            int col = n0 + threadIdx.x * 4 + j;
            int isp = col >> 5, jsp = col & 31;
            int oy = 2 * isp + a, ox = 2 * jsp + bq;
            size_t gi = (((size_t)n * OUTC + o) * OH + oy) * OW + ox;
            float v = acc[i][j] + bias + s[gi];
            v = v > 0.f ? v : 0.f;
            g_gate[gi] = 1.f / (1.f + expf(-v));
        }
    }
}

// ---------------- kernel 6: conv3x3 via tf32 mma.sync implicit GEMM ----------------
// Block tile: M = 64 oc, N = 256 px (4 image rows). 8 warps = 2(m) x 4(n).
// Each warp: mt=2 m16-tiles (32 oc), nt=8 n8-tiles (one full 64-px image row).
// K loop: ic chunks of 8, 9 kernel positions as shifted-window GEMMs.
__global__ __launch_bounds__(256) void conv_mma_kernel(
    const float* __restrict__ sskip, const float* __restrict__ cw,
    const float* __restrict__ cb) {
    int n = blockIdx.z;
    int oc0 = blockIdx.y * 64;
    int y0 = blockIdx.x * 4;

    __shared__ float in_s[8 * 440];  // [icc][yy*72 + xx], plane stride 440 (conflict-free)
    __shared__ float w_s[64 * 76];   // [oc][icc*9 + pos], row stride 76 (conflict-free)
    __shared__ float rs[64], rq[64];

    int tid = threadIdx.x;
    int warp = tid >> 5, lane = tid & 31;
    int wm = warp & 1;        // m half (0/1 -> oc +0/+32)
    int wn = warp >> 1;       // image row within 4-row tile (0..3)
    int qr = lane >> 2;       // 0..7
    int qc = lane & 3;        // 0..3

    float acc[2][8][4];
#pragma unroll
    for (int mi = 0; mi < 2; mi++)
#pragma unroll
        for (int j = 0; j < 8; j++)
#pragma unroll
            for (int c = 0; c < 4; c++) acc[mi][j][c] = 0.f;

    for (int ic0 = 0; ic0 < 2 * OUTC; ic0 += 8) {
        // input patch: 8 icc x 6 rows (halo) x 66 cols (halo), zero-padded
        for (int e = tid; e < 8 * 6 * 66; e += 256) {
            int icc = e / 396;
            int rem = e - icc * 396;
            int yy = rem / 66;
            int xx = rem - yy * 66;
            int gy = y0 + yy - 1, gx = xx - 1;
            int ic = ic0 + icc;
            float v = 0.f;
            if ((unsigned)gy < (unsigned)OH && (unsigned)gx < (unsigned)OW) {
                v = (ic < OUTC)
                    ? g_gate[(((size_t)n * OUTC + ic) * OH + gy) * OW + gx]
                    : sskip[(((size_t)n * OUTC + (ic - OUTC)) * OH + gy) * OW + gx];
            }
            in_s[icc * 440 + yy * 72 + xx] = v;
        }
        // weights: 64 oc x (8 icc * 9 pos) contiguous, float4 copy
        for (int e = tid; e < 64 * 18; e += 256) {
            int oc = e / 18, f = e - oc * 18;
            float4 v = *(const float4*)&cw[(size_t)(oc0 + oc) * (2 * OUTC * 9) + ic0 * 9 + f * 4];
            *(float4*)&w_s[oc * 76 + f * 4] = v;
        }
        __syncthreads();

#pragma unroll
        for (int ky = 0; ky < 3; ky++) {
            int rowoff = (wn + ky) * 72;
#pragma unroll
            for (int kx = 0; kx < 3; kx++) {
                int pos = ky * 3 + kx;
                unsigned a[2][4];
#pragma unroll
                for (int mi = 0; mi < 2; mi++) {
                    int ocb = wm * 32 + mi * 16 + qr;
                    a[mi][0] = f2tf(w_s[ocb * 76 + qc * 9 + pos]);
                    a[mi][1] = f2tf(w_s[(ocb + 8) * 76 + qc * 9 + pos]);
                    a[mi][2] = f2tf(w_s[ocb * 76 + (qc + 4) * 9 + pos]);
                    a[mi][3] = f2tf(w_s[(ocb + 8) * 76 + (qc + 4) * 9 + pos]);
                }
#pragma unroll
                for (int j = 0; j < 8; j++) {
                    unsigned b[2];
                    int col = j * 8 + qr + kx;
                    b[0] = f2tf(in_s[qc * 440 + rowoff + col]);
                    b[1] = f2tf(in_s[(qc + 4) * 440 + rowoff + col]);
                    mma_tf32(acc[0][j], a[0], b);
                    mma_tf32(acc[1][j], a[1], b);
                }
            }
        }
        __syncthreads();
    }

    // epilogue: bias, store y, BN partial sums
    if (tid < 64) { rs[tid] = 0.f; rq[tid] = 0.f; }
    __syncthreads();
    int row = y0 + wn;
#pragma unroll
    for (int mi = 0; mi < 2; mi++) {
#pragma unroll
        for (int half = 0; half < 2; half++) {
            int ocl = wm * 32 + mi * 16 + half * 8 + qr;
            int oc = oc0 + ocl;
            float bias = cb[oc];
            float s0 = 0.f, s1 = 0.f;
#pragma unroll
            for (int j = 0; j < 8; j++) {
#pragma unroll
                for (int cc = 0; cc < 2; cc++) {
                    float v = acc[mi][j][half * 2 + cc] + bias;
                    int col = j * 8 + qc * 2 + cc;
                    g_y[(((size_t)n * OUTC + oc) * OH + row) * OW + col] = v;
                    s0 += v;
                    s1 += v * v;
                }
            }
            s0 += __shfl_xor_sync(0xffffffffu, s0, 1);
            s0 += __shfl_xor_sync(0xffffffffu, s0, 2);
            s1 += __shfl_xor_sync(0xffffffffu, s1, 1);
            s1 += __shfl_xor_sync(0xffffffffu, s1, 2);
            if (qc == 0) {
                atomicAdd(&rs[ocl], s0);
                atomicAdd(&rq[ocl], s1);
            }
        }
    }
    __syncthreads();
    if (tid < 64) {
        atomicAdd(&g_bnsum[oc0 + tid], rs[tid]);
        atomicAdd(&g_bnsq[oc0 + tid], rq[tid]);
    }
}

// ---------------- small kernels ----------------
__global__ void zero_kernel() {
    int t = threadIdx.x;
    g_bnsum[t] = 0.f;
    g_bnsq[t] = 0.f;
}

__global__ void bnstats_kernel(const float* __restrict__ bn_g, const float* __restrict__ bn_b) {
    int c = threadIdx.x;
    float cnt = (float)(BB * OH * OW);
    float mean = g_bnsum[c] / cnt;
    float var = g_bnsq[c] / cnt - mean * mean;
    float inv = rsqrtf(var + 1e-5f);
    float sc = bn_g[c] * inv;
    g_bnscale[c] = sc;
    g_bnshift[c] = bn_b[c] - mean * sc;
}

__global__ void bnorm_kernel(float* __restrict__ out) {
    int i4 = blockIdx.x * blockDim.x + threadIdx.x;
    const int total4 = BB * OUTC * OH * OW / 4;
    if (i4 >= total4) return;
    int base = i4 * 4;
    int oc = (base >> 12) & (OUTC - 1);  // OH*OW = 4096
    float sc = g_bnscale[oc], sh = g_bnshift[oc];
    float4 v = *(const float4*)&g_y[base];
    float4 r;
    r.x = fmaxf(v.x * sc + sh, 0.f);
    r.y = fmaxf(v.y * sc + sh, 0.f);
    r.z = fmaxf(v.z * sc + sh, 0.f);
    r.w = fmaxf(v.w * sc + sh, 0.f);
    *(float4*)&out[base] = r;
}

// ---------------- launcher ----------------
extern "C" void kernel_launch(void* const* d_in, const int* in_sizes, int n_in,
                              void* d_out, int out_size) {
    const float* x    = (const float*)d_in[0];
    const float* s    = (const float*)d_in[1];
    const float* up_w = (const float*)d_in[2];
    const float* up_b = (const float*)d_in[3];
    const float* wq   = (const float*)d_in[4];
    const float* wkl  = (const float*)d_in[5];
    const float* wkr  = (const float*)d_in[6];
    const float* c1_w = (const float*)d_in[7];
    const float* c1_b = (const float*)d_in[8];
    const float* bn_g = (const float*)d_in[9];
    const float* bn_b = (const float*)d_in[10];
    float* out = (float*)d_out;

    dim3 blk(16, 16);
    proj_kernel<<<dim3(8, 2, NS * 3), blk>>>(x, wq, wkl, wkr);
    sumz_kernel<<<dim3(NS, 2), 128>>>();
    kv_kernel<<<dim3(2, 16, NS * 2), blk>>>(x);
    attnout_kernel<<<dim3(8, 16, NS), blk>>>(x);
    convt_kernel<<<dim3(16, 16, BB), blk>>>(x, up_w, up_b, s);
    zero_kernel<<<1, OUTC>>>();
    conv_mma_kernel<<<dim3(16, 4, BB), 256>>>(s, c1_w, c1_b);
    bnstats_kernel<<<1, OUTC>>>(bn_g, bn_b);
    int total4 = BB * OUTC * OH * OW / 4;
    bnorm_kernel<<<(total4 + 255) / 256, 256>>>(out);
}

// round 3
// speedup vs baseline: 1.8883x; 1.1114x over previous
#include <cuda_runtime.h>
#include <math.h>

#define BB 16
#define INC 512
#define OUTC 256
#define HH 32
#define WW 32
#define FD 1024
#define DK 128
#define NS 14          // interior samples (B-2)
#define OH 64
#define OW 64

// ---------------- scratch (static device memory; no allocation) ----------------
__device__ float g_mid[NS * INC * FD];        // rotatory outputs for batches 1..14
__device__ float g_q[NS * INC * DK];
__device__ float g_kl[NS * INC * DK];
__device__ float g_kr[NS * INC * DK];
__device__ float g_kvl[NS * DK * FD];
__device__ float g_kvr[NS * DK * FD];
__device__ float g_z[2 * NS * INC];           // [side][sample][row]
__device__ float g_gate[BB * OUTC * OH * OW]; // gated branch (first 256 channels of cat)
__device__ float g_y[BB * OUTC * OH * OW];    // conv3x3 pre-BN output
__device__ float g_bnsum[OUTC];
__device__ float g_bnsq[OUTC];
__device__ float g_bnscale[OUTC];
__device__ float g_bnshift[OUTC];

// ---------------- tf32 mma helpers ----------------
__device__ __forceinline__ unsigned f2tf(float f) {
    unsigned r;
    asm("cvt.rna.tf32.f32 %0, %1;" : "=r"(r) : "f"(f));
    return r;
}

__device__ __forceinline__ void mma_tf32(float (&d)[4], const unsigned (&a)[4], const unsigned (&b)[2]) {
    asm("mma.sync.aligned.m16n8k8.row.col.f32.tf32.tf32.f32 "
        "{%0,%1,%2,%3}, {%4,%5,%6,%7}, {%8,%9}, {%0,%1,%2,%3};"
        : "+f"(d[0]), "+f"(d[1]), "+f"(d[2]), "+f"(d[3])
        : "r"(a[0]), "r"(a[1]), "r"(a[2]), "r"(a[3]), "r"(b[0]), "r"(b[1]));
}

// ---------------- kernel 1: projections q/kl/kr = phi(A @ W) ----------------
__global__ __launch_bounds__(256) void proj_kernel(
    const float* __restrict__ x, const float* __restrict__ wq,
    const float* __restrict__ wkl, const float* __restrict__ wkr) {
    int zi = blockIdx.z;
    int sample = zi / 3, p = zi % 3;
    const float* A;
    const float* Wm;
    float* C;
    if (p == 0)      { A = x + (size_t)(sample + 1) * INC * FD; Wm = wq;  C = g_q  + (size_t)sample * INC * DK; }
    else if (p == 1) { A = x + (size_t)(sample + 0) * INC * FD; Wm = wkl; C = g_kl + (size_t)sample * INC * DK; }
    else             { A = x + (size_t)(sample + 2) * INC * FD; Wm = wkr; C = g_kr + (size_t)sample * INC * DK; }

    __shared__ float As[16][68];
    __shared__ float Bs[16][64];
    int m0 = blockIdx.x * 64;
    int n0 = blockIdx.y * 64;
    int tid = threadIdx.y * 16 + threadIdx.x;
    float acc[4][4] = {};
    for (int k0 = 0; k0 < FD; k0 += 16) {
#pragma unroll
        for (int it = 0; it < 4; it++) {
            int idx = it * 256 + tid;
            int m = idx >> 4, kk = idx & 15;
            As[kk][m] = A[(m0 + m) * FD + k0 + kk];
        }
#pragma unroll
        for (int it = 0; it < 4; it++) {
            int idx = it * 256 + tid;
            int kk = idx >> 6, n = idx & 63;
            Bs[kk][n] = Wm[(k0 + kk) * DK + n0 + n];
        }
        __syncthreads();
#pragma unroll
        for (int kk = 0; kk < 16; kk++) {
            float4 a4 = *(const float4*)&As[kk][threadIdx.y * 4];
            float4 b4 = *(const float4*)&Bs[kk][threadIdx.x * 4];
            float a[4] = {a4.x, a4.y, a4.z, a4.w};
            float b[4] = {b4.x, b4.y, b4.z, b4.w};
#pragma unroll
            for (int i = 0; i < 4; i++)
#pragma unroll
                for (int j = 0; j < 4; j++) acc[i][j] += a[i] * b[j];
        }
        __syncthreads();
    }
#pragma unroll
    for (int i = 0; i < 4; i++) {
        int m = m0 + threadIdx.y * 4 + i;
#pragma unroll
        for (int j = 0; j < 4; j++) {
            int n = n0 + threadIdx.x * 4 + j;
            float v = acc[i][j];
            C[m * DK + n] = (v > 0.f) ? (v + 1.f) : expf(v);  // elu(v)+1
        }
    }
}

// ---------------- kernel 2: column sums + z = q @ ksum + 1e-6 ----------------
__global__ void sumz_kernel() {
    int sample = blockIdx.x;
    int side = blockIdx.y;  // 0=l, 1=r
    const float* K = (side == 0 ? g_kl : g_kr) + (size_t)sample * INC * DK;
    const float* Q = g_q + (size_t)sample * INC * DK;
    __shared__ float ssum[DK];
    int t = threadIdx.x;  // 128 threads
    float s = 0.f;
    for (int n = 0; n < INC; n++) s += K[n * DK + t];
    ssum[t] = s;
    __syncthreads();
    float* Z = g_z + (size_t)(side * NS + sample) * INC;
    for (int rr = 0; rr < 4; rr++) {
        int row = rr * 128 + t;
        float d = 0.f;
        for (int k = 0; k < DK; k++) d += Q[row * DK + k] * ssum[k];
        Z[row] = d + 1e-6f;
    }
}

// ---------------- kernel 3: kv[k][d] = sum_n K[n][k] * V[n][d] ----------------
__global__ __launch_bounds__(256) void kv_kernel(const float* __restrict__ x) {
    int zi = blockIdx.z;
    int sample = zi >> 1, side = zi & 1;
    const float* K = (side == 0 ? g_kl : g_kr) + (size_t)sample * INC * DK;
    const float* V = x + (size_t)(sample + (side == 0 ? 0 : 2)) * INC * FD;
    float* C = (side == 0 ? g_kvl : g_kvr) + (size_t)sample * DK * FD;
    __shared__ float As[16][68];  // [nn][k]
    __shared__ float Bs[16][64];  // [nn][d]
    int m0 = blockIdx.x * 64;  // k dim (128)
    int n0 = blockIdx.y * 64;  // d dim (1024)
    int tid = threadIdx.y * 16 + threadIdx.x;
    float acc[4][4] = {};
    for (int c0 = 0; c0 < INC; c0 += 16) {
#pragma unroll
        for (int it = 0; it < 4; it++) {
            int idx = it * 256 + tid;
            int nn = idx >> 6, k = idx & 63;
            As[nn][k] = K[(c0 + nn) * DK + m0 + k];
        }
#pragma unroll
        for (int it = 0; it < 4; it++) {
            int idx = it * 256 + tid;
            int nn = idx >> 6, d = idx & 63;
            Bs[nn][d] = V[(c0 + nn) * FD + n0 + d];
        }
        __syncthreads();
#pragma unroll
        for (int nn = 0; nn < 16; nn++) {
            float4 a4 = *(const float4*)&As[nn][threadIdx.y * 4];
            float4 b4 = *(const float4*)&Bs[nn][threadIdx.x * 4];
            float a[4] = {a4.x, a4.y, a4.z, a4.w};
            float b[4] = {b4.x, b4.y, b4.z, b4.w};
#pragma unroll
            for (int i = 0; i < 4; i++)
#pragma unroll
                for (int j = 0; j < 4; j++) acc[i][j] += a[i] * b[j];
        }
        __syncthreads();
    }
#pragma unroll
    for (int i = 0; i < 4; i++) {
        int m = m0 + threadIdx.y * 4 + i;
#pragma unroll
        for (int j = 0; j < 4; j++) {
            int d = n0 + threadIdx.x * 4 + j;
            C[m * FD + d] = acc[i][j];
        }
    }
}

// ------ kernel 4: out = x + (q@kvl)/zl + (q@kvr)/zr  (dual-B GEMM, K=128) ------
__global__ __launch_bounds__(256) void attnout_kernel(const float* __restrict__ x) {
    int sample = blockIdx.z;
    const float* Q = g_q + (size_t)sample * INC * DK;
    const float* KVL = g_kvl + (size_t)sample * DK * FD;
    const float* KVR = g_kvr + (size_t)sample * DK * FD;
    const float* Zl = g_z + (size_t)sample * INC;
    const float* Zr = g_z + (size_t)(NS + sample) * INC;
    const float* X = x + (size_t)(sample + 1) * INC * FD;
    float* C = g_mid + (size_t)sample * INC * FD;
    __shared__ float As[16][68];
    __shared__ float Bl[16][64];
    __shared__ float Br[16][64];
    int m0 = blockIdx.x * 64;
    int n0 = blockIdx.y * 64;
    int tid = threadIdx.y * 16 + threadIdx.x;
    float accl[4][4] = {}, accr[4][4] = {};
    for (int k0 = 0; k0 < DK; k0 += 16) {
#pragma unroll
        for (int it = 0; it < 4; it++) {
            int idx = it * 256 + tid;
            int m = idx >> 4, kk = idx & 15;
            As[kk][m] = Q[(m0 + m) * DK + k0 + kk];
        }
#pragma unroll
        for (int it = 0; it < 4; it++) {
            int idx = it * 256 + tid;
            int kk = idx >> 6, n = idx & 63;
            Bl[kk][n] = KVL[(k0 + kk) * FD + n0 + n];
            Br[kk][n] = KVR[(k0 + kk) * FD + n0 + n];
        }
        __syncthreads();
#pragma unroll
        for (int kk = 0; kk < 16; kk++) {
            float4 a4 = *(const float4*)&As[kk][threadIdx.y * 4];
            float4 bl4 = *(const float4*)&Bl[kk][threadIdx.x * 4];
            float4 br4 = *(const float4*)&Br[kk][threadIdx.x * 4];
            float a[4] = {a4.x, a4.y, a4.z, a4.w};
            float bl[4] = {bl4.x, bl4.y, bl4.z, bl4.w};
            float br[4] = {br4.x, br4.y, br4.z, br4.w};
#pragma unroll
            for (int i = 0; i < 4; i++)
#pragma unroll
                for (int j = 0; j < 4; j++) {
                    accl[i][j] += a[i] * bl[j];
                    accr[i][j] += a[i] * br[j];
                }
        }
        __syncthreads();
    }
#pragma unroll
    for (int i = 0; i < 4; i++) {
        int m = m0 + threadIdx.y * 4 + i;
        float zl = Zl[m], zr = Zr[m];
#pragma unroll
        for (int j = 0; j < 4; j++) {
            int d = n0 + threadIdx.x * 4 + j;
            C[m * FD + d] = X[m * FD + d] + accl[i][j] / zl + accr[i][j] / zr;
        }
    }
}

// ------ kernel 5: ConvTranspose 2x2 s2 via tf32 mma + fused gate ------
// GEMM: C[wcol(1024)][ij(1024)] = sum_c upw[c][wcol] * src[c][ij], per sample.
// Block tile M=64 x N=256, K-chunk 16. 8 warps = 2(m) x 4(n).
__global__ __launch_bounds__(256) void convt_mma_kernel(
    const float* __restrict__ x, const float* __restrict__ upw,
    const float* __restrict__ upb, const float* __restrict__ s) {
    int n = blockIdx.z;
    const float* src = (n == 0) ? x
                     : (n == BB - 1) ? (x + (size_t)(BB - 1) * INC * FD)
                     : (g_mid + (size_t)(n - 1) * INC * FD);
    int m0 = blockIdx.x * 64;   // wcol
    int n0 = blockIdx.y * 256;  // ij

    __shared__ unsigned Asu[16 * 72];   // [k][m], stride 72 (72%32=8, conflict-free)
    __shared__ unsigned Bsu[16 * 264];  // [k][n], stride 264 (264%32=8, conflict-free)

    int tid = threadIdx.x;
    int warp = tid >> 5, lane = tid & 31;
    int wm = warp & 1;
    int wn = warp >> 1;
    int qr = lane >> 2;
    int qc = lane & 3;

    float acc[2][8][4];
#pragma unroll
    for (int mi = 0; mi < 2; mi++)
#pragma unroll
        for (int j = 0; j < 8; j++)
#pragma unroll
            for (int c = 0; c < 4; c++) acc[mi][j][c] = 0.f;

    for (int c0 = 0; c0 < INC; c0 += 16) {
#pragma unroll
        for (int it = 0; it < 4; it++) {
            int e = it * 256 + tid;
            int cc = e >> 6, m = e & 63;
            Asu[cc * 72 + m] = f2tf(upw[(size_t)(c0 + cc) * 1024 + m0 + m]);
        }
#pragma unroll
        for (int it = 0; it < 4; it++) {
            int e = it * 256 + tid;
            int cc = e >> 6, c4 = (e & 63) * 4;
            float4 v = *(const float4*)&src[(size_t)(c0 + cc) * FD + n0 + c4];
            unsigned* bp = &Bsu[cc * 264 + c4];
            bp[0] = f2tf(v.x); bp[1] = f2tf(v.y); bp[2] = f2tf(v.z); bp[3] = f2tf(v.w);
        }
        __syncthreads();
#pragma unroll
        for (int k8 = 0; k8 < 2; k8++) {
            unsigned a[2][4];
            int ra0 = (k8 * 8 + qc) * 72;
            int ra1 = (k8 * 8 + qc + 4) * 72;
#pragma unroll
            for (int mi = 0; mi < 2; mi++) {
                int ocb = wm * 32 + mi * 16 + qr;
                a[mi][0] = Asu[ra0 + ocb];
                a[mi][1] = Asu[ra0 + ocb + 8];
                a[mi][2] = Asu[ra1 + ocb];
                a[mi][3] = Asu[ra1 + ocb + 8];
            }
            int rb0 = (k8 * 8 + qc) * 264 + wn * 64 + qr;
            int rb1 = (k8 * 8 + qc + 4) * 264 + wn * 64 + qr;
#pragma unroll
            for (int j = 0; j < 8; j++) {
                unsigned b[2] = {Bsu[rb0 + j * 8], Bsu[rb1 + j * 8]};
                mma_tf32(acc[0][j], a[0], b);
                mma_tf32(acc[1][j], a[1], b);
            }
        }
        __syncthreads();
    }
    // epilogue: bias + skip + relu + sigmoid, scatter to g_gate
#pragma unroll
    for (int mi = 0; mi < 2; mi++) {
#pragma unroll
        for (int half = 0; half < 2; half++) {
            int row = m0 + wm * 32 + mi * 16 + half * 8 + qr;
            int o = row >> 2, ab = row & 3, av = ab >> 1, bq = ab & 1;
            float bias = upb[o];
#pragma unroll
            for (int j = 0; j < 8; j++) {
#pragma unroll
                for (int cc = 0; cc < 2; cc++) {
                    int col = n0 + wn * 64 + j * 8 + qc * 2 + cc;
                    int isp = col >> 5, jsp = col & 31;
                    int oy = 2 * isp + av, ox = 2 * jsp + bq;
                    size_t gi = (((size_t)n * OUTC + o) * OH + oy) * OW + ox;
                    float v = acc[mi][j][half * 2 + cc] + bias + s[gi];
                    v = v > 0.f ? v : 0.f;
                    g_gate[gi] = 1.f / (1.f + expf(-v));
                }
            }
        }
    }
}

// ---------------- kernel 6: conv3x3 via tf32 mma, pre-converted smem ----------------
__global__ __launch_bounds__(256) void conv_mma_kernel(
    const float* __restrict__ sskip, const float* __restrict__ cw,
    const float* __restrict__ cb) {
    int n = blockIdx.z;
    int oc0 = blockIdx.y * 64;
    int y0 = blockIdx.x * 4;

    __shared__ unsigned in_s[8 * 440];  // [icc][yy*72 + xx], plane stride 440 (conflict-free)
    __shared__ unsigned w_s[64 * 76];   // [oc][icc*9 + pos], row stride 76 (conflict-free)
    __shared__ float rs[64], rq[64];

    int tid = threadIdx.x;
    int warp = tid >> 5, lane = tid & 31;
    int wm = warp & 1;        // m half (0/1 -> oc +0/+32)
    int wn = warp >> 1;       // image row within 4-row tile (0..3)
    int qr = lane >> 2;       // 0..7
    int qc = lane & 3;        // 0..3

    if (tid < 64) { rs[tid] = 0.f; rq[tid] = 0.f; }

    float acc[2][8][4];
#pragma unroll
    for (int mi = 0; mi < 2; mi++)
#pragma unroll
        for (int j = 0; j < 8; j++)
#pragma unroll
            for (int c = 0; c < 4; c++) acc[mi][j][c] = 0.f;

    for (int ic0 = 0; ic0 < 2 * OUTC; ic0 += 8) {
        // input patch: 8 icc x 6 rows (halo) x 66 cols (halo), zero-padded, tf32
        for (int e = tid; e < 8 * 6 * 66; e += 256) {
            int icc = e / 396;
            int rem = e - icc * 396;
            int yy = rem / 66;
            int xx = rem - yy * 66;
            int gy = y0 + yy - 1, gx = xx - 1;
            int ic = ic0 + icc;
            float v = 0.f;
            if ((unsigned)gy < (unsigned)OH && (unsigned)gx < (unsigned)OW) {
                v = (ic < OUTC)
                    ? g_gate[(((size_t)n * OUTC + ic) * OH + gy) * OW + gx]
                    : sskip[(((size_t)n * OUTC + (ic - OUTC)) * OH + gy) * OW + gx];
            }
            in_s[icc * 440 + yy * 72 + xx] = f2tf(v);
        }
        // weights: 64 oc x (8 icc * 9 pos) contiguous, float4 load + tf32 convert
        for (int e = tid; e < 64 * 18; e += 256) {
            int oc = e / 18, f = e - oc * 18;
            float4 v = *(const float4*)&cw[(size_t)(oc0 + oc) * (2 * OUTC * 9) + ic0 * 9 + f * 4];
            unsigned* wp = &w_s[oc * 76 + f * 4];
            wp[0] = f2tf(v.x); wp[1] = f2tf(v.y); wp[2] = f2tf(v.z); wp[3] = f2tf(v.w);
        }
        __syncthreads();

#pragma unroll
        for (int ky = 0; ky < 3; ky++) {
            int rowoff = (wn + ky) * 72;
#pragma unroll
            for (int kx = 0; kx < 3; kx++) {
                int pos = ky * 3 + kx;
                unsigned a[2][4];
#pragma unroll
                for (int mi = 0; mi < 2; mi++) {
                    int ocb = wm * 32 + mi * 16 + qr;
                    a[mi][0] = w_s[ocb * 76 + qc * 9 + pos];
                    a[mi][1] = w_s[(ocb + 8) * 76 + qc * 9 + pos];
                    a[mi][2] = w_s[ocb * 76 + (qc + 4) * 9 + pos];
                    a[mi][3] = w_s[(ocb + 8) * 76 + (qc + 4) * 9 + pos];
                }
#pragma unroll
                for (int j = 0; j < 8; j++) {
                    unsigned b[2];
                    int col = j * 8 + qr + kx;
                    b[0] = in_s[qc * 440 + rowoff + col];
                    b[1] = in_s[(qc + 4) * 440 + rowoff + col];
                    mma_tf32(acc[0][j], a[0], b);
                    mma_tf32(acc[1][j], a[1], b);
                }
            }
        }
        __syncthreads();
    }

    // epilogue: bias, store y, BN partial sums
    int row = y0 + wn;
#pragma unroll
    for (int mi = 0; mi < 2; mi++) {
#pragma unroll
        for (int half = 0; half < 2; half++) {
            int ocl = wm * 32 + mi * 16 + half * 8 + qr;
            int oc = oc0 + ocl;
            float bias = cb[oc];
            float s0 = 0.f, s1 = 0.f;
#pragma unroll
            for (int j = 0; j < 8; j++) {
#pragma unroll
                for (int cc = 0; cc < 2; cc++) {
                    float v = acc[mi][j][half * 2 + cc] + bias;
                    int col = j * 8 + qc * 2 + cc;
                    g_y[(((size_t)n * OUTC + oc) * OH + row) * OW + col] = v;
                    s0 += v;
                    s1 += v * v;
                }
            }
            s0 += __shfl_xor_sync(0xffffffffu, s0, 1);
            s0 += __shfl_xor_sync(0xffffffffu, s0, 2);
            s1 += __shfl_xor_sync(0xffffffffu, s1, 1);
            s1 += __shfl_xor_sync(0xffffffffu, s1, 2);
            if (qc == 0) {
                atomicAdd(&rs[ocl], s0);
                atomicAdd(&rq[ocl], s1);
            }
        }
    }
    __syncthreads();
    if (tid < 64) {
        atomicAdd(&g_bnsum[oc0 + tid], rs[tid]);
        atomicAdd(&g_bnsq[oc0 + tid], rq[tid]);
    }
}

// ---------------- small kernels ----------------
__global__ void zero_kernel() {
    int t = threadIdx.x;
    g_bnsum[t] = 0.f;
    g_bnsq[t] = 0.f;
}

__global__ void bnstats_kernel(const float* __restrict__ bn_g, const float* __restrict__ bn_b) {
    int c = threadIdx.x;
    float cnt = (float)(BB * OH * OW);
    float mean = g_bnsum[c] / cnt;
    float var = g_bnsq[c] / cnt - mean * mean;
    float inv = rsqrtf(var + 1e-5f);
    float sc = bn_g[c] * inv;
    g_bnscale[c] = sc;
    g_bnshift[c] = bn_b[c] - mean * sc;
}

__global__ void bnorm_kernel(float* __restrict__ out) {
    int i4 = blockIdx.x * blockDim.x + threadIdx.x;
    const int total4 = BB * OUTC * OH * OW / 4;
    if (i4 >= total4) return;
    int base = i4 * 4;
    int oc = (base >> 12) & (OUTC - 1);  // OH*OW = 4096
    float sc = g_bnscale[oc], sh = g_bnshift[oc];
    float4 v = *(const float4*)&g_y[base];
    float4 r;
    r.x = fmaxf(v.x * sc + sh, 0.f);
    r.y = fmaxf(v.y * sc + sh, 0.f);
    r.z = fmaxf(v.z * sc + sh, 0.f);
    r.w = fmaxf(v.w * sc + sh, 0.f);
    *(float4*)&out[base] = r;
}

// ---------------- launcher ----------------
extern "C" void kernel_launch(void* const* d_in, const int* in_sizes, int n_in,
                              void* d_out, int out_size) {
    const float* x    = (const float*)d_in[0];
    const float* s    = (const float*)d_in[1];
    const float* up_w = (const float*)d_in[2];
    const float* up_b = (const float*)d_in[3];
    const float* wq   = (const float*)d_in[4];
    const float* wkl  = (const float*)d_in[5];
    const float* wkr  = (const float*)d_in[6];
    const float* c1_w = (const float*)d_in[7];
    const float* c1_b = (const float*)d_in[8];
    const float* bn_g = (const float*)d_in[9];
    const float* bn_b = (const float*)d_in[10];
    float* out = (float*)d_out;

    dim3 blk(16, 16);
    proj_kernel<<<dim3(8, 2, NS * 3), blk>>>(x, wq, wkl, wkr);
    sumz_kernel<<<dim3(NS, 2), 128>>>();
    kv_kernel<<<dim3(2, 16, NS * 2), blk>>>(x);
    attnout_kernel<<<dim3(8, 16, NS), blk>>>(x);
    convt_mma_kernel<<<dim3(16, 4, BB), 256>>>(x, up_w, up_b, s);
    zero_kernel<<<1, OUTC>>>();
    conv_mma_kernel<<<dim3(16, 4, BB), 256>>>(s, c1_w, c1_b);
    bnstats_kernel<<<1, OUTC>>>(bn_g, bn_b);
    int total4 = BB * OUTC * OH * OW / 4;
    bnorm_kernel<<<(total4 + 255) / 256, 256>>>(out);
}

// round 4
// speedup vs baseline: 2.2100x; 1.1704x over previous
#include <cuda_runtime.h>
#include <math.h>

#define BB 16
#define INC 512
#define OUTC 256
#define HH 32
#define WW 32
#define FD 1024
#define DK 128
#define NS 14          // interior samples (B-2)
#define OH 64
#define OW 64

// ---------------- scratch (static device memory; no allocation) ----------------
__device__ float g_mid[NS * INC * FD];        // rotatory outputs for batches 1..14
__device__ float g_q[NS * INC * DK];
__device__ float g_kl[NS * INC * DK];
__device__ float g_kr[NS * INC * DK];
__device__ float g_kvl[NS * DK * FD];
__device__ float g_kvr[NS * DK * FD];
__device__ float g_z[2 * NS * INC];           // [side][sample][row]
__device__ float g_gate[BB * OUTC * OH * OW]; // gated branch (first 256 channels of cat)
__device__ float g_y[BB * OUTC * OH * OW];    // conv3x3 pre-BN output
__device__ float g_bnsum[OUTC];
__device__ float g_bnsq[OUTC];
__device__ float g_bnscale[OUTC];
__device__ float g_bnshift[OUTC];

// ---------------- tf32 mma helpers ----------------
__device__ __forceinline__ unsigned f2tf(float f) {
    unsigned r;
    asm("cvt.rna.tf32.f32 %0, %1;" : "=r"(r) : "f"(f));
    return r;
}

__device__ __forceinline__ void mma_tf32(float (&d)[4], const unsigned (&a)[4], const unsigned (&b)[2]) {
    asm("mma.sync.aligned.m16n8k8.row.col.f32.tf32.tf32.f32 "
        "{%0,%1,%2,%3}, {%4,%5,%6,%7}, {%8,%9}, {%0,%1,%2,%3};"
        : "+f"(d[0]), "+f"(d[1]), "+f"(d[2]), "+f"(d[3])
        : "r"(a[0]), "r"(a[1]), "r"(a[2]), "r"(a[3]), "r"(b[0]), "r"(b[1]));
}

// ---------------- kernel 1: projections q/kl/kr = phi(A @ W) ----------------
__global__ __launch_bounds__(256) void proj_kernel(
    const float* __restrict__ x, const float* __restrict__ wq,
    const float* __restrict__ wkl, const float* __restrict__ wkr) {
    int zi = blockIdx.z;
    int sample = zi / 3, p = zi % 3;
    const float* A;
    const float* Wm;
    float* C;
    if (p == 0)      { A = x + (size_t)(sample + 1) * INC * FD; Wm = wq;  C = g_q  + (size_t)sample * INC * DK; }
    else if (p == 1) { A = x + (size_t)(sample + 0) * INC * FD; Wm = wkl; C = g_kl + (size_t)sample * INC * DK; }
    else             { A = x + (size_t)(sample + 2) * INC * FD; Wm = wkr; C = g_kr + (size_t)sample * INC * DK; }

    __shared__ float As[16][68];
    __shared__ float Bs[16][64];
    int m0 = blockIdx.x * 64;
    int n0 = blockIdx.y * 64;
    int tid = threadIdx.y * 16 + threadIdx.x;
    float acc[4][4] = {};
    for (int k0 = 0; k0 < FD; k0 += 16) {
#pragma unroll
        for (int it = 0; it < 4; it++) {
            int idx = it * 256 + tid;
            int m = idx >> 4, kk = idx & 15;
            As[kk][m] = A[(m0 + m) * FD + k0 + kk];
        }
#pragma unroll
        for (int it = 0; it < 4; it++) {
            int idx = it * 256 + tid;
            int kk = idx >> 6, n = idx & 63;
            Bs[kk][n] = Wm[(k0 + kk) * DK + n0 + n];
        }
        __syncthreads();
#pragma unroll
        for (int kk = 0; kk < 16; kk++) {
            float4 a4 = *(const float4*)&As[kk][threadIdx.y * 4];
            float4 b4 = *(const float4*)&Bs[kk][threadIdx.x * 4];
            float a[4] = {a4.x, a4.y, a4.z, a4.w};
            float b[4] = {b4.x, b4.y, b4.z, b4.w};
#pragma unroll
            for (int i = 0; i < 4; i++)
#pragma unroll
                for (int j = 0; j < 4; j++) acc[i][j] += a[i] * b[j];
        }
        __syncthreads();
    }
#pragma unroll
    for (int i = 0; i < 4; i++) {
        int m = m0 + threadIdx.y * 4 + i;
#pragma unroll
        for (int j = 0; j < 4; j++) {
            int n = n0 + threadIdx.x * 4 + j;
            float v = acc[i][j];
            C[m * DK + n] = (v > 0.f) ? (v + 1.f) : expf(v);  // elu(v)+1
        }
    }
}

// ---------------- kernel 2: column sums + z = q @ ksum + 1e-6 ----------------
__global__ void sumz_kernel() {
    int sample = blockIdx.x;
    int side = blockIdx.y;  // 0=l, 1=r
    const float* K = (side == 0 ? g_kl : g_kr) + (size_t)sample * INC * DK;
    const float* Q = g_q + (size_t)sample * INC * DK;
    __shared__ float ssum[DK];
    int t = threadIdx.x;  // 128 threads
    float s = 0.f;
    for (int n = 0; n < INC; n++) s += K[n * DK + t];
    ssum[t] = s;
    __syncthreads();
    float* Z = g_z + (size_t)(side * NS + sample) * INC;
    for (int rr = 0; rr < 4; rr++) {
        int row = rr * 128 + t;
        float d = 0.f;
        for (int k = 0; k < DK; k++) d += Q[row * DK + k] * ssum[k];
        Z[row] = d + 1e-6f;
    }
}

// ---------------- kernel 3: kv[k][d] = sum_n K[n][k] * V[n][d] ----------------
__global__ __launch_bounds__(256) void kv_kernel(const float* __restrict__ x) {
    int zi = blockIdx.z;
    int sample = zi >> 1, side = zi & 1;
    const float* K = (side == 0 ? g_kl : g_kr) + (size_t)sample * INC * DK;
    const float* V = x + (size_t)(sample + (side == 0 ? 0 : 2)) * INC * FD;
    float* C = (side == 0 ? g_kvl : g_kvr) + (size_t)sample * DK * FD;
    __shared__ float As[16][68];  // [nn][k]
    __shared__ float Bs[16][64];  // [nn][d]
    int m0 = blockIdx.x * 64;  // k dim (128)
    int n0 = blockIdx.y * 64;  // d dim (1024)
    int tid = threadIdx.y * 16 + threadIdx.x;
    float acc[4][4] = {};
    for (int c0 = 0; c0 < INC; c0 += 16) {
#pragma unroll
        for (int it = 0; it < 4; it++) {
            int idx = it * 256 + tid;
            int nn = idx >> 6, k = idx & 63;
            As[nn][k] = K[(c0 + nn) * DK + m0 + k];
        }
#pragma unroll
        for (int it = 0; it < 4; it++) {
            int idx = it * 256 + tid;
            int nn = idx >> 6, d = idx & 63;
            Bs[nn][d] = V[(c0 + nn) * FD + n0 + d];
        }
        __syncthreads();
#pragma unroll
        for (int nn = 0; nn < 16; nn++) {
            float4 a4 = *(const float4*)&As[nn][threadIdx.y * 4];
            float4 b4 = *(const float4*)&Bs[nn][threadIdx.x * 4];
            float a[4] = {a4.x, a4.y, a4.z, a4.w};
            float b[4] = {b4.x, b4.y, b4.z, b4.w};
#pragma unroll
            for (int i = 0; i < 4; i++)
#pragma unroll
                for (int j = 0; j < 4; j++) acc[i][j] += a[i] * b[j];
        }
        __syncthreads();
    }
#pragma unroll
    for (int i = 0; i < 4; i++) {
        int m = m0 + threadIdx.y * 4 + i;
#pragma unroll
        for (int j = 0; j < 4; j++) {
            int d = n0 + threadIdx.x * 4 + j;
            C[m * FD + d] = acc[i][j];
        }
    }
}

// ------ kernel 4: out = x + (q@kvl)/zl + (q@kvr)/zr  (dual-B GEMM, K=128) ------
__global__ __launch_bounds__(256) void attnout_kernel(const float* __restrict__ x) {
    int sample = blockIdx.z;
    const float* Q = g_q + (size_t)sample * INC * DK;
    const float* KVL = g_kvl + (size_t)sample * DK * FD;
    const float* KVR = g_kvr + (size_t)sample * DK * FD;
    const float* Zl = g_z + (size_t)sample * INC;
    const float* Zr = g_z + (size_t)(NS + sample) * INC;
    const float* X = x + (size_t)(sample + 1) * INC * FD;
    float* C = g_mid + (size_t)sample * INC * FD;
    __shared__ float As[16][68];
    __shared__ float Bl[16][64];
    __shared__ float Br[16][64];
    int m0 = blockIdx.x * 64;
    int n0 = blockIdx.y * 64;
    int tid = threadIdx.y * 16 + threadIdx.x;
    float accl[4][4] = {}, accr[4][4] = {};
    for (int k0 = 0; k0 < DK; k0 += 16) {
#pragma unroll
        for (int it = 0; it < 4; it++) {
            int idx = it * 256 + tid;
            int m = idx >> 4, kk = idx & 15;
            As[kk][m] = Q[(m0 + m) * DK + k0 + kk];
        }
#pragma unroll
        for (int it = 0; it < 4; it++) {
            int idx = it * 256 + tid;
            int kk = idx >> 6, n = idx & 63;
            Bl[kk][n] = KVL[(k0 + kk) * FD + n0 + n];
            Br[kk][n] = KVR[(k0 + kk) * FD + n0 + n];
        }
        __syncthreads();
#pragma unroll
        for (int kk = 0; kk < 16; kk++) {
            float4 a4 = *(const float4*)&As[kk][threadIdx.y * 4];
            float4 bl4 = *(const float4*)&Bl[kk][threadIdx.x * 4];
            float4 br4 = *(const float4*)&Br[kk][threadIdx.x * 4];
            float a[4] = {a4.x, a4.y, a4.z, a4.w};
            float bl[4] = {bl4.x, bl4.y, bl4.z, bl4.w};
            float br[4] = {br4.x, br4.y, br4.z, br4.w};
#pragma unroll
            for (int i = 0; i < 4; i++)
#pragma unroll
                for (int j = 0; j < 4; j++) {
                    accl[i][j] += a[i] * bl[j];
                    accr[i][j] += a[i] * br[j];
                }
        }
        __syncthreads();
    }
#pragma unroll
    for (int i = 0; i < 4; i++) {
        int m = m0 + threadIdx.y * 4 + i;
        float zl = Zl[m], zr = Zr[m];
#pragma unroll
        for (int j = 0; j < 4; j++) {
            int d = n0 + threadIdx.x * 4 + j;
            C[m * FD + d] = X[m * FD + d] + accl[i][j] / zl + accr[i][j] / zr;
        }
    }
}

// ------ kernel 5: ConvTranspose 2x2 s2 via tf32 mma + fused gate ------
__global__ __launch_bounds__(256) void convt_mma_kernel(
    const float* __restrict__ x, const float* __restrict__ upw,
    const float* __restrict__ upb, const float* __restrict__ s) {
    int n = blockIdx.z;
    const float* src = (n == 0) ? x
                     : (n == BB - 1) ? (x + (size_t)(BB - 1) * INC * FD)
                     : (g_mid + (size_t)(n - 1) * INC * FD);
    int m0 = blockIdx.x * 64;   // wcol
    int n0 = blockIdx.y * 256;  // ij

    __shared__ unsigned Asu[16 * 72];   // [k][m], stride 72 (conflict-free)
    __shared__ unsigned Bsu[16 * 264];  // [k][n], stride 264 (conflict-free)

    int tid = threadIdx.x;
    int warp = tid >> 5, lane = tid & 31;
    int wm = warp & 1;
    int wn = warp >> 1;
    int qr = lane >> 2;
    int qc = lane & 3;

    float acc[2][8][4];
#pragma unroll
    for (int mi = 0; mi < 2; mi++)
#pragma unroll
        for (int j = 0; j < 8; j++)
#pragma unroll
            for (int c = 0; c < 4; c++) acc[mi][j][c] = 0.f;

    for (int c0 = 0; c0 < INC; c0 += 16) {
#pragma unroll
        for (int it = 0; it < 4; it++) {
            int e = it * 256 + tid;
            int cc = e >> 6, m = e & 63;
            Asu[cc * 72 + m] = f2tf(upw[(size_t)(c0 + cc) * 1024 + m0 + m]);
        }
#pragma unroll
        for (int it = 0; it < 4; it++) {
            int e = it * 256 + tid;
            int cc = e >> 6, c4 = (e & 63) * 4;
            float4 v = *(const float4*)&src[(size_t)(c0 + cc) * FD + n0 + c4];
            unsigned* bp = &Bsu[cc * 264 + c4];
            bp[0] = f2tf(v.x); bp[1] = f2tf(v.y); bp[2] = f2tf(v.z); bp[3] = f2tf(v.w);
        }
        __syncthreads();
#pragma unroll
        for (int k8 = 0; k8 < 2; k8++) {
            unsigned a[2][4];
            int ra0 = (k8 * 8 + qc) * 72;
            int ra1 = (k8 * 8 + qc + 4) * 72;
#pragma unroll
            for (int mi = 0; mi < 2; mi++) {
                int ocb = wm * 32 + mi * 16 + qr;
                a[mi][0] = Asu[ra0 + ocb];
                a[mi][1] = Asu[ra0 + ocb + 8];
                a[mi][2] = Asu[ra1 + ocb];
                a[mi][3] = Asu[ra1 + ocb + 8];
            }
            int rb0 = (k8 * 8 + qc) * 264 + wn * 64 + qr;
            int rb1 = (k8 * 8 + qc + 4) * 264 + wn * 64 + qr;
#pragma unroll
            for (int j = 0; j < 8; j++) {
                unsigned b[2] = {Bsu[rb0 + j * 8], Bsu[rb1 + j * 8]};
                mma_tf32(acc[0][j], a[0], b);
                mma_tf32(acc[1][j], a[1], b);
            }
        }
        __syncthreads();
    }
    // epilogue: bias + skip + relu + sigmoid, scatter to g_gate
#pragma unroll
    for (int mi = 0; mi < 2; mi++) {
#pragma unroll
        for (int half = 0; half < 2; half++) {
            int row = m0 + wm * 32 + mi * 16 + half * 8 + qr;
            int o = row >> 2, ab = row & 3, av = ab >> 1, bq = ab & 1;
            float bias = upb[o];
#pragma unroll
            for (int j = 0; j < 8; j++) {
#pragma unroll
                for (int cc = 0; cc < 2; cc++) {
                    int col = n0 + wn * 64 + j * 8 + qc * 2 + cc;
                    int isp = col >> 5, jsp = col & 31;
                    int oy = 2 * isp + av, ox = 2 * jsp + bq;
                    size_t gi = (((size_t)n * OUTC + o) * OH + oy) * OW + ox;
                    float v = acc[mi][j][half * 2 + cc] + bias + s[gi];
                    v = v > 0.f ? v : 0.f;
                    g_gate[gi] = 1.f / (1.f + expf(-v));
                }
            }
        }
    }
}

// ---------------- kernel 6: conv3x3 via tf32 mma, 8-row tile, vectorized fill ----------------
// Block: 64 oc x 512 px (8 image rows). 8 warps, warp = one row, 4 m16 x 8 n8 tiles.
#define PS 744   // in_s plane stride (744 % 32 == 8, >= 10*72=720)
__global__ __launch_bounds__(256) void conv_mma_kernel(
    const float* __restrict__ sskip, const float* __restrict__ cw,
    const float* __restrict__ cb) {
    int n = blockIdx.z;
    int oc0 = blockIdx.y * 64;
    int y0 = blockIdx.x * 8;

    __shared__ unsigned in_s[8 * PS];   // [icc][yy*72 + xcol], xcol 0..65 (image col-1)
    __shared__ unsigned w_s[64 * 76];   // [oc][icc*9 + pos], stride 76 (conflict-free)
    __shared__ float rs[64], rq[64];

    int tid = threadIdx.x;
    int warp = tid >> 5, lane = tid & 31;
    int wn = warp;            // image row within 8-row tile
    int qr = lane >> 2;       // 0..7
    int qc = lane & 3;        // 0..3

    // halo columns (image cols -1 and 64) are always zero-pad: write once
    for (int e = tid; e < 160; e += 256) {
        int r = e >> 1;
        int icc = r / 10, yy = r - icc * 10;
        in_s[icc * PS + yy * 72 + ((e & 1) ? 65 : 0)] = 0u;
    }
    if (tid < 64) { rs[tid] = 0.f; rq[tid] = 0.f; }

    float acc[4][8][4] = {};

    int seg = (tid & 15) * 4;  // x start of this thread's float4
    for (int ic0 = 0; ic0 < 2 * OUTC; ic0 += 8) {
        // interior fill: 80 (icc,yy) rows x 16 float4 segments
        for (int r = tid >> 4; r < 80; r += 16) {
            int icc = r / 10, yy = r - icc * 10;
            int gy = y0 + yy - 1;
            int ic = ic0 + icc;
            unsigned* dst = &in_s[icc * PS + yy * 72 + 1 + seg];
            if ((unsigned)gy < (unsigned)OH) {
                const float* srcp = (ic < OUTC)
                    ? &g_gate[(((size_t)n * OUTC + ic) * OH + gy) * OW + seg]
                    : &sskip[(((size_t)n * OUTC + (ic - OUTC)) * OH + gy) * OW + seg];
                float4 v = *(const float4*)srcp;
                dst[0] = f2tf(v.x); dst[1] = f2tf(v.y); dst[2] = f2tf(v.z); dst[3] = f2tf(v.w);
            } else {
                dst[0] = 0u; dst[1] = 0u; dst[2] = 0u; dst[3] = 0u;
            }
        }
        // weights: 64 oc x (8 icc * 9 pos) contiguous, float4 load + tf32 convert
        for (int e = tid; e < 64 * 18; e += 256) {
            int oc = e / 18, f = e - oc * 18;
            float4 v = *(const float4*)&cw[(size_t)(oc0 + oc) * (2 * OUTC * 9) + ic0 * 9 + f * 4];
            unsigned* wp = &w_s[oc * 76 + f * 4];
            wp[0] = f2tf(v.x); wp[1] = f2tf(v.y); wp[2] = f2tf(v.z); wp[3] = f2tf(v.w);
        }
        __syncthreads();

#pragma unroll
        for (int ky = 0; ky < 3; ky++) {
            int rowoff = (wn + ky) * 72;
#pragma unroll
            for (int kx = 0; kx < 3; kx++) {
                int pos = ky * 3 + kx;
                unsigned a[4][4];
#pragma unroll
                for (int mi = 0; mi < 4; mi++) {
                    int ocb = mi * 16 + qr;
                    a[mi][0] = w_s[ocb * 76 + qc * 9 + pos];
                    a[mi][1] = w_s[(ocb + 8) * 76 + qc * 9 + pos];
                    a[mi][2] = w_s[ocb * 76 + (qc + 4) * 9 + pos];
                    a[mi][3] = w_s[(ocb + 8) * 76 + (qc + 4) * 9 + pos];
                }
#pragma unroll
                for (int j = 0; j < 8; j++) {
                    int col = j * 8 + qr + kx;
                    unsigned b[2] = {in_s[qc * PS + rowoff + col],
                                     in_s[(qc + 4) * PS + rowoff + col]};
                    mma_tf32(acc[0][j], a[0], b);
                    mma_tf32(acc[1][j], a[1], b);
                    mma_tf32(acc[2][j], a[2], b);
                    mma_tf32(acc[3][j], a[3], b);
                }
            }
        }
        __syncthreads();
    }

    // epilogue: bias, store y, BN partial sums
    int row = y0 + wn;
#pragma unroll
    for (int mi = 0; mi < 4; mi++) {
#pragma unroll
        for (int half = 0; half < 2; half++) {
            int ocl = mi * 16 + half * 8 + qr;
            int oc = oc0 + ocl;
            float bias = cb[oc];
            float s0 = 0.f, s1 = 0.f;
#pragma unroll
            for (int j = 0; j < 8; j++) {
#pragma unroll
                for (int cc = 0; cc < 2; cc++) {
                    float v = acc[mi][j][half * 2 + cc] + bias;
                    int col = j * 8 + qc * 2 + cc;
                    g_y[(((size_t)n * OUTC + oc) * OH + row) * OW + col] = v;
                    s0 += v;
                    s1 += v * v;
                }
            }
            s0 += __shfl_xor_sync(0xffffffffu, s0, 1);
            s0 += __shfl_xor_sync(0xffffffffu, s0, 2);
            s1 += __shfl_xor_sync(0xffffffffu, s1, 1);
            s1 += __shfl_xor_sync(0xffffffffu, s1, 2);
            if (qc == 0) {
                atomicAdd(&rs[ocl], s0);
                atomicAdd(&rq[ocl], s1);
            }
        }
    }
    __syncthreads();
    if (tid < 64) {
        atomicAdd(&g_bnsum[oc0 + tid], rs[tid]);
        atomicAdd(&g_bnsq[oc0 + tid], rq[tid]);
    }
}

// ---------------- small kernels ----------------
__global__ void zero_kernel() {
    int t = threadIdx.x;
    g_bnsum[t] = 0.f;
    g_bnsq[t] = 0.f;
}

__global__ void bnstats_kernel(const float* __restrict__ bn_g, const float* __restrict__ bn_b) {
    int c = threadIdx.x;
    float cnt = (float)(BB * OH * OW);
    float mean = g_bnsum[c] / cnt;
    float var = g_bnsq[c] / cnt - mean * mean;
    float inv = rsqrtf(var + 1e-5f);
    float sc = bn_g[c] * inv;
    g_bnscale[c] = sc;
    g_bnshift[c] = bn_b[c] - mean * sc;
}

__global__ void bnorm_kernel(float* __restrict__ out) {
    int i4 = blockIdx.x * blockDim.x + threadIdx.x;
    const int total4 = BB * OUTC * OH * OW / 4;
    if (i4 >= total4) return;
    int base = i4 * 4;
    int oc = (base >> 12) & (OUTC - 1);  // OH*OW = 4096
    float sc = g_bnscale[oc], sh = g_bnshift[oc];
    float4 v = *(const float4*)&g_y[base];
    float4 r;
    r.x = fmaxf(v.x * sc + sh, 0.f);
    r.y = fmaxf(v.y * sc + sh, 0.f);
    r.z = fmaxf(v.z * sc + sh, 0.f);
    r.w = fmaxf(v.w * sc + sh, 0.f);
    *(float4*)&out[base] = r;
}

// ---------------- launcher ----------------
extern "C" void kernel_launch(void* const* d_in, const int* in_sizes, int n_in,
                              void* d_out, int out_size) {
    const float* x    = (const float*)d_in[0];
    const float* s    = (const float*)d_in[1];
    const float* up_w = (const float*)d_in[2];
    const float* up_b = (const float*)d_in[3];
    const float* wq   = (const float*)d_in[4];
    const float* wkl  = (const float*)d_in[5];
    const float* wkr  = (const float*)d_in[6];
    const float* c1_w = (const float*)d_in[7];
    const float* c1_b = (const float*)d_in[8];
    const float* bn_g = (const float*)d_in[9];
    const float* bn_b = (const float*)d_in[10];
    float* out = (float*)d_out;

    dim3 blk(16, 16);
    proj_kernel<<<dim3(8, 2, NS * 3), blk>>>(x, wq, wkl, wkr);
    sumz_kernel<<<dim3(NS, 2), 128>>>();
    kv_kernel<<<dim3(2, 16, NS * 2), blk>>>(x);
    attnout_kernel<<<dim3(8, 16, NS), blk>>>(x);
    convt_mma_kernel<<<dim3(16, 4, BB), 256>>>(x, up_w, up_b, s);
    zero_kernel<<<1, OUTC>>>();
    conv_mma_kernel<<<dim3(8, 4, BB), 256>>>(s, c1_w, c1_b);
    bnstats_kernel<<<1, OUTC>>>(bn_g, bn_b);
    int total4 = BB * OUTC * OH * OW / 4;
    bnorm_kernel<<<(total4 + 255) / 256, 256>>>(out);
}

// round 5
// speedup vs baseline: 2.3563x; 1.0662x over previous
#include <cuda_runtime.h>
#include <math.h>

#define BB 16
#define INC 512
#define OUTC 256
#define HH 32
#define WW 32
#define FD 1024
#define DK 128
#define NS 14          // interior samples (B-2)
#define OH 64
#define OW 64

// ---------------- scratch (static device memory; no allocation) ----------------
__device__ float g_mid[NS * INC * FD];        // rotatory outputs for batches 1..14
__device__ float g_q[NS * INC * DK];
__device__ float g_kl[NS * INC * DK];
__device__ float g_kr[NS * INC * DK];
__device__ float g_kvl[NS * DK * FD];
__device__ float g_kvr[NS * DK * FD];
__device__ float g_z[2 * NS * INC];           // [side][sample][row]
__device__ float g_gate[BB * OUTC * OH * OW]; // gated branch (first 256 channels of cat)
__device__ float g_y[BB * OUTC * OH * OW];    // conv3x3 pre-BN output
__device__ float g_bnsum[OUTC];
__device__ float g_bnsq[OUTC];
__device__ float g_bnscale[OUTC];
__device__ float g_bnshift[OUTC];

// ---------------- tf32 mma helpers ----------------
__device__ __forceinline__ unsigned f2tf(float f) {
    unsigned r;
    asm("cvt.rna.tf32.f32 %0, %1;" : "=r"(r) : "f"(f));
    return r;
}

__device__ __forceinline__ void mma_tf32(float (&d)[4], const unsigned (&a)[4], const unsigned (&b)[2]) {
    asm("mma.sync.aligned.m16n8k8.row.col.f32.tf32.tf32.f32 "
        "{%0,%1,%2,%3}, {%4,%5,%6,%7}, {%8,%9}, {%0,%1,%2,%3};"
        : "+f"(d[0]), "+f"(d[1]), "+f"(d[2]), "+f"(d[3])
        : "r"(a[0]), "r"(a[1]), "r"(a[2]), "r"(a[3]), "r"(b[0]), "r"(b[1]));
}

// ---------------- kernel 1: projections q/kl/kr = phi(A @ W), tf32 mma ----------------
// A (512x1024) @ W (1024x128). Block tile 64(m) x 128(n). 8 warps = 4(m16) x 2(n64).
__global__ __launch_bounds__(256) void proj_mma_kernel(
    const float* __restrict__ x, const float* __restrict__ wq,
    const float* __restrict__ wkl, const float* __restrict__ wkr) {
    int zi = blockIdx.z;
    int sample = zi / 3, p = zi % 3;
    const float* A;
    const float* Wm;
    float* C;
    if (p == 0)      { A = x + (size_t)(sample + 1) * INC * FD; Wm = wq;  C = g_q  + (size_t)sample * INC * DK; }
    else if (p == 1) { A = x + (size_t)(sample + 0) * INC * FD; Wm = wkl; C = g_kl + (size_t)sample * INC * DK; }
    else             { A = x + (size_t)(sample + 2) * INC * FD; Wm = wkr; C = g_kr + (size_t)sample * INC * DK; }

    __shared__ unsigned Asu[16 * 72];   // [k][m]
    __shared__ unsigned Bsu[16 * 136];  // [k][n]

    int m0 = blockIdx.x * 64;
    int tid = threadIdx.x;
    int warp = tid >> 5, lane = tid & 31;
    int wm = warp & 3;        // m16 tile
    int wn = warp >> 2;       // n 64-col half
    int qr = lane >> 2, qc = lane & 3;

    float acc[8][4] = {};

    for (int k0 = 0; k0 < FD; k0 += 16) {
#pragma unroll
        for (int it = 0; it < 4; it++) {
            int idx = it * 256 + tid;
            int m = idx >> 4, kk = idx & 15;
            Asu[kk * 72 + m] = f2tf(A[(size_t)(m0 + m) * FD + k0 + kk]);
        }
#pragma unroll
        for (int it = 0; it < 2; it++) {
            int e = it * 256 + tid;
            int kk = e >> 5, c4 = (e & 31) * 4;
            float4 v = *(const float4*)&Wm[(size_t)(k0 + kk) * DK + c4];
            unsigned* bp = &Bsu[kk * 136 + c4];
            bp[0] = f2tf(v.x); bp[1] = f2tf(v.y); bp[2] = f2tf(v.z); bp[3] = f2tf(v.w);
        }
        __syncthreads();
#pragma unroll
        for (int k8 = 0; k8 < 2; k8++) {
            int ra0 = (k8 * 8 + qc) * 72;
            int ra1 = (k8 * 8 + qc + 4) * 72;
            unsigned a[4];
            int mb = wm * 16 + qr;
            a[0] = Asu[ra0 + mb];
            a[1] = Asu[ra0 + mb + 8];
            a[2] = Asu[ra1 + mb];
            a[3] = Asu[ra1 + mb + 8];
            int rb0 = (k8 * 8 + qc) * 136 + wn * 64 + qr;
            int rb1 = (k8 * 8 + qc + 4) * 136 + wn * 64 + qr;
#pragma unroll
            for (int j = 0; j < 8; j++) {
                unsigned b[2] = {Bsu[rb0 + j * 8], Bsu[rb1 + j * 8]};
                mma_tf32(acc[j], a, b);
            }
        }
        __syncthreads();
    }
    // epilogue: phi = elu + 1
#pragma unroll
    for (int half = 0; half < 2; half++) {
        int m = m0 + wm * 16 + half * 8 + qr;
#pragma unroll
        for (int j = 0; j < 8; j++) {
#pragma unroll
            for (int cc = 0; cc < 2; cc++) {
                int ncol = wn * 64 + j * 8 + qc * 2 + cc;
                float v = acc[j][half * 2 + cc];
                C[(size_t)m * DK + ncol] = (v > 0.f) ? (v + 1.f) : expf(v);
            }
        }
    }
}

// ---------------- kernel 2: column sums + z = q @ ksum + 1e-6 ----------------
__global__ void sumz_kernel() {
    int sample = blockIdx.x;
    int side = blockIdx.y;  // 0=l, 1=r
    const float* K = (side == 0 ? g_kl : g_kr) + (size_t)sample * INC * DK;
    const float* Q = g_q + (size_t)sample * INC * DK;
    __shared__ float ssum[DK];
    int t = threadIdx.x;  // 128 threads
    float s = 0.f;
    for (int n = 0; n < INC; n++) s += K[n * DK + t];
    ssum[t] = s;
    __syncthreads();
    float* Z = g_z + (size_t)(side * NS + sample) * INC;
    for (int rr = 0; rr < 4; rr++) {
        int row = rr * 128 + t;
        float d = 0.f;
        for (int k = 0; k < DK; k++) d += Q[row * DK + k] * ssum[k];
        Z[row] = d + 1e-6f;
    }
}

// ---------------- kernel 3: kv[k][d] = sum_n K[n][k] * V[n][d], tf32 mma ----------------
// M=128 (k), N=1024 (d), reduce over n=512. Block tile 64x256. 8 warps = 2(m) x 4(n).
__global__ __launch_bounds__(256) void kv_mma_kernel(const float* __restrict__ x) {
    int zi = blockIdx.z;
    int sample = zi >> 1, side = zi & 1;
    const float* K = (side == 0 ? g_kl : g_kr) + (size_t)sample * INC * DK;
    const float* V = x + (size_t)(sample + (side == 0 ? 0 : 2)) * INC * FD;
    float* C = (side == 0 ? g_kvl : g_kvr) + (size_t)sample * DK * FD;

    __shared__ unsigned Asu[16 * 72];   // [nn][k]
    __shared__ unsigned Bsu[16 * 264];  // [nn][d]

    int m0 = blockIdx.x * 64;   // k dim
    int n0 = blockIdx.y * 256;  // d dim
    int tid = threadIdx.x;
    int warp = tid >> 5, lane = tid & 31;
    int wm = warp & 1, wn = warp >> 1;
    int qr = lane >> 2, qc = lane & 3;

    float acc[2][8][4] = {};

    for (int c0 = 0; c0 < INC; c0 += 16) {
#pragma unroll
        for (int it = 0; it < 4; it++) {
            int idx = it * 256 + tid;
            int nn = idx >> 6, k = idx & 63;
            Asu[nn * 72 + k] = f2tf(K[(size_t)(c0 + nn) * DK + m0 + k]);
        }
#pragma unroll
        for (int it = 0; it < 4; it++) {
            int e = it * 256 + tid;
            int nn = e >> 6, c4 = (e & 63) * 4;
            float4 v = *(const float4*)&V[(size_t)(c0 + nn) * FD + n0 + c4];
            unsigned* bp = &Bsu[nn * 264 + c4];
            bp[0] = f2tf(v.x); bp[1] = f2tf(v.y); bp[2] = f2tf(v.z); bp[3] = f2tf(v.w);
        }
        __syncthreads();
#pragma unroll
        for (int k8 = 0; k8 < 2; k8++) {
            unsigned a[2][4];
            int ra0 = (k8 * 8 + qc) * 72;
            int ra1 = (k8 * 8 + qc + 4) * 72;
#pragma unroll
            for (int mi = 0; mi < 2; mi++) {
                int mb = wm * 32 + mi * 16 + qr;
                a[mi][0] = Asu[ra0 + mb];
                a[mi][1] = Asu[ra0 + mb + 8];
                a[mi][2] = Asu[ra1 + mb];
                a[mi][3] = Asu[ra1 + mb + 8];
            }
            int rb0 = (k8 * 8 + qc) * 264 + wn * 64 + qr;
            int rb1 = (k8 * 8 + qc + 4) * 264 + wn * 64 + qr;
#pragma unroll
            for (int j = 0; j < 8; j++) {
                unsigned b[2] = {Bsu[rb0 + j * 8], Bsu[rb1 + j * 8]};
                mma_tf32(acc[0][j], a[0], b);
                mma_tf32(acc[1][j], a[1], b);
            }
        }
        __syncthreads();
    }
#pragma unroll
    for (int mi = 0; mi < 2; mi++) {
#pragma unroll
        for (int half = 0; half < 2; half++) {
            int m = m0 + wm * 32 + mi * 16 + half * 8 + qr;
#pragma unroll
            for (int j = 0; j < 8; j++) {
#pragma unroll
                for (int cc = 0; cc < 2; cc++) {
                    int d = n0 + wn * 64 + j * 8 + qc * 2 + cc;
                    C[(size_t)m * FD + d] = acc[mi][j][half * 2 + cc];
                }
            }
        }
    }
}

// ------ kernel 4: out = x + (q@kvl)/zl + (q@kvr)/zr, dual-B tf32 mma ------
// M=512, N=1024, K=128. Block tile 64x256, 8 warps = 2(m) x 4(n).
__global__ __launch_bounds__(256) void attnout_mma_kernel(const float* __restrict__ x) {
    int sample = blockIdx.z;
    const float* Q = g_q + (size_t)sample * INC * DK;
    const float* KVL = g_kvl + (size_t)sample * DK * FD;
    const float* KVR = g_kvr + (size_t)sample * DK * FD;
    const float* Zl = g_z + (size_t)sample * INC;
    const float* Zr = g_z + (size_t)(NS + sample) * INC;
    const float* X = x + (size_t)(sample + 1) * INC * FD;
    float* C = g_mid + (size_t)sample * INC * FD;

    __shared__ unsigned Asu[16 * 72];
    __shared__ unsigned Blu[16 * 264];
    __shared__ unsigned Bru[16 * 264];

    int m0 = blockIdx.x * 64;
    int n0 = blockIdx.y * 256;
    int tid = threadIdx.x;
    int warp = tid >> 5, lane = tid & 31;
    int wm = warp & 1, wn = warp >> 1;
    int qr = lane >> 2, qc = lane & 3;

    float accl[2][8][4] = {}, accr[2][8][4] = {};

    for (int k0 = 0; k0 < DK; k0 += 16) {
#pragma unroll
        for (int it = 0; it < 4; it++) {
            int idx = it * 256 + tid;
            int m = idx >> 4, kk = idx & 15;
            Asu[kk * 72 + m] = f2tf(Q[(size_t)(m0 + m) * DK + k0 + kk]);
        }
#pragma unroll
        for (int it = 0; it < 4; it++) {
            int e = it * 256 + tid;
            int kk = e >> 6, c4 = (e & 63) * 4;
            float4 vl = *(const float4*)&KVL[(size_t)(k0 + kk) * FD + n0 + c4];
            float4 vr = *(const float4*)&KVR[(size_t)(k0 + kk) * FD + n0 + c4];
            unsigned* bl = &Blu[kk * 264 + c4];
            unsigned* br = &Bru[kk * 264 + c4];
            bl[0] = f2tf(vl.x); bl[1] = f2tf(vl.y); bl[2] = f2tf(vl.z); bl[3] = f2tf(vl.w);
            br[0] = f2tf(vr.x); br[1] = f2tf(vr.y); br[2] = f2tf(vr.z); br[3] = f2tf(vr.w);
        }
        __syncthreads();
#pragma unroll
        for (int k8 = 0; k8 < 2; k8++) {
            unsigned a[2][4];
            int ra0 = (k8 * 8 + qc) * 72;
            int ra1 = (k8 * 8 + qc + 4) * 72;
#pragma unroll
            for (int mi = 0; mi < 2; mi++) {
                int mb = wm * 32 + mi * 16 + qr;
                a[mi][0] = Asu[ra0 + mb];
                a[mi][1] = Asu[ra0 + mb + 8];
                a[mi][2] = Asu[ra1 + mb];
                a[mi][3] = Asu[ra1 + mb + 8];
            }
            int rb0 = (k8 * 8 + qc) * 264 + wn * 64 + qr;
            int rb1 = (k8 * 8 + qc + 4) * 264 + wn * 64 + qr;
#pragma unroll
            for (int j = 0; j < 8; j++) {
                unsigned bl[2] = {Blu[rb0 + j * 8], Blu[rb1 + j * 8]};
                unsigned br[2] = {Bru[rb0 + j * 8], Bru[rb1 + j * 8]};
                mma_tf32(accl[0][j], a[0], bl);
                mma_tf32(accl[1][j], a[1], bl);
                mma_tf32(accr[0][j], a[0], br);
                mma_tf32(accr[1][j], a[1], br);
            }
        }
        __syncthreads();
    }
#pragma unroll
    for (int mi = 0; mi < 2; mi++) {
#pragma unroll
        for (int half = 0; half < 2; half++) {
            int m = m0 + wm * 32 + mi * 16 + half * 8 + qr;
            float zl = Zl[m], zr = Zr[m];
#pragma unroll
            for (int j = 0; j < 8; j++) {
#pragma unroll
                for (int cc = 0; cc < 2; cc++) {
                    int d = n0 + wn * 64 + j * 8 + qc * 2 + cc;
                    C[(size_t)m * FD + d] = X[(size_t)m * FD + d]
                        + accl[mi][j][half * 2 + cc] / zl
                        + accr[mi][j][half * 2 + cc] / zr;
                }
            }
        }
    }
}

// ------ kernel 5: ConvTranspose 2x2 s2 via tf32 mma + fused gate ------
__global__ __launch_bounds__(256) void convt_mma_kernel(
    const float* __restrict__ x, const float* __restrict__ upw,
    const float* __restrict__ upb, const float* __restrict__ s) {
    int n = blockIdx.z;
    const float* src = (n == 0) ? x
                     : (n == BB - 1) ? (x + (size_t)(BB - 1) * INC * FD)
                     : (g_mid + (size_t)(n - 1) * INC * FD);
    int m0 = blockIdx.x * 64;   // wcol
    int n0 = blockIdx.y * 256;  // ij

    __shared__ unsigned Asu[16 * 72];
    __shared__ unsigned Bsu[16 * 264];

    int tid = threadIdx.x;
    int warp = tid >> 5, lane = tid & 31;
    int wm = warp & 1;
    int wn = warp >> 1;
    int qr = lane >> 2;
    int qc = lane & 3;

    float acc[2][8][4] = {};

    for (int c0 = 0; c0 < INC; c0 += 16) {
#pragma unroll
        for (int it = 0; it < 4; it++) {
            int e = it * 256 + tid;
            int cc = e >> 6, m = e & 63;
            Asu[cc * 72 + m] = f2tf(upw[(size_t)(c0 + cc) * 1024 + m0 + m]);
        }
#pragma unroll
        for (int it = 0; it < 4; it++) {
            int e = it * 256 + tid;
            int cc = e >> 6, c4 = (e & 63) * 4;
            float4 v = *(const float4*)&src[(size_t)(c0 + cc) * FD + n0 + c4];
            unsigned* bp = &Bsu[cc * 264 + c4];
            bp[0] = f2tf(v.x); bp[1] = f2tf(v.y); bp[2] = f2tf(v.z); bp[3] = f2tf(v.w);
        }
        __syncthreads();
#pragma unroll
        for (int k8 = 0; k8 < 2; k8++) {
            unsigned a[2][4];
            int ra0 = (k8 * 8 + qc) * 72;
            int ra1 = (k8 * 8 + qc + 4) * 72;
#pragma unroll
            for (int mi = 0; mi < 2; mi++) {
                int ocb = wm * 32 + mi * 16 + qr;
                a[mi][0] = Asu[ra0 + ocb];
                a[mi][1] = Asu[ra0 + ocb + 8];
                a[mi][2] = Asu[ra1 + ocb];
                a[mi][3] = Asu[ra1 + ocb + 8];
            }
            int rb0 = (k8 * 8 + qc) * 264 + wn * 64 + qr;
            int rb1 = (k8 * 8 + qc + 4) * 264 + wn * 64 + qr;
#pragma unroll
            for (int j = 0; j < 8; j++) {
                unsigned b[2] = {Bsu[rb0 + j * 8], Bsu[rb1 + j * 8]};
                mma_tf32(acc[0][j], a[0], b);
                mma_tf32(acc[1][j], a[1], b);
            }
        }
        __syncthreads();
    }
    // epilogue: bias + skip + relu + sigmoid, scatter to g_gate
#pragma unroll
    for (int mi = 0; mi < 2; mi++) {
#pragma unroll
        for (int half = 0; half < 2; half++) {
            int row = m0 + wm * 32 + mi * 16 + half * 8 + qr;
            int o = row >> 2, ab = row & 3, av = ab >> 1, bq = ab & 1;
            float bias = upb[o];
#pragma unroll
            for (int j = 0; j < 8; j++) {
#pragma unroll
                for (int cc = 0; cc < 2; cc++) {
                    int col = n0 + wn * 64 + j * 8 + qc * 2 + cc;
                    int isp = col >> 5, jsp = col & 31;
                    int oy = 2 * isp + av, ox = 2 * jsp + bq;
                    size_t gi = (((size_t)n * OUTC + o) * OH + oy) * OW + ox;
                    float v = acc[mi][j][half * 2 + cc] + bias + s[gi];
                    v = v > 0.f ? v : 0.f;
                    g_gate[gi] = 1.f / (1.f + expf(-v));
                }
            }
        }
    }
}

// ---------------- kernel 6: conv3x3 via tf32 mma, 8-row tile, vectorized fill ----------------
#define PS 744   // in_s plane stride (744 % 32 == 8, >= 10*72=720)
__global__ __launch_bounds__(256) void conv_mma_kernel(
    const float* __restrict__ sskip, const float* __restrict__ cw,
    const float* __restrict__ cb) {
    int n = blockIdx.z;
    int oc0 = blockIdx.y * 64;
    int y0 = blockIdx.x * 8;

    __shared__ unsigned in_s[8 * PS];   // [icc][yy*72 + xcol]
    __shared__ unsigned w_s[64 * 76];   // [oc][icc*9 + pos]
    __shared__ float rs[64], rq[64];

    int tid = threadIdx.x;
    int warp = tid >> 5, lane = tid & 31;
    int wn = warp;            // image row within 8-row tile
    int qr = lane >> 2;       // 0..7
    int qc = lane & 3;        // 0..3

    for (int e = tid; e < 160; e += 256) {
        int r = e >> 1;
        int icc = r / 10, yy = r - icc * 10;
        in_s[icc * PS + yy * 72 + ((e & 1) ? 65 : 0)] = 0u;
    }
    if (tid < 64) { rs[tid] = 0.f; rq[tid] = 0.f; }

    float acc[4][8][4] = {};

    int seg = (tid & 15) * 4;
    for (int ic0 = 0; ic0 < 2 * OUTC; ic0 += 8) {
        for (int r = tid >> 4; r < 80; r += 16) {
            int icc = r / 10, yy = r - icc * 10;
            int gy = y0 + yy - 1;
            int ic = ic0 + icc;
            unsigned* dst = &in_s[icc * PS + yy * 72 + 1 + seg];
            if ((unsigned)gy < (unsigned)OH) {
                const float* srcp = (ic < OUTC)
                    ? &g_gate[(((size_t)n * OUTC + ic) * OH + gy) * OW + seg]
                    : &sskip[(((size_t)n * OUTC + (ic - OUTC)) * OH + gy) * OW + seg];
                float4 v = *(const float4*)srcp;
                dst[0] = f2tf(v.x); dst[1] = f2tf(v.y); dst[2] = f2tf(v.z); dst[3] = f2tf(v.w);
            } else {
                dst[0] = 0u; dst[1] = 0u; dst[2] = 0u; dst[3] = 0u;
            }
        }
        for (int e = tid; e < 64 * 18; e += 256) {
            int oc = e / 18, f = e - oc * 18;
            float4 v = *(const float4*)&cw[(size_t)(oc0 + oc) * (2 * OUTC * 9) + ic0 * 9 + f * 4];
            unsigned* wp = &w_s[oc * 76 + f * 4];
            wp[0] = f2tf(v.x); wp[1] = f2tf(v.y); wp[2] = f2tf(v.z); wp[3] = f2tf(v.w);
        }
        __syncthreads();

#pragma unroll
        for (int ky = 0; ky < 3; ky++) {
            int rowoff = (wn + ky) * 72;
#pragma unroll
            for (int kx = 0; kx < 3; kx++) {
                int pos = ky * 3 + kx;
                unsigned a[4][4];
#pragma unroll
                for (int mi = 0; mi < 4; mi++) {
                    int ocb = mi * 16 + qr;
                    a[mi][0] = w_s[ocb * 76 + qc * 9 + pos];
                    a[mi][1] = w_s[(ocb + 8) * 76 + qc * 9 + pos];
                    a[mi][2] = w_s[ocb * 76 + (qc + 4) * 9 + pos];
                    a[mi][3] = w_s[(ocb + 8) * 76 + (qc + 4) * 9 + pos];
                }
#pragma unroll
                for (int j = 0; j < 8; j++) {
                    int col = j * 8 + qr + kx;
                    unsigned b[2] = {in_s[qc * PS + rowoff + col],
                                     in_s[(qc + 4) * PS + rowoff + col]};
                    mma_tf32(acc[0][j], a[0], b);
                    mma_tf32(acc[1][j], a[1], b);
                    mma_tf32(acc[2][j], a[2], b);
                    mma_tf32(acc[3][j], a[3], b);
                }
            }
        }
        __syncthreads();
    }

    int row = y0 + wn;
#pragma unroll
    for (int mi = 0; mi < 4; mi++) {
#pragma unroll
        for (int half = 0; half < 2; half++) {
            int ocl = mi * 16 + half * 8 + qr;
            int oc = oc0 + ocl;
            float bias = cb[oc];
            float s0 = 0.f, s1 = 0.f;
#pragma unroll
            for (int j = 0; j < 8; j++) {
#pragma unroll
                for (int cc = 0; cc < 2; cc++) {
                    float v = acc[mi][j][half * 2 + cc] + bias;
                    int col = j * 8 + qc * 2 + cc;
                    g_y[(((size_t)n * OUTC + oc) * OH + row) * OW + col] = v;
                    s0 += v;
                    s1 += v * v;
                }
            }
            s0 += __shfl_xor_sync(0xffffffffu, s0, 1);
            s0 += __shfl_xor_sync(0xffffffffu, s0, 2);
            s1 += __shfl_xor_sync(0xffffffffu, s1, 1);
            s1 += __shfl_xor_sync(0xffffffffu, s1, 2);
            if (qc == 0) {
                atomicAdd(&rs[ocl], s0);
                atomicAdd(&rq[ocl], s1);
            }
        }
    }
    __syncthreads();
    if (tid < 64) {
        atomicAdd(&g_bnsum[oc0 + tid], rs[tid]);
        atomicAdd(&g_bnsq[oc0 + tid], rq[tid]);
    }
}

// ---------------- small kernels ----------------
__global__ void zero_kernel() {
    int t = threadIdx.x;
    g_bnsum[t] = 0.f;
    g_bnsq[t] = 0.f;
}

__global__ void bnstats_kernel(const float* __restrict__ bn_g, const float* __restrict__ bn_b) {
    int c = threadIdx.x;
    float cnt = (float)(BB * OH * OW);
    float mean = g_bnsum[c] / cnt;
    float var = g_bnsq[c] / cnt - mean * mean;
    float inv = rsqrtf(var + 1e-5f);
    float sc = bn_g[c] * inv;
    g_bnscale[c] = sc;
    g_bnshift[c] = bn_b[c] - mean * sc;
}

__global__ void bnorm_kernel(float* __restrict__ out) {
    int i4 = blockIdx.x * blockDim.x + threadIdx.x;
    const int total4 = BB * OUTC * OH * OW / 4;
    if (i4 >= total4) return;
    int base = i4 * 4;
    int oc = (base >> 12) & (OUTC - 1);  // OH*OW = 4096
    float sc = g_bnscale[oc], sh = g_bnshift[oc];
    float4 v = *(const float4*)&g_y[base];
    float4 r;
    r.x = fmaxf(v.x * sc + sh, 0.f);
    r.y = fmaxf(v.y * sc + sh, 0.f);
    r.z = fmaxf(v.z * sc + sh, 0.f);
    r.w = fmaxf(v.w * sc + sh, 0.f);
    *(float4*)&out[base] = r;
}

// ---------------- launcher ----------------
extern "C" void kernel_launch(void* const* d_in, const int* in_sizes, int n_in,
                              void* d_out, int out_size) {
    const float* x    = (const float*)d_in[0];
    const float* s    = (const float*)d_in[1];
    const float* up_w = (const float*)d_in[2];
    const float* up_b = (const float*)d_in[3];
    const float* wq   = (const float*)d_in[4];
    const float* wkl  = (const float*)d_in[5];
    const float* wkr  = (const float*)d_in[6];
    const float* c1_w = (const float*)d_in[7];
    const float* c1_b = (const float*)d_in[8];
    const float* bn_g = (const float*)d_in[9];
    const float* bn_b = (const float*)d_in[10];
    float* out = (float*)d_out;

    proj_mma_kernel<<<dim3(8, 1, NS * 3), 256>>>(x, wq, wkl, wkr);
    sumz_kernel<<<dim3(NS, 2), 128>>>();
    kv_mma_kernel<<<dim3(2, 4, NS * 2), 256>>>(x);
    attnout_mma_kernel<<<dim3(8, 4, NS), 256>>>(x);
    convt_mma_kernel<<<dim3(16, 4, BB), 256>>>(x, up_w, up_b, s);
    zero_kernel<<<1, OUTC>>>();
    conv_mma_kernel<<<dim3(8, 4, BB), 256>>>(s, c1_w, c1_b);
    bnstats_kernel<<<1, OUTC>>>(bn_g, bn_b);
    int total4 = BB * OUTC * OH * OW / 4;
    bnorm_kernel<<<(total4 + 255) / 256, 256>>>(out);
}

// round 6
// speedup vs baseline: 3.5182x; 1.4931x over previous
#include <cuda_runtime.h>
#include <math.h>

#define BB 16
#define INC 512
#define OUTC 256
#define HH 32
#define WW 32
#define FD 1024
#define DK 128
#define NS 14          // interior samples (B-2)
#define OH 64
#define OW 64

// ---------------- scratch (static device memory; no allocation) ----------------
__device__ float g_mid[NS * INC * FD];        // rotatory outputs for batches 1..14
__device__ float g_q[NS * INC * DK];
__device__ float g_kl[NS * INC * DK];
__device__ float g_kr[NS * INC * DK];
__device__ float g_kvl[NS * DK * FD];
__device__ float g_kvr[NS * DK * FD];
__device__ float g_z[2 * NS * INC];           // [side][sample][row]
__device__ float g_gate[BB * OUTC * OH * OW]; // gated branch (first 256 channels of cat)
__device__ float g_y[BB * OUTC * OH * OW];    // conv3x3 pre-BN output
__device__ float g_bnsum[OUTC];
__device__ float g_bnsq[OUTC];
__device__ float g_bnscale[OUTC];
__device__ float g_bnshift[OUTC];

// ---------------- tf32 mma helpers ----------------
__device__ __forceinline__ unsigned f2tf(float f) {
    unsigned r;
    asm("cvt.rna.tf32.f32 %0, %1;" : "=r"(r) : "f"(f));
    return r;
}

__device__ __forceinline__ void mma_tf32(float (&d)[4], const unsigned (&a)[4], const unsigned (&b)[2]) {
    asm("mma.sync.aligned.m16n8k8.row.col.f32.tf32.tf32.f32 "
        "{%0,%1,%2,%3}, {%4,%5,%6,%7}, {%8,%9}, {%0,%1,%2,%3};"
        : "+f"(d[0]), "+f"(d[1]), "+f"(d[2]), "+f"(d[3])
        : "r"(a[0]), "r"(a[1]), "r"(a[2]), "r"(a[3]), "r"(b[0]), "r"(b[1]));
}

// ---------------- kernel 1: projections q/kl/kr = phi(A @ W), tf32 mma ----------------
__global__ __launch_bounds__(256) void proj_mma_kernel(
    const float* __restrict__ x, const float* __restrict__ wq,
    const float* __restrict__ wkl, const float* __restrict__ wkr) {
    int zi = blockIdx.z;
    int sample = zi / 3, p = zi % 3;
    const float* A;
    const float* Wm;
    float* C;
    if (p == 0)      { A = x + (size_t)(sample + 1) * INC * FD; Wm = wq;  C = g_q  + (size_t)sample * INC * DK; }
    else if (p == 1) { A = x + (size_t)(sample + 0) * INC * FD; Wm = wkl; C = g_kl + (size_t)sample * INC * DK; }
    else             { A = x + (size_t)(sample + 2) * INC * FD; Wm = wkr; C = g_kr + (size_t)sample * INC * DK; }

    __shared__ unsigned Asu[16 * 72];   // [k][m]
    __shared__ unsigned Bsu[16 * 136];  // [k][n]

    int m0 = blockIdx.x * 64;
    int tid = threadIdx.x;
    int warp = tid >> 5, lane = tid & 31;
    int wm = warp & 3;        // m16 tile
    int wn = warp >> 2;       // n 64-col half
    int qr = lane >> 2, qc = lane & 3;

    float acc[8][4] = {};

    for (int k0 = 0; k0 < FD; k0 += 16) {
#pragma unroll
        for (int it = 0; it < 4; it++) {
            int idx = it * 256 + tid;
            int m = idx >> 4, kk = idx & 15;
            Asu[kk * 72 + m] = f2tf(A[(size_t)(m0 + m) * FD + k0 + kk]);
        }
#pragma unroll
        for (int it = 0; it < 2; it++) {
            int e = it * 256 + tid;
            int kk = e >> 5, c4 = (e & 31) * 4;
            float4 v = *(const float4*)&Wm[(size_t)(k0 + kk) * DK + c4];
            unsigned* bp = &Bsu[kk * 136 + c4];
            bp[0] = f2tf(v.x); bp[1] = f2tf(v.y); bp[2] = f2tf(v.z); bp[3] = f2tf(v.w);
        }
        __syncthreads();
#pragma unroll
        for (int k8 = 0; k8 < 2; k8++) {
            int ra0 = (k8 * 8 + qc) * 72;
            int ra1 = (k8 * 8 + qc + 4) * 72;
            unsigned a[4];
            int mb = wm * 16 + qr;
            a[0] = Asu[ra0 + mb];
            a[1] = Asu[ra0 + mb + 8];
            a[2] = Asu[ra1 + mb];
            a[3] = Asu[ra1 + mb + 8];
            int rb0 = (k8 * 8 + qc) * 136 + wn * 64 + qr;
            int rb1 = (k8 * 8 + qc + 4) * 136 + wn * 64 + qr;
#pragma unroll
            for (int j = 0; j < 8; j++) {
                unsigned b[2] = {Bsu[rb0 + j * 8], Bsu[rb1 + j * 8]};
                mma_tf32(acc[j], a, b);
            }
        }
        __syncthreads();
    }
    // epilogue: phi = elu + 1
#pragma unroll
    for (int half = 0; half < 2; half++) {
        int m = m0 + wm * 16 + half * 8 + qr;
#pragma unroll
        for (int j = 0; j < 8; j++) {
#pragma unroll
            for (int cc = 0; cc < 2; cc++) {
                int ncol = wn * 64 + j * 8 + qc * 2 + cc;
                float v = acc[j][half * 2 + cc];
                C[(size_t)m * DK + ncol] = (v > 0.f) ? (v + 1.f) : expf(v);
            }
        }
    }
}

// ---------------- kernel 2: column sums + z = q @ ksum + 1e-6 ----------------
__global__ void sumz_kernel() {
    int sample = blockIdx.x;
    int side = blockIdx.y;  // 0=l, 1=r
    const float* K = (side == 0 ? g_kl : g_kr) + (size_t)sample * INC * DK;
    const float* Q = g_q + (size_t)sample * INC * DK;
    __shared__ float ssum[DK];
    int t = threadIdx.x;  // 128 threads
    float s = 0.f;
    for (int n = 0; n < INC; n++) s += K[n * DK + t];
    ssum[t] = s;
    __syncthreads();
    float* Z = g_z + (size_t)(side * NS + sample) * INC;
    for (int rr = 0; rr < 4; rr++) {
        int row = rr * 128 + t;
        float d = 0.f;
        for (int k = 0; k < DK; k++) d += Q[row * DK + k] * ssum[k];
        Z[row] = d + 1e-6f;
    }
}

// ---------------- kernel 3: kv[k][d] = sum_n K[n][k] * V[n][d], tf32 mma ----------------
__global__ __launch_bounds__(256) void kv_mma_kernel(const float* __restrict__ x) {
    int zi = blockIdx.z;
    int sample = zi >> 1, side = zi & 1;
    const float* K = (side == 0 ? g_kl : g_kr) + (size_t)sample * INC * DK;
    const float* V = x + (size_t)(sample + (side == 0 ? 0 : 2)) * INC * FD;
    float* C = (side == 0 ? g_kvl : g_kvr) + (size_t)sample * DK * FD;

    __shared__ unsigned Asu[16 * 72];   // [nn][k]
    __shared__ unsigned Bsu[16 * 264];  // [nn][d]

    int m0 = blockIdx.x * 64;   // k dim
    int n0 = blockIdx.y * 256;  // d dim
    int tid = threadIdx.x;
    int warp = tid >> 5, lane = tid & 31;
    int wm = warp & 1, wn = warp >> 1;
    int qr = lane >> 2, qc = lane & 3;

    float acc[2][8][4] = {};

    for (int c0 = 0; c0 < INC; c0 += 16) {
#pragma unroll
        for (int it = 0; it < 4; it++) {
            int idx = it * 256 + tid;
            int nn = idx >> 6, k = idx & 63;
            Asu[nn * 72 + k] = f2tf(K[(size_t)(c0 + nn) * DK + m0 + k]);
        }
#pragma unroll
        for (int it = 0; it < 4; it++) {
            int e = it * 256 + tid;
            int nn = e >> 6, c4 = (e & 63) * 4;
            float4 v = *(const float4*)&V[(size_t)(c0 + nn) * FD + n0 + c4];
            unsigned* bp = &Bsu[nn * 264 + c4];
            bp[0] = f2tf(v.x); bp[1] = f2tf(v.y); bp[2] = f2tf(v.z); bp[3] = f2tf(v.w);
        }
        __syncthreads();
#pragma unroll
        for (int k8 = 0; k8 < 2; k8++) {
            unsigned a[2][4];
            int ra0 = (k8 * 8 + qc) * 72;
            int ra1 = (k8 * 8 + qc + 4) * 72;
#pragma unroll
            for (int mi = 0; mi < 2; mi++) {
                int mb = wm * 32 + mi * 16 + qr;
                a[mi][0] = Asu[ra0 + mb];
                a[mi][1] = Asu[ra0 + mb + 8];
                a[mi][2] = Asu[ra1 + mb];
                a[mi][3] = Asu[ra1 + mb + 8];
            }
            int rb0 = (k8 * 8 + qc) * 264 + wn * 64 + qr;
            int rb1 = (k8 * 8 + qc + 4) * 264 + wn * 64 + qr;
#pragma unroll
            for (int j = 0; j < 8; j++) {
                unsigned b[2] = {Bsu[rb0 + j * 8], Bsu[rb1 + j * 8]};
                mma_tf32(acc[0][j], a[0], b);
                mma_tf32(acc[1][j], a[1], b);
            }
        }
        __syncthreads();
    }
#pragma unroll
    for (int mi = 0; mi < 2; mi++) {
#pragma unroll
        for (int half = 0; half < 2; half++) {
            int m = m0 + wm * 32 + mi * 16 + half * 8 + qr;
#pragma unroll
            for (int j = 0; j < 8; j++) {
#pragma unroll
                for (int cc = 0; cc < 2; cc++) {
                    int d = n0 + wn * 64 + j * 8 + qc * 2 + cc;
                    C[(size_t)m * FD + d] = acc[mi][j][half * 2 + cc];
                }
            }
        }
    }
}

// ------ kernel 4: out = x + (q@kvl)/zl + (q@kvr)/zr, dual-B tf32 mma ------
__global__ __launch_bounds__(256) void attnout_mma_kernel(const float* __restrict__ x) {
    int sample = blockIdx.z;
    const float* Q = g_q + (size_t)sample * INC * DK;
    const float* KVL = g_kvl + (size_t)sample * DK * FD;
    const float* KVR = g_kvr + (size_t)sample * DK * FD;
    const float* Zl = g_z + (size_t)sample * INC;
    const float* Zr = g_z + (size_t)(NS + sample) * INC;
    const float* X = x + (size_t)(sample + 1) * INC * FD;
    float* C = g_mid + (size_t)sample * INC * FD;

    __shared__ unsigned Asu[16 * 72];
    __shared__ unsigned Blu[16 * 264];
    __shared__ unsigned Bru[16 * 264];

    int m0 = blockIdx.x * 64;
    int n0 = blockIdx.y * 256;
    int tid = threadIdx.x;
    int warp = tid >> 5, lane = tid & 31;
    int wm = warp & 1, wn = warp >> 1;
    int qr = lane >> 2, qc = lane & 3;

    float accl[2][8][4] = {}, accr[2][8][4] = {};

    for (int k0 = 0; k0 < DK; k0 += 16) {
#pragma unroll
        for (int it = 0; it < 4; it++) {
            int idx = it * 256 + tid;
            int m = idx >> 4, kk = idx & 15;
            Asu[kk * 72 + m] = f2tf(Q[(size_t)(m0 + m) * DK + k0 + kk]);
        }
#pragma unroll
        for (int it = 0; it < 4; it++) {
            int e = it * 256 + tid;
            int kk = e >> 6, c4 = (e & 63) * 4;
            float4 vl = *(const float4*)&KVL[(size_t)(k0 + kk) * FD + n0 + c4];
            float4 vr = *(const float4*)&KVR[(size_t)(k0 + kk) * FD + n0 + c4];
            unsigned* bl = &Blu[kk * 264 + c4];
            unsigned* br = &Bru[kk * 264 + c4];
            bl[0] = f2tf(vl.x); bl[1] = f2tf(vl.y); bl[2] = f2tf(vl.z); bl[3] = f2tf(vl.w);
            br[0] = f2tf(vr.x); br[1] = f2tf(vr.y); br[2] = f2tf(vr.z); br[3] = f2tf(vr.w);
        }
        __syncthreads();
#pragma unroll
        for (int k8 = 0; k8 < 2; k8++) {
            unsigned a[2][4];
            int ra0 = (k8 * 8 + qc) * 72;
            int ra1 = (k8 * 8 + qc + 4) * 72;
#pragma unroll
            for (int mi = 0; mi < 2; mi++) {
                int mb = wm * 32 + mi * 16 + qr;
                a[mi][0] = Asu[ra0 + mb];
                a[mi][1] = Asu[ra0 + mb + 8];
                a[mi][2] = Asu[ra1 + mb];
                a[mi][3] = Asu[ra1 + mb + 8];
            }
            int rb0 = (k8 * 8 + qc) * 264 + wn * 64 + qr;
            int rb1 = (k8 * 8 + qc + 4) * 264 + wn * 64 + qr;
#pragma unroll
            for (int j = 0; j < 8; j++) {
                unsigned bl[2] = {Blu[rb0 + j * 8], Blu[rb1 + j * 8]};
                unsigned br[2] = {Bru[rb0 + j * 8], Bru[rb1 + j * 8]};
                mma_tf32(accl[0][j], a[0], bl);
                mma_tf32(accl[1][j], a[1], bl);
                mma_tf32(accr[0][j], a[0], br);
                mma_tf32(accr[1][j], a[1], br);
            }
        }
        __syncthreads();
    }
#pragma unroll
    for (int mi = 0; mi < 2; mi++) {
#pragma unroll
        for (int half = 0; half < 2; half++) {
            int m = m0 + wm * 32 + mi * 16 + half * 8 + qr;
            float zl = Zl[m], zr = Zr[m];
#pragma unroll
            for (int j = 0; j < 8; j++) {
#pragma unroll
                for (int cc = 0; cc < 2; cc++) {
                    int d = n0 + wn * 64 + j * 8 + qc * 2 + cc;
                    C[(size_t)m * FD + d] = X[(size_t)m * FD + d]
                        + accl[mi][j][half * 2 + cc] / zl
                        + accr[mi][j][half * 2 + cc] / zr;
                }
            }
        }
    }
}

// ------ kernel 5: ConvTranspose 2x2 s2 via tf32 mma, double-buffered pipeline ------
__global__ __launch_bounds__(256) void convt_mma_kernel(
    const float* __restrict__ x, const float* __restrict__ upw,
    const float* __restrict__ upb, const float* __restrict__ s) {
    int n = blockIdx.z;
    const float* src = (n == 0) ? x
                     : (n == BB - 1) ? (x + (size_t)(BB - 1) * INC * FD)
                     : (g_mid + (size_t)(n - 1) * INC * FD);
    int m0 = blockIdx.x * 64;   // wcol
    int n0 = blockIdx.y * 256;  // ij

    __shared__ unsigned Asu[2][16 * 72];
    __shared__ unsigned Bsu[2][16 * 264];

    int tid = threadIdx.x;
    int warp = tid >> 5, lane = tid & 31;
    int wm = warp & 1;
    int wn = warp >> 1;
    int qr = lane >> 2;
    int qc = lane & 3;

    float acc[2][8][4] = {};

    float a_r[4];
    float4 b_r[4];

    // prefetch chunk 0
#pragma unroll
    for (int it = 0; it < 4; it++) {
        int e = it * 256 + tid;
        int cc = e >> 6, m = e & 63;
        a_r[it] = upw[(size_t)cc * 1024 + m0 + m];
        int c4 = (e & 63) * 4;
        b_r[it] = *(const float4*)&src[(size_t)cc * FD + n0 + c4];
    }
    // store chunk 0 to buffer 0
#pragma unroll
    for (int it = 0; it < 4; it++) {
        int e = it * 256 + tid;
        int cc = e >> 6, m = e & 63;
        Asu[0][cc * 72 + m] = f2tf(a_r[it]);
        int c4 = (e & 63) * 4;
        unsigned* bp = &Bsu[0][cc * 264 + c4];
        bp[0] = f2tf(b_r[it].x); bp[1] = f2tf(b_r[it].y);
        bp[2] = f2tf(b_r[it].z); bp[3] = f2tf(b_r[it].w);
    }

    int pi = 0;
    for (int c = 0; c < 32; c++) {
        __syncthreads();
        bool more = (c < 31);
        if (more) {
            int c0 = (c + 1) * 16;
#pragma unroll
            for (int it = 0; it < 4; it++) {
                int e = it * 256 + tid;
                int cc = e >> 6, m = e & 63;
                a_r[it] = upw[(size_t)(c0 + cc) * 1024 + m0 + m];
                int c4 = (e & 63) * 4;
                b_r[it] = *(const float4*)&src[(size_t)(c0 + cc) * FD + n0 + c4];
            }
        }
        const unsigned* As = Asu[pi];
        const unsigned* Bs = Bsu[pi];
#pragma unroll
        for (int k8 = 0; k8 < 2; k8++) {
            unsigned a[2][4];
            int ra0 = (k8 * 8 + qc) * 72;
            int ra1 = (k8 * 8 + qc + 4) * 72;
#pragma unroll
            for (int mi = 0; mi < 2; mi++) {
                int ocb = wm * 32 + mi * 16 + qr;
                a[mi][0] = As[ra0 + ocb];
                a[mi][1] = As[ra0 + ocb + 8];
                a[mi][2] = As[ra1 + ocb];
                a[mi][3] = As[ra1 + ocb + 8];
            }
            int rb0 = (k8 * 8 + qc) * 264 + wn * 64 + qr;
            int rb1 = (k8 * 8 + qc + 4) * 264 + wn * 64 + qr;
#pragma unroll
            for (int j = 0; j < 8; j++) {
                unsigned b[2] = {Bs[rb0 + j * 8], Bs[rb1 + j * 8]};
                mma_tf32(acc[0][j], a[0], b);
                mma_tf32(acc[1][j], a[1], b);
            }
        }
        if (more) {
            unsigned* Ad = Asu[pi ^ 1];
            unsigned* Bd = Bsu[pi ^ 1];
#pragma unroll
            for (int it = 0; it < 4; it++) {
                int e = it * 256 + tid;
                int cc = e >> 6, m = e & 63;
                Ad[cc * 72 + m] = f2tf(a_r[it]);
                int c4 = (e & 63) * 4;
                unsigned* bp = &Bd[cc * 264 + c4];
                bp[0] = f2tf(b_r[it].x); bp[1] = f2tf(b_r[it].y);
                bp[2] = f2tf(b_r[it].z); bp[3] = f2tf(b_r[it].w);
            }
        }
        pi ^= 1;
    }
    // epilogue: bias + skip + relu + sigmoid, scatter to g_gate
#pragma unroll
    for (int mi = 0; mi < 2; mi++) {
#pragma unroll
        for (int half = 0; half < 2; half++) {
            int row = m0 + wm * 32 + mi * 16 + half * 8 + qr;
            int o = row >> 2, ab = row & 3, av = ab >> 1, bq = ab & 1;
            float bias = upb[o];
#pragma unroll
            for (int j = 0; j < 8; j++) {
#pragma unroll
                for (int cc = 0; cc < 2; cc++) {
                    int col = n0 + wn * 64 + j * 8 + qc * 2 + cc;
                    int isp = col >> 5, jsp = col & 31;
                    int oy = 2 * isp + av, ox = 2 * jsp + bq;
                    size_t gi = (((size_t)n * OUTC + o) * OH + oy) * OW + ox;
                    float v = acc[mi][j][half * 2 + cc] + bias + s[gi];
                    v = v > 0.f ? v : 0.f;
                    g_gate[gi] = 1.f / (1.f + expf(-v));
                }
            }
        }
    }
}

// ---------------- kernel 6: conv3x3 via tf32 mma, double-buffered pipeline ----------------
// Dynamic smem: 2 input buffers (8 planes x 744) + 2 weight buffers (64 x 76) + rs/rq.
#define PS 744
#define INW (8 * PS)      // 5952 words per input buffer
#define WW_ 4864          // 64*76 words per weight buffer
__global__ __launch_bounds__(256) void conv_mma_kernel(
    const float* __restrict__ sskip, const float* __restrict__ cw,
    const float* __restrict__ cb) {
    extern __shared__ unsigned dyns[];
    unsigned* inb = dyns;                   // 2 * INW
    unsigned* wb = dyns + 2 * INW;          // 2 * WW_
    float* rs = (float*)(dyns + 2 * INW + 2 * WW_);
    float* rq = rs + 64;

    int n = blockIdx.z;
    int oc0 = blockIdx.y * 64;
    int y0 = blockIdx.x * 8;

    int tid = threadIdx.x;
    int warp = tid >> 5, lane = tid & 31;
    int wn = warp;
    int qr = lane >> 2;
    int qc = lane & 3;

    // halo columns zero for BOTH buffers
    for (int e = tid; e < 320; e += 256) {
        int bsel = e >= 160;
        int r2 = e - bsel * 160;
        int r = r2 >> 1;
        int icc = r / 10, yy = r - icc * 10;
        inb[bsel * INW + icc * PS + yy * 72 + ((r2 & 1) ? 65 : 0)] = 0u;
    }
    if (tid < 64) { rs[tid] = 0.f; rq[tid] = 0.f; }

    float acc[4][8][4] = {};

    int seg = (tid & 15) * 4;
    int rbase = tid >> 4;

    float4 vin[5];
    float4 vw[5];

    // ---- prefetch chunk 0 ----
#pragma unroll
    for (int i = 0; i < 5; i++) {
        int r = rbase + 16 * i;
        int icc = r / 10, yy = r - icc * 10;
        int gy = y0 + yy - 1;
        int ic = icc;  // ic0 = 0
        if ((unsigned)gy < (unsigned)OH) {
            const float* srcp = (ic < OUTC)
                ? &g_gate[(((size_t)n * OUTC + ic) * OH + gy) * OW + seg]
                : &sskip[(((size_t)n * OUTC + (ic - OUTC)) * OH + gy) * OW + seg];
            vin[i] = *(const float4*)srcp;
        } else vin[i] = make_float4(0.f, 0.f, 0.f, 0.f);
    }
#pragma unroll
    for (int i = 0; i < 5; i++) {
        int e = tid + 256 * i;
        if (e < 1152) {
            int oc = e / 18, f = e - oc * 18;
            vw[i] = *(const float4*)&cw[(size_t)(oc0 + oc) * (2 * OUTC * 9) + f * 4];
        }
    }
    // ---- store chunk 0 to buffer 0 ----
#pragma unroll
    for (int i = 0; i < 5; i++) {
        int r = rbase + 16 * i;
        int icc = r / 10, yy = r - icc * 10;
        unsigned* dst = &inb[icc * PS + yy * 72 + 1 + seg];
        dst[0] = f2tf(vin[i].x); dst[1] = f2tf(vin[i].y);
        dst[2] = f2tf(vin[i].z); dst[3] = f2tf(vin[i].w);
    }
#pragma unroll
    for (int i = 0; i < 5; i++) {
        int e = tid + 256 * i;
        if (e < 1152) {
            int oc = e / 18, f = e - oc * 18;
            unsigned* wp = &wb[oc * 76 + f * 4];
            wp[0] = f2tf(vw[i].x); wp[1] = f2tf(vw[i].y);
            wp[2] = f2tf(vw[i].z); wp[3] = f2tf(vw[i].w);
        }
    }

    int pi = 0;
    for (int c = 0; c < 64; c++) {
        __syncthreads();
        bool more = (c < 63);
        if (more) {
            int ic0 = (c + 1) * 8;
#pragma unroll
            for (int i = 0; i < 5; i++) {
                int r = rbase + 16 * i;
                int icc = r / 10, yy = r - icc * 10;
                int gy = y0 + yy - 1;
                int ic = ic0 + icc;
                if ((unsigned)gy < (unsigned)OH) {
                    const float* srcp = (ic < OUTC)
                        ? &g_gate[(((size_t)n * OUTC + ic) * OH + gy) * OW + seg]
                        : &sskip[(((size_t)n * OUTC + (ic - OUTC)) * OH + gy) * OW + seg];
                    vin[i] = *(const float4*)srcp;
                } else vin[i] = make_float4(0.f, 0.f, 0.f, 0.f);
            }
#pragma unroll
            for (int i = 0; i < 5; i++) {
                int e = tid + 256 * i;
                if (e < 1152) {
                    int oc = e / 18, f = e - oc * 18;
                    vw[i] = *(const float4*)&cw[(size_t)(oc0 + oc) * (2 * OUTC * 9) + ic0 * 9 + f * 4];
                }
            }
        }
        const unsigned* in_s = inb + (pi ? INW : 0);
        const unsigned* w_s = wb + (pi ? WW_ : 0);
#pragma unroll
        for (int ky = 0; ky < 3; ky++) {
            int rowoff = (wn + ky) * 72;
#pragma unroll
            for (int kx = 0; kx < 3; kx++) {
                int pos = ky * 3 + kx;
                unsigned a[4][4];
#pragma unroll
                for (int mi = 0; mi < 4; mi++) {
                    int ocb = mi * 16 + qr;
                    a[mi][0] = w_s[ocb * 76 + qc * 9 + pos];
                    a[mi][1] = w_s[(ocb + 8) * 76 + qc * 9 + pos];
                    a[mi][2] = w_s[ocb * 76 + (qc + 4) * 9 + pos];
                    a[mi][3] = w_s[(ocb + 8) * 76 + (qc + 4) * 9 + pos];
                }
#pragma unroll
                for (int j = 0; j < 8; j++) {
                    int col = j * 8 + qr + kx;
                    unsigned b[2] = {in_s[qc * PS + rowoff + col],
                                     in_s[(qc + 4) * PS + rowoff + col]};
                    mma_tf32(acc[0][j], a[0], b);
                    mma_tf32(acc[1][j], a[1], b);
                    mma_tf32(acc[2][j], a[2], b);
                    mma_tf32(acc[3][j], a[3], b);
                }
            }
        }
        if (more) {
            unsigned* ind = inb + (pi ? 0 : INW);
            unsigned* wd = wb + (pi ? 0 : WW_);
#pragma unroll
            for (int i = 0; i < 5; i++) {
                int r = rbase + 16 * i;
                int icc = r / 10, yy = r - icc * 10;
                unsigned* dst = &ind[icc * PS + yy * 72 + 1 + seg];
                dst[0] = f2tf(vin[i].x); dst[1] = f2tf(vin[i].y);
                dst[2] = f2tf(vin[i].z); dst[3] = f2tf(vin[i].w);
            }
#pragma unroll
            for (int i = 0; i < 5; i++) {
                int e = tid + 256 * i;
                if (e < 1152) {
                    int oc = e / 18, f = e - oc * 18;
                    unsigned* wp = &wd[oc * 76 + f * 4];
                    wp[0] = f2tf(vw[i].x); wp[1] = f2tf(vw[i].y);
                    wp[2] = f2tf(vw[i].z); wp[3] = f2tf(vw[i].w);
                }
            }
        }
        pi ^= 1;
    }

    // epilogue: bias, store y, BN partial sums
    int row = y0 + wn;
#pragma unroll
    for (int mi = 0; mi < 4; mi++) {
#pragma unroll
        for (int half = 0; half < 2; half++) {
            int ocl = mi * 16 + half * 8 + qr;
            int oc = oc0 + ocl;
            float bias = cb[oc];
            float s0 = 0.f, s1 = 0.f;
#pragma unroll
            for (int j = 0; j < 8; j++) {
#pragma unroll
                for (int cc = 0; cc < 2; cc++) {
                    float v = acc[mi][j][half * 2 + cc] + bias;
                    int col = j * 8 + qc * 2 + cc;
                    g_y[(((size_t)n * OUTC + oc) * OH + row) * OW + col] = v;
                    s0 += v;
                    s1 += v * v;
                }
            }
            s0 += __shfl_xor_sync(0xffffffffu, s0, 1);
            s0 += __shfl_xor_sync(0xffffffffu, s0, 2);
            s1 += __shfl_xor_sync(0xffffffffu, s1, 1);
            s1 += __shfl_xor_sync(0xffffffffu, s1, 2);
            if (qc == 0) {
                atomicAdd(&rs[ocl], s0);
                atomicAdd(&rq[ocl], s1);
            }
        }
    }
    __syncthreads();
    if (tid < 64) {
        atomicAdd(&g_bnsum[oc0 + tid], rs[tid]);
        atomicAdd(&g_bnsq[oc0 + tid], rq[tid]);
    }
}

// ---------------- small kernels ----------------
__global__ void zero_kernel() {
    int t = threadIdx.x;
    g_bnsum[t] = 0.f;
    g_bnsq[t] = 0.f;
}

__global__ void bnstats_kernel(const float* __restrict__ bn_g, const float* __restrict__ bn_b) {
    int c = threadIdx.x;
    float cnt = (float)(BB * OH * OW);
    float mean = g_bnsum[c] / cnt;
    float var = g_bnsq[c] / cnt - mean * mean;
    float inv = rsqrtf(var + 1e-5f);
    float sc = bn_g[c] * inv;
    g_bnscale[c] = sc;
    g_bnshift[c] = bn_b[c] - mean * sc;
}

__global__ void bnorm_kernel(float* __restrict__ out) {
    int i4 = blockIdx.x * blockDim.x + threadIdx.x;
    const int total4 = BB * OUTC * OH * OW / 4;
    if (i4 >= total4) return;
    int base = i4 * 4;
    int oc = (base >> 12) & (OUTC - 1);  // OH*OW = 4096
    float sc = g_bnscale[oc], sh = g_bnshift[oc];
    float4 v = *(const float4*)&g_y[base];
    float4 r;
    r.x = fmaxf(v.x * sc + sh, 0.f);
    r.y = fmaxf(v.y * sc + sh, 0.f);
    r.z = fmaxf(v.z * sc + sh, 0.f);
    r.w = fmaxf(v.w * sc + sh, 0.f);
    *(float4*)&out[base] = r;
}

// ---------------- launcher ----------------
extern "C" void kernel_launch(void* const* d_in, const int* in_sizes, int n_in,
                              void* d_out, int out_size) {
    const float* x    = (const float*)d_in[0];
    const float* s    = (const float*)d_in[1];
    const float* up_w = (const float*)d_in[2];
    const float* up_b = (const float*)d_in[3];
    const float* wq   = (const float*)d_in[4];
    const float* wkl  = (const float*)d_in[5];
    const float* wkr  = (const float*)d_in[6];
    const float* c1_w = (const float*)d_in[7];
    const float* c1_b = (const float*)d_in[8];
    const float* bn_g = (const float*)d_in[9];
    const float* bn_b = (const float*)d_in[10];
    float* out = (float*)d_out;

    const int conv_smem = (2 * INW + 2 * WW_) * 4 + 128 * 4;  // 87040 bytes
    cudaFuncSetAttribute(conv_mma_kernel,
                         cudaFuncAttributeMaxDynamicSharedMemorySize, conv_smem);

    proj_mma_kernel<<<dim3(8, 1, NS * 3), 256>>>(x, wq, wkl, wkr);
    sumz_kernel<<<dim3(NS, 2), 128>>>();
    kv_mma_kernel<<<dim3(2, 4, NS * 2), 256>>>(x);
    attnout_mma_kernel<<<dim3(8, 4, NS), 256>>>(x);
    convt_mma_kernel<<<dim3(16, 4, BB), 256>>>(x, up_w, up_b, s);
    zero_kernel<<<1, OUTC>>>();
    conv_mma_kernel<<<dim3(8, 4, BB), 256, conv_smem>>>(s, c1_w, c1_b);
    bnstats_kernel<<<1, OUTC>>>(bn_g, bn_b);
    int total4 = BB * OUTC * OH * OW / 4;
    bnorm_kernel<<<(total4 + 255) / 256, 256>>>(out);
}

// round 7
// speedup vs baseline: 3.6530x; 1.0383x over previous
#include <cuda_runtime.h>
#include <math.h>

#define BB 16
#define INC 512
#define OUTC 256
#define HH 32
#define WW 32
#define FD 1024
#define DK 128
#define NS 14          // interior samples (B-2)
#define OH 64
#define OW 64

// ---------------- scratch (static device memory; no allocation) ----------------
__device__ float g_mid[NS * INC * FD];        // rotatory outputs for batches 1..14
__device__ float g_q[NS * INC * DK];
__device__ float g_kl[NS * INC * DK];
__device__ float g_kr[NS * INC * DK];
__device__ float g_kvl[NS * DK * FD];
__device__ float g_kvr[NS * DK * FD];
__device__ float g_z[2 * NS * INC];           // [side][sample][row]
__device__ float g_gate[BB * OUTC * OH * OW]; // gated branch (first 256 channels of cat)
__device__ float g_y[BB * OUTC * OH * OW];    // conv3x3 pre-BN output
__device__ float g_bnsum[OUTC];
__device__ float g_bnsq[OUTC];
__device__ float g_bnscale[OUTC];
__device__ float g_bnshift[OUTC];

// ---------------- tf32 mma helpers ----------------
__device__ __forceinline__ unsigned f2tf(float f) {
    unsigned r;
    asm("cvt.rna.tf32.f32 %0, %1;" : "=r"(r) : "f"(f));
    return r;
}

__device__ __forceinline__ void mma_tf32(float (&d)[4], const unsigned (&a)[4], const unsigned (&b)[2]) {
    asm("mma.sync.aligned.m16n8k8.row.col.f32.tf32.tf32.f32 "
        "{%0,%1,%2,%3}, {%4,%5,%6,%7}, {%8,%9}, {%0,%1,%2,%3};"
        : "+f"(d[0]), "+f"(d[1]), "+f"(d[2]), "+f"(d[3])
        : "r"(a[0]), "r"(a[1]), "r"(a[2]), "r"(a[3]), "r"(b[0]), "r"(b[1]));
}

// ---------------- kernel 1: projections q/kl/kr = phi(A @ W), tf32 mma, pipelined ----------------
__global__ __launch_bounds__(256) void proj_mma_kernel(
    const float* __restrict__ x, const float* __restrict__ wq,
    const float* __restrict__ wkl, const float* __restrict__ wkr) {
    int zi = blockIdx.z;
    int sample = zi / 3, p = zi % 3;
    const float* A;
    const float* Wm;
    float* C;
    if (p == 0)      { A = x + (size_t)(sample + 1) * INC * FD; Wm = wq;  C = g_q  + (size_t)sample * INC * DK; }
    else if (p == 1) { A = x + (size_t)(sample + 0) * INC * FD; Wm = wkl; C = g_kl + (size_t)sample * INC * DK; }
    else             { A = x + (size_t)(sample + 2) * INC * FD; Wm = wkr; C = g_kr + (size_t)sample * INC * DK; }

    __shared__ unsigned Asu[2][16 * 72];   // [k][m]
    __shared__ unsigned Bsu[2][16 * 136];  // [k][n]

    int m0 = blockIdx.x * 64;
    int tid = threadIdx.x;
    int warp = tid >> 5, lane = tid & 31;
    int wm = warp & 3;        // m16 tile
    int wn = warp >> 2;       // n 64-col half
    int qr = lane >> 2, qc = lane & 3;

    float acc[8][4] = {};
    float a_r[4];
    float4 b_r[2];

    // prefetch + store chunk 0
#pragma unroll
    for (int it = 0; it < 4; it++) {
        int idx = it * 256 + tid;
        int m = idx >> 4, kk = idx & 15;
        a_r[it] = A[(size_t)(m0 + m) * FD + kk];
    }
#pragma unroll
    for (int it = 0; it < 2; it++) {
        int e = it * 256 + tid;
        int kk = e >> 5, c4 = (e & 31) * 4;
        b_r[it] = *(const float4*)&Wm[(size_t)kk * DK + c4];
    }
#pragma unroll
    for (int it = 0; it < 4; it++) {
        int idx = it * 256 + tid;
        int m = idx >> 4, kk = idx & 15;
        Asu[0][kk * 72 + m] = f2tf(a_r[it]);
    }
#pragma unroll
    for (int it = 0; it < 2; it++) {
        int e = it * 256 + tid;
        int kk = e >> 5, c4 = (e & 31) * 4;
        unsigned* bp = &Bsu[0][kk * 136 + c4];
        bp[0] = f2tf(b_r[it].x); bp[1] = f2tf(b_r[it].y);
        bp[2] = f2tf(b_r[it].z); bp[3] = f2tf(b_r[it].w);
    }

    int pi = 0;
    for (int c = 0; c < 64; c++) {
        __syncthreads();
        bool more = (c < 63);
        if (more) {
            int k0 = (c + 1) * 16;
#pragma unroll
            for (int it = 0; it < 4; it++) {
                int idx = it * 256 + tid;
                int m = idx >> 4, kk = idx & 15;
                a_r[it] = A[(size_t)(m0 + m) * FD + k0 + kk];
            }
#pragma unroll
            for (int it = 0; it < 2; it++) {
                int e = it * 256 + tid;
                int kk = e >> 5, c4 = (e & 31) * 4;
                b_r[it] = *(const float4*)&Wm[(size_t)(k0 + kk) * DK + c4];
            }
        }
        const unsigned* As = Asu[pi];
        const unsigned* Bs = Bsu[pi];
#pragma unroll
        for (int k8 = 0; k8 < 2; k8++) {
            int ra0 = (k8 * 8 + qc) * 72;
            int ra1 = (k8 * 8 + qc + 4) * 72;
            unsigned a[4];
            int mb = wm * 16 + qr;
            a[0] = As[ra0 + mb];
            a[1] = As[ra0 + mb + 8];
            a[2] = As[ra1 + mb];
            a[3] = As[ra1 + mb + 8];
            int rb0 = (k8 * 8 + qc) * 136 + wn * 64 + qr;
            int rb1 = (k8 * 8 + qc + 4) * 136 + wn * 64 + qr;
#pragma unroll
            for (int j = 0; j < 8; j++) {
                unsigned b[2] = {Bs[rb0 + j * 8], Bs[rb1 + j * 8]};
                mma_tf32(acc[j], a, b);
            }
        }
        if (more) {
            unsigned* Ad = Asu[pi ^ 1];
            unsigned* Bd = Bsu[pi ^ 1];
#pragma unroll
            for (int it = 0; it < 4; it++) {
                int idx = it * 256 + tid;
                int m = idx >> 4, kk = idx & 15;
                Ad[kk * 72 + m] = f2tf(a_r[it]);
            }
#pragma unroll
            for (int it = 0; it < 2; it++) {
                int e = it * 256 + tid;
                int kk = e >> 5, c4 = (e & 31) * 4;
                unsigned* bp = &Bd[kk * 136 + c4];
                bp[0] = f2tf(b_r[it].x); bp[1] = f2tf(b_r[it].y);
                bp[2] = f2tf(b_r[it].z); bp[3] = f2tf(b_r[it].w);
            }
        }
        pi ^= 1;
    }
    // epilogue: phi = elu + 1
#pragma unroll
    for (int half = 0; half < 2; half++) {
        int m = m0 + wm * 16 + half * 8 + qr;
#pragma unroll
        for (int j = 0; j < 8; j++) {
#pragma unroll
            for (int cc = 0; cc < 2; cc++) {
                int ncol = wn * 64 + j * 8 + qc * 2 + cc;
                float v = acc[j][half * 2 + cc];
                C[(size_t)m * DK + ncol] = (v > 0.f) ? (v + 1.f) : expf(v);
            }
        }
    }
}

// ---------------- kernel 2: column sums + z = q @ ksum + 1e-6 ----------------
__global__ void sumz_kernel() {
    int sample = blockIdx.x;
    int side = blockIdx.y;  // 0=l, 1=r
    const float* K = (side == 0 ? g_kl : g_kr) + (size_t)sample * INC * DK;
    const float* Q = g_q + (size_t)sample * INC * DK;
    __shared__ float ssum[DK];
    int t = threadIdx.x;  // 128 threads
    float s = 0.f;
    for (int n = 0; n < INC; n++) s += K[n * DK + t];
    ssum[t] = s;
    __syncthreads();
    float* Z = g_z + (size_t)(side * NS + sample) * INC;
    for (int rr = 0; rr < 4; rr++) {
        int row = rr * 128 + t;
        float d = 0.f;
        for (int k = 0; k < DK; k++) d += Q[row * DK + k] * ssum[k];
        Z[row] = d + 1e-6f;
    }
}

// ---------------- kernel 3: kv[k][d] = sum_n K[n][k] * V[n][d], tf32 mma, pipelined ----------------
__global__ __launch_bounds__(256) void kv_mma_kernel(const float* __restrict__ x) {
    int zi = blockIdx.z;
    int sample = zi >> 1, side = zi & 1;
    const float* K = (side == 0 ? g_kl : g_kr) + (size_t)sample * INC * DK;
    const float* V = x + (size_t)(sample + (side == 0 ? 0 : 2)) * INC * FD;
    float* C = (side == 0 ? g_kvl : g_kvr) + (size_t)sample * DK * FD;

    __shared__ unsigned Asu[2][16 * 72];   // [nn][k]
    __shared__ unsigned Bsu[2][16 * 264];  // [nn][d]

    int m0 = blockIdx.x * 64;   // k dim
    int n0 = blockIdx.y * 256;  // d dim
    int tid = threadIdx.x;
    int warp = tid >> 5, lane = tid & 31;
    int wm = warp & 1, wn = warp >> 1;
    int qr = lane >> 2, qc = lane & 3;

    float acc[2][8][4] = {};
    float a_r[4];
    float4 b_r[4];

    // prefetch + store chunk 0
#pragma unroll
    for (int it = 0; it < 4; it++) {
        int idx = it * 256 + tid;
        int nn = idx >> 6, k = idx & 63;
        a_r[it] = K[(size_t)nn * DK + m0 + k];
    }
#pragma unroll
    for (int it = 0; it < 4; it++) {
        int e = it * 256 + tid;
        int nn = e >> 6, c4 = (e & 63) * 4;
        b_r[it] = *(const float4*)&V[(size_t)nn * FD + n0 + c4];
    }
#pragma unroll
    for (int it = 0; it < 4; it++) {
        int idx = it * 256 + tid;
        int nn = idx >> 6, k = idx & 63;
        Asu[0][nn * 72 + k] = f2tf(a_r[it]);
    }
#pragma unroll
    for (int it = 0; it < 4; it++) {
        int e = it * 256 + tid;
        int nn = e >> 6, c4 = (e & 63) * 4;
        unsigned* bp = &Bsu[0][nn * 264 + c4];
        bp[0] = f2tf(b_r[it].x); bp[1] = f2tf(b_r[it].y);
        bp[2] = f2tf(b_r[it].z); bp[3] = f2tf(b_r[it].w);
    }

    int pi = 0;
    for (int c = 0; c < 32; c++) {
        __syncthreads();
        bool more = (c < 31);
        if (more) {
            int c0 = (c + 1) * 16;
#pragma unroll
            for (int it = 0; it < 4; it++) {
                int idx = it * 256 + tid;
                int nn = idx >> 6, k = idx & 63;
                a_r[it] = K[(size_t)(c0 + nn) * DK + m0 + k];
            }
#pragma unroll
            for (int it = 0; it < 4; it++) {
                int e = it * 256 + tid;
                int nn = e >> 6, c4 = (e & 63) * 4;
                b_r[it] = *(const float4*)&V[(size_t)(c0 + nn) * FD + n0 + c4];
            }
        }
        const unsigned* As = Asu[pi];
        const unsigned* Bs = Bsu[pi];
#pragma unroll
        for (int k8 = 0; k8 < 2; k8++) {
            unsigned a[2][4];
            int ra0 = (k8 * 8 + qc) * 72;
            int ra1 = (k8 * 8 + qc + 4) * 72;
#pragma unroll
            for (int mi = 0; mi < 2; mi++) {
                int mb = wm * 32 + mi * 16 + qr;
                a[mi][0] = As[ra0 + mb];
                a[mi][1] = As[ra0 + mb + 8];
                a[mi][2] = As[ra1 + mb];
                a[mi][3] = As[ra1 + mb + 8];
            }
            int rb0 = (k8 * 8 + qc) * 264 + wn * 64 + qr;
            int rb1 = (k8 * 8 + qc + 4) * 264 + wn * 64 + qr;
#pragma unroll
            for (int j = 0; j < 8; j++) {
                unsigned b[2] = {Bs[rb0 + j * 8], Bs[rb1 + j * 8]};
                mma_tf32(acc[0][j], a[0], b);
                mma_tf32(acc[1][j], a[1], b);
            }
        }
        if (more) {
            unsigned* Ad = Asu[pi ^ 1];
            unsigned* Bd = Bsu[pi ^ 1];
#pragma unroll
            for (int it = 0; it < 4; it++) {
                int idx = it * 256 + tid;
                int nn = idx >> 6, k = idx & 63;
                Ad[nn * 72 + k] = f2tf(a_r[it]);
            }
#pragma unroll
            for (int it = 0; it < 4; it++) {
                int e = it * 256 + tid;
                int nn = e >> 6, c4 = (e & 63) * 4;
                unsigned* bp = &Bd[nn * 264 + c4];
                bp[0] = f2tf(b_r[it].x); bp[1] = f2tf(b_r[it].y);
                bp[2] = f2tf(b_r[it].z); bp[3] = f2tf(b_r[it].w);
            }
        }
        pi ^= 1;
    }
#pragma unroll
    for (int mi = 0; mi < 2; mi++) {
#pragma unroll
        for (int half = 0; half < 2; half++) {
            int m = m0 + wm * 32 + mi * 16 + half * 8 + qr;
#pragma unroll
            for (int j = 0; j < 8; j++) {
#pragma unroll
                for (int cc = 0; cc < 2; cc++) {
                    int d = n0 + wn * 64 + j * 8 + qc * 2 + cc;
                    C[(size_t)m * FD + d] = acc[mi][j][half * 2 + cc];
                }
            }
        }
    }
}

// ------ kernel 4: out = x + (q@kvl)/zl + (q@kvr)/zr, dual-B tf32 mma, pipelined ------
#define AOA 1152   // 16*72
#define AOB 4224   // 16*264
__global__ __launch_bounds__(256) void attnout_mma_kernel(const float* __restrict__ x) {
    extern __shared__ unsigned dsm[];
    unsigned* AsuB = dsm;                    // 2 * AOA
    unsigned* BluB = dsm + 2 * AOA;          // 2 * AOB
    unsigned* BruB = dsm + 2 * AOA + 2 * AOB;

    int sample = blockIdx.z;
    const float* Q = g_q + (size_t)sample * INC * DK;
    const float* KVL = g_kvl + (size_t)sample * DK * FD;
    const float* KVR = g_kvr + (size_t)sample * DK * FD;
    const float* Zl = g_z + (size_t)sample * INC;
    const float* Zr = g_z + (size_t)(NS + sample) * INC;
    const float* X = x + (size_t)(sample + 1) * INC * FD;
    float* C = g_mid + (size_t)sample * INC * FD;

    int m0 = blockIdx.x * 64;
    int n0 = blockIdx.y * 256;
    int tid = threadIdx.x;
    int warp = tid >> 5, lane = tid & 31;
    int wm = warp & 1, wn = warp >> 1;
    int qr = lane >> 2, qc = lane & 3;

    float accl[2][8][4] = {}, accr[2][8][4] = {};
    float a_r[4];
    float4 bl_r[4], br_r[4];

    // prefetch + store chunk 0
#pragma unroll
    for (int it = 0; it < 4; it++) {
        int idx = it * 256 + tid;
        int m = idx >> 4, kk = idx & 15;
        a_r[it] = Q[(size_t)(m0 + m) * DK + kk];
    }
#pragma unroll
    for (int it = 0; it < 4; it++) {
        int e = it * 256 + tid;
        int kk = e >> 6, c4 = (e & 63) * 4;
        bl_r[it] = *(const float4*)&KVL[(size_t)kk * FD + n0 + c4];
        br_r[it] = *(const float4*)&KVR[(size_t)kk * FD + n0 + c4];
    }
#pragma unroll
    for (int it = 0; it < 4; it++) {
        int idx = it * 256 + tid;
        int m = idx >> 4, kk = idx & 15;
        AsuB[kk * 72 + m] = f2tf(a_r[it]);
    }
#pragma unroll
    for (int it = 0; it < 4; it++) {
        int e = it * 256 + tid;
        int kk = e >> 6, c4 = (e & 63) * 4;
        unsigned* bl = &BluB[kk * 264 + c4];
        unsigned* br = &BruB[kk * 264 + c4];
        bl[0] = f2tf(bl_r[it].x); bl[1] = f2tf(bl_r[it].y);
        bl[2] = f2tf(bl_r[it].z); bl[3] = f2tf(bl_r[it].w);
        br[0] = f2tf(br_r[it].x); br[1] = f2tf(br_r[it].y);
        br[2] = f2tf(br_r[it].z); br[3] = f2tf(br_r[it].w);
    }

    int pi = 0;
    for (int c = 0; c < 8; c++) {
        __syncthreads();
        bool more = (c < 7);
        if (more) {
            int k0 = (c + 1) * 16;
#pragma unroll
            for (int it = 0; it < 4; it++) {
                int idx = it * 256 + tid;
                int m = idx >> 4, kk = idx & 15;
                a_r[it] = Q[(size_t)(m0 + m) * DK + k0 + kk];
            }
#pragma unroll
            for (int it = 0; it < 4; it++) {
                int e = it * 256 + tid;
                int kk = e >> 6, c4 = (e & 63) * 4;
                bl_r[it] = *(const float4*)&KVL[(size_t)(k0 + kk) * FD + n0 + c4];
                br_r[it] = *(const float4*)&KVR[(size_t)(k0 + kk) * FD + n0 + c4];
            }
        }
        const unsigned* As = AsuB + pi * AOA;
        const unsigned* Bl = BluB + pi * AOB;
        const unsigned* Br = BruB + pi * AOB;
#pragma unroll
        for (int k8 = 0; k8 < 2; k8++) {
            unsigned a[2][4];
            int ra0 = (k8 * 8 + qc) * 72;
            int ra1 = (k8 * 8 + qc + 4) * 72;
#pragma unroll
            for (int mi = 0; mi < 2; mi++) {
                int mb = wm * 32 + mi * 16 + qr;
                a[mi][0] = As[ra0 + mb];
                a[mi][1] = As[ra0 + mb + 8];
                a[mi][2] = As[ra1 + mb];
                a[mi][3] = As[ra1 + mb + 8];
            }
            int rb0 = (k8 * 8 + qc) * 264 + wn * 64 + qr;
            int rb1 = (k8 * 8 + qc + 4) * 264 + wn * 64 + qr;
#pragma unroll
            for (int j = 0; j < 8; j++) {
                unsigned bl[2] = {Bl[rb0 + j * 8], Bl[rb1 + j * 8]};
                unsigned br[2] = {Br[rb0 + j * 8], Br[rb1 + j * 8]};
                mma_tf32(accl[0][j], a[0], bl);
                mma_tf32(accl[1][j], a[1], bl);
                mma_tf32(accr[0][j], a[0], br);
                mma_tf32(accr[1][j], a[1], br);
            }
        }
        if (more) {
            unsigned* Ad = AsuB + (pi ^ 1) * AOA;
            unsigned* Bld = BluB + (pi ^ 1) * AOB;
            unsigned* Brd = BruB + (pi ^ 1) * AOB;
#pragma unroll
            for (int it = 0; it < 4; it++) {
                int idx = it * 256 + tid;
                int m = idx >> 4, kk = idx & 15;
                Ad[kk * 72 + m] = f2tf(a_r[it]);
            }
#pragma unroll
            for (int it = 0; it < 4; it++) {
                int e = it * 256 + tid;
                int kk = e >> 6, c4 = (e & 63) * 4;
                unsigned* bl = &Bld[kk * 264 + c4];
                unsigned* br = &Brd[kk * 264 + c4];
                bl[0] = f2tf(bl_r[it].x); bl[1] = f2tf(bl_r[it].y);
                bl[2] = f2tf(bl_r[it].z); bl[3] = f2tf(bl_r[it].w);
                br[0] = f2tf(br_r[it].x); br[1] = f2tf(br_r[it].y);
                br[2] = f2tf(br_r[it].z); br[3] = f2tf(br_r[it].w);
            }
        }
        pi ^= 1;
    }
#pragma unroll
    for (int mi = 0; mi < 2; mi++) {
#pragma unroll
        for (int half = 0; half < 2; half++) {
            int m = m0 + wm * 32 + mi * 16 + half * 8 + qr;
            float zl = Zl[m], zr = Zr[m];
#pragma unroll
            for (int j = 0; j < 8; j++) {
#pragma unroll
                for (int cc = 0; cc < 2; cc++) {
                    int d = n0 + wn * 64 + j * 8 + qc * 2 + cc;
                    C[(size_t)m * FD + d] = X[(size_t)m * FD + d]
                        + accl[mi][j][half * 2 + cc] / zl
                        + accr[mi][j][half * 2 + cc] / zr;
                }
            }
        }
    }
}

// ------ kernel 5: ConvTranspose 2x2 s2 via tf32 mma, double-buffered pipeline ------
__global__ __launch_bounds__(256) void convt_mma_kernel(
    const float* __restrict__ x, const float* __restrict__ upw,
    const float* __restrict__ upb, const float* __restrict__ s) {
    int n = blockIdx.z;
    const float* src = (n == 0) ? x
                     : (n == BB - 1) ? (x + (size_t)(BB - 1) * INC * FD)
                     : (g_mid + (size_t)(n - 1) * INC * FD);
    int m0 = blockIdx.x * 64;   // wcol
    int n0 = blockIdx.y * 256;  // ij

    __shared__ unsigned Asu[2][16 * 72];
    __shared__ unsigned Bsu[2][16 * 264];

    int tid = threadIdx.x;
    int warp = tid >> 5, lane = tid & 31;
    int wm = warp & 1;
    int wn = warp >> 1;
    int qr = lane >> 2;
    int qc = lane & 3;

    float acc[2][8][4] = {};

    float a_r[4];
    float4 b_r[4];

    // prefetch chunk 0
#pragma unroll
    for (int it = 0; it < 4; it++) {
        int e = it * 256 + tid;
        int cc = e >> 6, m = e & 63;
        a_r[it] = upw[(size_t)cc * 1024 + m0 + m];
        int c4 = (e & 63) * 4;
        b_r[it] = *(const float4*)&src[(size_t)cc * FD + n0 + c4];
    }
    // store chunk 0 to buffer 0
#pragma unroll
    for (int it = 0; it < 4; it++) {
        int e = it * 256 + tid;
        int cc = e >> 6, m = e & 63;
        Asu[0][cc * 72 + m] = f2tf(a_r[it]);
        int c4 = (e & 63) * 4;
        unsigned* bp = &Bsu[0][cc * 264 + c4];
        bp[0] = f2tf(b_r[it].x); bp[1] = f2tf(b_r[it].y);
        bp[2] = f2tf(b_r[it].z); bp[3] = f2tf(b_r[it].w);
    }

    int pi = 0;
    for (int c = 0; c < 32; c++) {
        __syncthreads();
        bool more = (c < 31);
        if (more) {
            int c0 = (c + 1) * 16;
#pragma unroll
            for (int it = 0; it < 4; it++) {
                int e = it * 256 + tid;
                int cc = e >> 6, m = e & 63;
                a_r[it] = upw[(size_t)(c0 + cc) * 1024 + m0 + m];
                int c4 = (e & 63) * 4;
                b_r[it] = *(const float4*)&src[(size_t)(c0 + cc) * FD + n0 + c4];
            }
        }
        const unsigned* As = Asu[pi];
        const unsigned* Bs = Bsu[pi];
#pragma unroll
        for (int k8 = 0; k8 < 2; k8++) {
            unsigned a[2][4];
            int ra0 = (k8 * 8 + qc) * 72;
            int ra1 = (k8 * 8 + qc + 4) * 72;
#pragma unroll
            for (int mi = 0; mi < 2; mi++) {
                int ocb = wm * 32 + mi * 16 + qr;
                a[mi][0] = As[ra0 + ocb];
                a[mi][1] = As[ra0 + ocb + 8];
                a[mi][2] = As[ra1 + ocb];
                a[mi][3] = As[ra1 + ocb + 8];
            }
            int rb0 = (k8 * 8 + qc) * 264 + wn * 64 + qr;
            int rb1 = (k8 * 8 + qc + 4) * 264 + wn * 64 + qr;
#pragma unroll
            for (int j = 0; j < 8; j++) {
                unsigned b[2] = {Bs[rb0 + j * 8], Bs[rb1 + j * 8]};
                mma_tf32(acc[0][j], a[0], b);
                mma_tf32(acc[1][j], a[1], b);
            }
        }
        if (more) {
            unsigned* Ad = Asu[pi ^ 1];
            unsigned* Bd = Bsu[pi ^ 1];
#pragma unroll
            for (int it = 0; it < 4; it++) {
                int e = it * 256 + tid;
                int cc = e >> 6, m = e & 63;
                Ad[cc * 72 + m] = f2tf(a_r[it]);
                int c4 = (e & 63) * 4;
                unsigned* bp = &Bd[cc * 264 + c4];
                bp[0] = f2tf(b_r[it].x); bp[1] = f2tf(b_r[it].y);
                bp[2] = f2tf(b_r[it].z); bp[3] = f2tf(b_r[it].w);
            }
        }
        pi ^= 1;
    }
    // epilogue: bias + skip + relu + sigmoid, scatter to g_gate
#pragma unroll
    for (int mi = 0; mi < 2; mi++) {
#pragma unroll
        for (int half = 0; half < 2; half++) {
            int row = m0 + wm * 32 + mi * 16 + half * 8 + qr;
            int o = row >> 2, ab = row & 3, av = ab >> 1, bq = ab & 1;
            float bias = upb[o];
#pragma unroll
            for (int j = 0; j < 8; j++) {
#pragma unroll
                for (int cc = 0; cc < 2; cc++) {
                    int col = n0 + wn * 64 + j * 8 + qc * 2 + cc;
                    int isp = col >> 5, jsp = col & 31;
                    int oy = 2 * isp + av, ox = 2 * jsp + bq;
                    size_t gi = (((size_t)n * OUTC + o) * OH + oy) * OW + ox;
                    float v = acc[mi][j][half * 2 + cc] + bias + s[gi];
                    v = v > 0.f ? v : 0.f;
                    g_gate[gi] = 1.f / (1.f + expf(-v));
                }
            }
        }
    }
}

// ---------------- kernel 6: conv3x3 via tf32 mma, double-buffered pipeline ----------------
#define PS 744
#define INW (8 * PS)      // 5952 words per input buffer
#define WW_ 4864          // 64*76 words per weight buffer
__global__ __launch_bounds__(256) void conv_mma_kernel(
    const float* __restrict__ sskip, const float* __restrict__ cw,
    const float* __restrict__ cb) {
    extern __shared__ unsigned dyns[];
    unsigned* inb = dyns;                   // 2 * INW
    unsigned* wb = dyns + 2 * INW;          // 2 * WW_
    float* rs = (float*)(dyns + 2 * INW + 2 * WW_);
    float* rq = rs + 64;

    int n = blockIdx.z;
    int oc0 = blockIdx.y * 64;
    int y0 = blockIdx.x * 8;

    int tid = threadIdx.x;
    int warp = tid >> 5, lane = tid & 31;
    int wn = warp;
    int qr = lane >> 2;
    int qc = lane & 3;

    // halo columns zero for BOTH buffers
    for (int e = tid; e < 320; e += 256) {
        int bsel = e >= 160;
        int r2 = e - bsel * 160;
        int r = r2 >> 1;
        int icc = r / 10, yy = r - icc * 10;
        inb[bsel * INW + icc * PS + yy * 72 + ((r2 & 1) ? 65 : 0)] = 0u;
    }
    if (tid < 64) { rs[tid] = 0.f; rq[tid] = 0.f; }

    float acc[4][8][4] = {};

    int seg = (tid & 15) * 4;
    int rbase = tid >> 4;

    float4 vin[5];
    float4 vw[5];

    // ---- prefetch chunk 0 ----
#pragma unroll
    for (int i = 0; i < 5; i++) {
        int r = rbase + 16 * i;
        int icc = r / 10, yy = r - icc * 10;
        int gy = y0 + yy - 1;
        int ic = icc;  // ic0 = 0
        if ((unsigned)gy < (unsigned)OH) {
            const float* srcp = (ic < OUTC)
                ? &g_gate[(((size_t)n * OUTC + ic) * OH + gy) * OW + seg]
                : &sskip[(((size_t)n * OUTC + (ic - OUTC)) * OH + gy) * OW + seg];
            vin[i] = *(const float4*)srcp;
        } else vin[i] = make_float4(0.f, 0.f, 0.f, 0.f);
    }
#pragma unroll
    for (int i = 0; i < 5; i++) {
        int e = tid + 256 * i;
        if (e < 1152) {
            int oc = e / 18, f = e - oc * 18;
            vw[i] = *(const float4*)&cw[(size_t)(oc0 + oc) * (2 * OUTC * 9) + f * 4];
        }
    }
    // ---- store chunk 0 to buffer 0 ----
#pragma unroll
    for (int i = 0; i < 5; i++) {
        int r = rbase + 16 * i;
        int icc = r / 10, yy = r - icc * 10;
        unsigned* dst = &inb[icc * PS + yy * 72 + 1 + seg];
        dst[0] = f2tf(vin[i].x); dst[1] = f2tf(vin[i].y);
        dst[2] = f2tf(vin[i].z); dst[3] = f2tf(vin[i].w);
    }
#pragma unroll
    for (int i = 0; i < 5; i++) {
        int e = tid + 256 * i;
        if (e < 1152) {
            int oc = e / 18, f = e - oc * 18;
            unsigned* wp = &wb[oc * 76 + f * 4];
            wp[0] = f2tf(vw[i].x); wp[1] = f2tf(vw[i].y);
            wp[2] = f2tf(vw[i].z); wp[3] = f2tf(vw[i].w);
        }
    }

    int pi = 0;
    for (int c = 0; c < 64; c++) {
        __syncthreads();
        bool more = (c < 63);
        if (more) {
            int ic0 = (c + 1) * 8;
#pragma unroll
            for (int i = 0; i < 5; i++) {
                int r = rbase + 16 * i;
                int icc = r / 10, yy = r - icc * 10;
                int gy = y0 + yy - 1;
                int ic = ic0 + icc;
                if ((unsigned)gy < (unsigned)OH) {
                    const float* srcp = (ic < OUTC)
                        ? &g_gate[(((size_t)n * OUTC + ic) * OH + gy) * OW + seg]
                        : &sskip[(((size_t)n * OUTC + (ic - OUTC)) * OH + gy) * OW + seg];
                    vin[i] = *(const float4*)srcp;
                } else vin[i] = make_float4(0.f, 0.f, 0.f, 0.f);
            }
#pragma unroll
            for (int i = 0; i < 5; i++) {
                int e = tid + 256 * i;
                if (e < 1152) {
                    int oc = e / 18, f = e - oc * 18;
                    vw[i] = *(const float4*)&cw[(size_t)(oc0 + oc) * (2 * OUTC * 9) + ic0 * 9 + f * 4];
                }
            }
        }
        const unsigned* in_s = inb + (pi ? INW : 0);
        const unsigned* w_s = wb + (pi ? WW_ : 0);
#pragma unroll
        for (int ky = 0; ky < 3; ky++) {
            int rowoff = (wn + ky) * 72;
#pragma unroll
            for (int kx = 0; kx < 3; kx++) {
                int pos = ky * 3 + kx;
                unsigned a[4][4];
#pragma unroll
                for (int mi = 0; mi < 4; mi++) {
                    int ocb = mi * 16 + qr;
                    a[mi][0] = w_s[ocb * 76 + qc * 9 + pos];
                    a[mi][1] = w_s[(ocb + 8) * 76 + qc * 9 + pos];
                    a[mi][2] = w_s[ocb * 76 + (qc + 4) * 9 + pos];
                    a[mi][3] = w_s[(ocb + 8) * 76 + (qc + 4) * 9 + pos];
                }
#pragma unroll
                for (int j = 0; j < 8; j++) {
                    int col = j * 8 + qr + kx;
                    unsigned b[2] = {in_s[qc * PS + rowoff + col],
                                     in_s[(qc + 4) * PS + rowoff + col]};
                    mma_tf32(acc[0][j], a[0], b);
                    mma_tf32(acc[1][j], a[1], b);
                    mma_tf32(acc[2][j], a[2], b);
                    mma_tf32(acc[3][j], a[3], b);
                }
            }
        }
        if (more) {
            unsigned* ind = inb + (pi ? 0 : INW);
            unsigned* wd = wb + (pi ? 0 : WW_);
#pragma unroll
            for (int i = 0; i < 5; i++) {
                int r = rbase + 16 * i;
                int icc = r / 10, yy = r - icc * 10;
                unsigned* dst = &ind[icc * PS + yy * 72 + 1 + seg];
                dst[0] = f2tf(vin[i].x); dst[1] = f2tf(vin[i].y);
                dst[2] = f2tf(vin[i].z); dst[3] = f2tf(vin[i].w);
            }
#pragma unroll
            for (int i = 0; i < 5; i++) {
                int e = tid + 256 * i;
                if (e < 1152) {
                    int oc = e / 18, f = e - oc * 18;
                    unsigned* wp = &wd[oc * 76 + f * 4];
                    wp[0] = f2tf(vw[i].x); wp[1] = f2tf(vw[i].y);
                    wp[2] = f2tf(vw[i].z); wp[3] = f2tf(vw[i].w);
                }
            }
        }
        pi ^= 1;
    }

    // epilogue: bias, store y, BN partial sums
    int row = y0 + wn;
#pragma unroll
    for (int mi = 0; mi < 4; mi++) {
#pragma unroll
        for (int half = 0; half < 2; half++) {
            int ocl = mi * 16 + half * 8 + qr;
            int oc = oc0 + ocl;
            float bias = cb[oc];
            float s0 = 0.f, s1 = 0.f;
#pragma unroll
            for (int j = 0; j < 8; j++) {
#pragma unroll
                for (int cc = 0; cc < 2; cc++) {
                    float v = acc[mi][j][half * 2 + cc] + bias;
                    int col = j * 8 + qc * 2 + cc;
                    g_y[(((size_t)n * OUTC + oc) * OH + row) * OW + col] = v;
                    s0 += v;
                    s1 += v * v;
                }
            }
            s0 += __shfl_xor_sync(0xffffffffu, s0, 1);
            s0 += __shfl_xor_sync(0xffffffffu, s0, 2);
            s1 += __shfl_xor_sync(0xffffffffu, s1, 1);
            s1 += __shfl_xor_sync(0xffffffffu, s1, 2);
            if (qc == 0) {
                atomicAdd(&rs[ocl], s0);
                atomicAdd(&rq[ocl], s1);
            }
        }
    }
    __syncthreads();
    if (tid < 64) {
        atomicAdd(&g_bnsum[oc0 + tid], rs[tid]);
        atomicAdd(&g_bnsq[oc0 + tid], rq[tid]);
    }
}

// ---------------- small kernels ----------------
__global__ void zero_kernel() {
    int t = threadIdx.x;
    g_bnsum[t] = 0.f;
    g_bnsq[t] = 0.f;
}

__global__ void bnstats_kernel(const float* __restrict__ bn_g, const float* __restrict__ bn_b) {
    int c = threadIdx.x;
    float cnt = (float)(BB * OH * OW);
    float mean = g_bnsum[c] / cnt;
    float var = g_bnsq[c] / cnt - mean * mean;
    float inv = rsqrtf(var + 1e-5f);
    float sc = bn_g[c] * inv;
    g_bnscale[c] = sc;
    g_bnshift[c] = bn_b[c] - mean * sc;
}

__global__ void bnorm_kernel(float* __restrict__ out) {
    int i4 = blockIdx.x * blockDim.x + threadIdx.x;
    const int total4 = BB * OUTC * OH * OW / 4;
    if (i4 >= total4) return;
    int base = i4 * 4;
    int oc = (base >> 12) & (OUTC - 1);  // OH*OW = 4096
    float sc = g_bnscale[oc], sh = g_bnshift[oc];
    float4 v = *(const float4*)&g_y[base];
    float4 r;
    r.x = fmaxf(v.x * sc + sh, 0.f);
    r.y = fmaxf(v.y * sc + sh, 0.f);
    r.z = fmaxf(v.z * sc + sh, 0.f);
    r.w = fmaxf(v.w * sc + sh, 0.f);
    *(float4*)&out[base] = r;
}

// ---------------- launcher ----------------
extern "C" void kernel_launch(void* const* d_in, const int* in_sizes, int n_in,
                              void* d_out, int out_size) {
    const float* x    = (const float*)d_in[0];
    const float* s    = (const float*)d_in[1];
    const float* up_w = (const float*)d_in[2];
    const float* up_b = (const float*)d_in[3];
    const float* wq   = (const float*)d_in[4];
    const float* wkl  = (const float*)d_in[5];
    const float* wkr  = (const float*)d_in[6];
    const float* c1_w = (const float*)d_in[7];
    const float* c1_b = (const float*)d_in[8];
    const float* bn_g = (const float*)d_in[9];
    const float* bn_b = (const float*)d_in[10];
    float* out = (float*)d_out;

    const int conv_smem = (2 * INW + 2 * WW_) * 4 + 128 * 4;  // 87040 bytes
    cudaFuncSetAttribute(conv_mma_kernel,
                         cudaFuncAttributeMaxDynamicSharedMemorySize, conv_smem);
    const int ao_smem = (2 * AOA + 2 * AOB * 2) * 4;          // 76800 bytes
    cudaFuncSetAttribute(attnout_mma_kernel,
                         cudaFuncAttributeMaxDynamicSharedMemorySize, ao_smem);

    proj_mma_kernel<<<dim3(8, 1, NS * 3), 256>>>(x, wq, wkl, wkr);
    sumz_kernel<<<dim3(NS, 2), 128>>>();
    kv_mma_kernel<<<dim3(2, 4, NS * 2), 256>>>(x);
    attnout_mma_kernel<<<dim3(8, 4, NS), 256, ao_smem>>>(x);
    convt_mma_kernel<<<dim3(16, 4, BB), 256>>>(x, up_w, up_b, s);
    zero_kernel<<<1, OUTC>>>();
    conv_mma_kernel<<<dim3(8, 4, BB), 256, conv_smem>>>(s, c1_w, c1_b);
    bnstats_kernel<<<1, OUTC>>>(bn_g, bn_b);
    int total4 = BB * OUTC * OH * OW / 4;
    bnorm_kernel<<<(total4 + 255) / 256, 256>>>(out);
}

// round 8
// speedup vs baseline: 4.1802x; 1.1443x over previous
#include <cuda_runtime.h>
#include <math.h>

#define BB 16
#define INC 512
#define OUTC 256
#define HH 32
#define WW 32
#define FD 1024
#define DK 128
#define NS 14          // interior samples (B-2)
#define OH 64
#define OW 64

// ---------------- scratch (static device memory; no allocation) ----------------
__device__ float g_mid[NS * INC * FD];
__device__ float g_q[NS * INC * DK];
__device__ float g_kl[NS * INC * DK];
__device__ float g_kr[NS * INC * DK];
__device__ float g_kvl[NS * DK * FD];
__device__ float g_kvr[NS * DK * FD];
__device__ float g_z[2 * NS * INC];
__device__ float g_gate[BB * OUTC * OH * OW];
__device__ float g_y[BB * OUTC * OH * OW];
__device__ float g_bnsum[OUTC];
__device__ float g_bnsq[OUTC];
__device__ float g_bnscale[OUTC];
__device__ float g_bnshift[OUTC];

// ---------------- tf32 mma helpers ----------------
// NOTE: raw fp32 bit patterns are fed to the tf32 MMA; the tensor core
// truncates the low mantissa bits (CUTLASS round_toward_zero fast path).
__device__ __forceinline__ void mma_tf32(float (&d)[4], const unsigned (&a)[4], const unsigned (&b)[2]) {
    asm("mma.sync.aligned.m16n8k8.row.col.f32.tf32.tf32.f32 "
        "{%0,%1,%2,%3}, {%4,%5,%6,%7}, {%8,%9}, {%0,%1,%2,%3};"
        : "+f"(d[0]), "+f"(d[1]), "+f"(d[2]), "+f"(d[3])
        : "r"(a[0]), "r"(a[1]), "r"(a[2]), "r"(a[3]), "r"(b[0]), "r"(b[1]));
}

__device__ __forceinline__ void cpa16(void* d, const void* s) {
    unsigned sa = (unsigned)__cvta_generic_to_shared(d);
    asm volatile("cp.async.cg.shared.global [%0], [%1], 16;" :: "r"(sa), "l"(s));
}
__device__ __forceinline__ void cpa16z(void* d, const void* s, int sz) {
    unsigned sa = (unsigned)__cvta_generic_to_shared(d);
    asm volatile("cp.async.cg.shared.global [%0], [%1], 16, %2;" :: "r"(sa), "l"(s), "r"(sz));
}
__device__ __forceinline__ void cpa4(void* d, const void* s) {
    unsigned sa = (unsigned)__cvta_generic_to_shared(d);
    asm volatile("cp.async.ca.shared.global [%0], [%1], 4;" :: "r"(sa), "l"(s));
}
#define CP_COMMIT() asm volatile("cp.async.commit_group;")
#define CP_WAIT0()  asm volatile("cp.async.wait_group 0;")

// ---------------- kernel 1: projections q/kl/kr = phi(A @ W) ----------------
__global__ __launch_bounds__(256) void proj_mma_kernel(
    const float* __restrict__ x, const float* __restrict__ wq,
    const float* __restrict__ wkl, const float* __restrict__ wkr) {
    int zi = blockIdx.z;
    int sample = zi / 3, p = zi % 3;
    const float* A;
    const float* Wm;
    float* C;
    if (p == 0)      { A = x + (size_t)(sample + 1) * INC * FD; Wm = wq;  C = g_q  + (size_t)sample * INC * DK; }
    else if (p == 1) { A = x + (size_t)(sample + 0) * INC * FD; Wm = wkl; C = g_kl + (size_t)sample * INC * DK; }
    else             { A = x + (size_t)(sample + 2) * INC * FD; Wm = wkr; C = g_kr + (size_t)sample * INC * DK; }

    __shared__ unsigned Asu[2][16 * 72];
    __shared__ unsigned Bsu[2][16 * 136];

    int m0 = blockIdx.x * 64;
    int tid = threadIdx.x;
    int warp = tid >> 5, lane = tid & 31;
    int wm = warp & 3;
    int wn = warp >> 2;
    int qr = lane >> 2, qc = lane & 3;

    float acc[8][4] = {};

    // issue chunk 0
#pragma unroll
    for (int it = 0; it < 4; it++) {
        int idx = it * 256 + tid;
        int m = idx >> 4, kk = idx & 15;
        cpa4(&Asu[0][kk * 72 + m], &A[(size_t)(m0 + m) * FD + kk]);
    }
#pragma unroll
    for (int it = 0; it < 2; it++) {
        int e = it * 256 + tid;
        int kk = e >> 5, c4 = (e & 31) * 4;
        cpa16(&Bsu[0][kk * 136 + c4], &Wm[(size_t)kk * DK + c4]);
    }
    CP_COMMIT();

    int pi = 0;
    for (int c = 0; c < 64; c++) {
        CP_WAIT0();
        __syncthreads();
        if (c < 63) {
            int k0 = (c + 1) * 16;
            unsigned* Ad = Asu[pi ^ 1];
            unsigned* Bd = Bsu[pi ^ 1];
#pragma unroll
            for (int it = 0; it < 4; it++) {
                int idx = it * 256 + tid;
                int m = idx >> 4, kk = idx & 15;
                cpa4(&Ad[kk * 72 + m], &A[(size_t)(m0 + m) * FD + k0 + kk]);
            }
#pragma unroll
            for (int it = 0; it < 2; it++) {
                int e = it * 256 + tid;
                int kk = e >> 5, c4 = (e & 31) * 4;
                cpa16(&Bd[kk * 136 + c4], &Wm[(size_t)(k0 + kk) * DK + c4]);
            }
            CP_COMMIT();
        }
        const unsigned* As = Asu[pi];
        const unsigned* Bs = Bsu[pi];
#pragma unroll
        for (int k8 = 0; k8 < 2; k8++) {
            int ra0 = (k8 * 8 + qc) * 72;
            int ra1 = (k8 * 8 + qc + 4) * 72;
            unsigned a[4];
            int mb = wm * 16 + qr;
            a[0] = As[ra0 + mb];
            a[1] = As[ra0 + mb + 8];
            a[2] = As[ra1 + mb];
            a[3] = As[ra1 + mb + 8];
            int rb0 = (k8 * 8 + qc) * 136 + wn * 64 + qr;
            int rb1 = (k8 * 8 + qc + 4) * 136 + wn * 64 + qr;
#pragma unroll
            for (int j = 0; j < 8; j++) {
                unsigned b[2] = {Bs[rb0 + j * 8], Bs[rb1 + j * 8]};
                mma_tf32(acc[j], a, b);
            }
        }
        pi ^= 1;
    }
    // epilogue: phi = elu + 1
#pragma unroll
    for (int half = 0; half < 2; half++) {
        int m = m0 + wm * 16 + half * 8 + qr;
#pragma unroll
        for (int j = 0; j < 8; j++) {
#pragma unroll
            for (int cc = 0; cc < 2; cc++) {
                int ncol = wn * 64 + j * 8 + qc * 2 + cc;
                float v = acc[j][half * 2 + cc];
                C[(size_t)m * DK + ncol] = (v > 0.f) ? (v + 1.f) : expf(v);
            }
        }
    }
}

// ---------------- kernel 2: column sums + z = q @ ksum + 1e-6 ----------------
__global__ void sumz_kernel() {
    int sample = blockIdx.x;
    int side = blockIdx.y;
    const float* K = (side == 0 ? g_kl : g_kr) + (size_t)sample * INC * DK;
    const float* Q = g_q + (size_t)sample * INC * DK;
    __shared__ float ssum[DK];
    int t = threadIdx.x;
    float s = 0.f;
    for (int n = 0; n < INC; n++) s += K[n * DK + t];
    ssum[t] = s;
    __syncthreads();
    float* Z = g_z + (size_t)(side * NS + sample) * INC;
    for (int rr = 0; rr < 4; rr++) {
        int row = rr * 128 + t;
        float d = 0.f;
        for (int k = 0; k < DK; k++) d += Q[row * DK + k] * ssum[k];
        Z[row] = d + 1e-6f;
    }
}

// ---------------- kernel 3: kv[k][d] = sum_n K[n][k] * V[n][d] ----------------
__global__ __launch_bounds__(256) void kv_mma_kernel(const float* __restrict__ x) {
    int zi = blockIdx.z;
    int sample = zi >> 1, side = zi & 1;
    const float* K = (side == 0 ? g_kl : g_kr) + (size_t)sample * INC * DK;
    const float* V = x + (size_t)(sample + (side == 0 ? 0 : 2)) * INC * FD;
    float* C = (side == 0 ? g_kvl : g_kvr) + (size_t)sample * DK * FD;

    __shared__ unsigned Asu[2][16 * 72];
    __shared__ unsigned Bsu[2][16 * 264];

    int m0 = blockIdx.x * 64;
    int n0 = blockIdx.y * 256;
    int tid = threadIdx.x;
    int warp = tid >> 5, lane = tid & 31;
    int wm = warp & 1, wn = warp >> 1;
    int qr = lane >> 2, qc = lane & 3;

    float acc[2][8][4] = {};

    // issue chunk 0
    {
        int nn = tid >> 4, k4 = (tid & 15) * 4;
        cpa16(&Asu[0][nn * 72 + k4], &K[(size_t)nn * DK + m0 + k4]);
    }
#pragma unroll
    for (int it = 0; it < 4; it++) {
        int e = it * 256 + tid;
        int nn = e >> 6, c4 = (e & 63) * 4;
        cpa16(&Bsu[0][nn * 264 + c4], &V[(size_t)nn * FD + n0 + c4]);
    }
    CP_COMMIT();

    int pi = 0;
    for (int c = 0; c < 32; c++) {
        CP_WAIT0();
        __syncthreads();
        if (c < 31) {
            int c0 = (c + 1) * 16;
            unsigned* Ad = Asu[pi ^ 1];
            unsigned* Bd = Bsu[pi ^ 1];
            {
                int nn = tid >> 4, k4 = (tid & 15) * 4;
                cpa16(&Ad[nn * 72 + k4], &K[(size_t)(c0 + nn) * DK + m0 + k4]);
            }
#pragma unroll
            for (int it = 0; it < 4; it++) {
                int e = it * 256 + tid;
                int nn = e >> 6, c4 = (e & 63) * 4;
                cpa16(&Bd[nn * 264 + c4], &V[(size_t)(c0 + nn) * FD + n0 + c4]);
            }
            CP_COMMIT();
        }
        const unsigned* As = Asu[pi];
        const unsigned* Bs = Bsu[pi];
#pragma unroll
        for (int k8 = 0; k8 < 2; k8++) {
            unsigned a[2][4];
            int ra0 = (k8 * 8 + qc) * 72;
            int ra1 = (k8 * 8 + qc + 4) * 72;
#pragma unroll
            for (int mi = 0; mi < 2; mi++) {
                int mb = wm * 32 + mi * 16 + qr;
                a[mi][0] = As[ra0 + mb];
                a[mi][1] = As[ra0 + mb + 8];
                a[mi][2] = As[ra1 + mb];
                a[mi][3] = As[ra1 + mb + 8];
            }
            int rb0 = (k8 * 8 + qc) * 264 + wn * 64 + qr;
            int rb1 = (k8 * 8 + qc + 4) * 264 + wn * 64 + qr;
#pragma unroll
            for (int j = 0; j < 8; j++) {
                unsigned b[2] = {Bs[rb0 + j * 8], Bs[rb1 + j * 8]};
                mma_tf32(acc[0][j], a[0], b);
                mma_tf32(acc[1][j], a[1], b);
            }
        }
        pi ^= 1;
    }
#pragma unroll
    for (int mi = 0; mi < 2; mi++) {
#pragma unroll
        for (int half = 0; half < 2; half++) {
            int m = m0 + wm * 32 + mi * 16 + half * 8 + qr;
#pragma unroll
            for (int j = 0; j < 8; j++) {
#pragma unroll
                for (int cc = 0; cc < 2; cc++) {
                    int d = n0 + wn * 64 + j * 8 + qc * 2 + cc;
                    C[(size_t)m * FD + d] = acc[mi][j][half * 2 + cc];
                }
            }
        }
    }
}

// ------ kernel 4: out = x + (q@kvl)/zl + (q@kvr)/zr, dual-B tf32 mma ------
#define AOA 1152   // 16*72
#define AOB 4224   // 16*264
__global__ __launch_bounds__(256) void attnout_mma_kernel(const float* __restrict__ x) {
    extern __shared__ unsigned dsm[];
    unsigned* AsuB = dsm;
    unsigned* BluB = dsm + 2 * AOA;
    unsigned* BruB = dsm + 2 * AOA + 2 * AOB;

    int sample = blockIdx.z;
    const float* Q = g_q + (size_t)sample * INC * DK;
    const float* KVL = g_kvl + (size_t)sample * DK * FD;
    const float* KVR = g_kvr + (size_t)sample * DK * FD;
    const float* Zl = g_z + (size_t)sample * INC;
    const float* Zr = g_z + (size_t)(NS + sample) * INC;
    const float* X = x + (size_t)(sample + 1) * INC * FD;
    float* C = g_mid + (size_t)sample * INC * FD;

    int m0 = blockIdx.x * 64;
    int n0 = blockIdx.y * 256;
    int tid = threadIdx.x;
    int warp = tid >> 5, lane = tid & 31;
    int wm = warp & 1, wn = warp >> 1;
    int qr = lane >> 2, qc = lane & 3;

    float accl[2][8][4] = {}, accr[2][8][4] = {};

    // issue chunk 0
#pragma unroll
    for (int it = 0; it < 4; it++) {
        int idx = it * 256 + tid;
        int m = idx >> 4, kk = idx & 15;
        cpa4(&AsuB[kk * 72 + m], &Q[(size_t)(m0 + m) * DK + kk]);
    }
#pragma unroll
    for (int it = 0; it < 4; it++) {
        int e = it * 256 + tid;
        int kk = e >> 6, c4 = (e & 63) * 4;
        cpa16(&BluB[kk * 264 + c4], &KVL[(size_t)kk * FD + n0 + c4]);
        cpa16(&BruB[kk * 264 + c4], &KVR[(size_t)kk * FD + n0 + c4]);
    }
    CP_COMMIT();

    int pi = 0;
    for (int c = 0; c < 8; c++) {
        CP_WAIT0();
        __syncthreads();
        if (c < 7) {
            int k0 = (c + 1) * 16;
            unsigned* Ad = AsuB + (pi ^ 1) * AOA;
            unsigned* Bld = BluB + (pi ^ 1) * AOB;
            unsigned* Brd = BruB + (pi ^ 1) * AOB;
#pragma unroll
            for (int it = 0; it < 4; it++) {
                int idx = it * 256 + tid;
                int m = idx >> 4, kk = idx & 15;
                cpa4(&Ad[kk * 72 + m], &Q[(size_t)(m0 + m) * DK + k0 + kk]);
            }
#pragma unroll
            for (int it = 0; it < 4; it++) {
                int e = it * 256 + tid;
                int kk = e >> 6, c4 = (e & 63) * 4;
                cpa16(&Bld[kk * 264 + c4], &KVL[(size_t)(k0 + kk) * FD + n0 + c4]);
                cpa16(&Brd[kk * 264 + c4], &KVR[(size_t)(k0 + kk) * FD + n0 + c4]);
            }
            CP_COMMIT();
        }
        const unsigned* As = AsuB + pi * AOA;
        const unsigned* Bl = BluB + pi * AOB;
        const unsigned* Br = BruB + pi * AOB;
#pragma unroll
        for (int k8 = 0; k8 < 2; k8++) {
            unsigned a[2][4];
            int ra0 = (k8 * 8 + qc) * 72;
            int ra1 = (k8 * 8 + qc + 4) * 72;
#pragma unroll
            for (int mi = 0; mi < 2; mi++) {
                int mb = wm * 32 + mi * 16 + qr;
                a[mi][0] = As[ra0 + mb];
                a[mi][1] = As[ra0 + mb + 8];
                a[mi][2] = As[ra1 + mb];
                a[mi][3] = As[ra1 + mb + 8];
            }
            int rb0 = (k8 * 8 + qc) * 264 + wn * 64 + qr;
            int rb1 = (k8 * 8 + qc + 4) * 264 + wn * 64 + qr;
#pragma unroll
            for (int j = 0; j < 8; j++) {
                unsigned bl[2] = {Bl[rb0 + j * 8], Bl[rb1 + j * 8]};
                unsigned br[2] = {Br[rb0 + j * 8], Br[rb1 + j * 8]};
                mma_tf32(accl[0][j], a[0], bl);
                mma_tf32(accl[1][j], a[1], bl);
                mma_tf32(accr[0][j], a[0], br);
                mma_tf32(accr[1][j], a[1], br);
            }
        }
        pi ^= 1;
    }
#pragma unroll
    for (int mi = 0; mi < 2; mi++) {
#pragma unroll
        for (int half = 0; half < 2; half++) {
            int m = m0 + wm * 32 + mi * 16 + half * 8 + qr;
            float zl = Zl[m], zr = Zr[m];
#pragma unroll
            for (int j = 0; j < 8; j++) {
#pragma unroll
                for (int cc = 0; cc < 2; cc++) {
                    int d = n0 + wn * 64 + j * 8 + qc * 2 + cc;
                    C[(size_t)m * FD + d] = X[(size_t)m * FD + d]
                        + accl[mi][j][half * 2 + cc] / zl
                        + accr[mi][j][half * 2 + cc] / zr;
                }
            }
        }
    }
}

// ------ kernel 5: ConvTranspose 2x2 s2 via tf32 mma + fused gate ------
__global__ __launch_bounds__(256) void convt_mma_kernel(
    const float* __restrict__ x, const float* __restrict__ upw,
    const float* __restrict__ upb, const float* __restrict__ s) {
    int n = blockIdx.z;
    const float* src = (n == 0) ? x
                     : (n == BB - 1) ? (x + (size_t)(BB - 1) * INC * FD)
                     : (g_mid + (size_t)(n - 1) * INC * FD);
    int m0 = blockIdx.x * 64;
    int n0 = blockIdx.y * 256;

    __shared__ unsigned Asu[2][16 * 72];
    __shared__ unsigned Bsu[2][16 * 264];

    int tid = threadIdx.x;
    int warp = tid >> 5, lane = tid & 31;
    int wm = warp & 1;
    int wn = warp >> 1;
    int qr = lane >> 2;
    int qc = lane & 3;

    float acc[2][8][4] = {};

    // issue chunk 0
    {
        int cc = tid >> 4, m4 = (tid & 15) * 4;
        cpa16(&Asu[0][cc * 72 + m4], &upw[(size_t)cc * 1024 + m0 + m4]);
    }
#pragma unroll
    for (int it = 0; it < 4; it++) {
        int e = it * 256 + tid;
        int cc = e >> 6, c4 = (e & 63) * 4;
        cpa16(&Bsu[0][cc * 264 + c4], &src[(size_t)cc * FD + n0 + c4]);
    }
    CP_COMMIT();

    int pi = 0;
    for (int c = 0; c < 32; c++) {
        CP_WAIT0();
        __syncthreads();
        if (c < 31) {
            int c0 = (c + 1) * 16;
            unsigned* Ad = Asu[pi ^ 1];
            unsigned* Bd = Bsu[pi ^ 1];
            {
                int cc = tid >> 4, m4 = (tid & 15) * 4;
                cpa16(&Ad[cc * 72 + m4], &upw[(size_t)(c0 + cc) * 1024 + m0 + m4]);
            }
#pragma unroll
            for (int it = 0; it < 4; it++) {
                int e = it * 256 + tid;
                int cc = e >> 6, c4 = (e & 63) * 4;
                cpa16(&Bd[cc * 264 + c4], &src[(size_t)(c0 + cc) * FD + n0 + c4]);
            }
            CP_COMMIT();
        }
        const unsigned* As = Asu[pi];
        const unsigned* Bs = Bsu[pi];
#pragma unroll
        for (int k8 = 0; k8 < 2; k8++) {
            unsigned a[2][4];
            int ra0 = (k8 * 8 + qc) * 72;
            int ra1 = (k8 * 8 + qc + 4) * 72;
#pragma unroll
            for (int mi = 0; mi < 2; mi++) {
                int ocb = wm * 32 + mi * 16 + qr;
                a[mi][0] = As[ra0 + ocb];
                a[mi][1] = As[ra0 + ocb + 8];
                a[mi][2] = As[ra1 + ocb];
                a[mi][3] = As[ra1 + ocb + 8];
            }
            int rb0 = (k8 * 8 + qc) * 264 + wn * 64 + qr;
            int rb1 = (k8 * 8 + qc + 4) * 264 + wn * 64 + qr;
#pragma unroll
            for (int j = 0; j < 8; j++) {
                unsigned b[2] = {Bs[rb0 + j * 8], Bs[rb1 + j * 8]};
                mma_tf32(acc[0][j], a[0], b);
                mma_tf32(acc[1][j], a[1], b);
            }
        }
        pi ^= 1;
    }
    // epilogue: bias + skip + relu + sigmoid, scatter to g_gate
#pragma unroll
    for (int mi = 0; mi < 2; mi++) {
#pragma unroll
        for (int half = 0; half < 2; half++) {
            int row = m0 + wm * 32 + mi * 16 + half * 8 + qr;
            int o = row >> 2, ab = row & 3, av = ab >> 1, bq = ab & 1;
            float bias = upb[o];
#pragma unroll
            for (int j = 0; j < 8; j++) {
#pragma unroll
                for (int cc = 0; cc < 2; cc++) {
                    int col = n0 + wn * 64 + j * 8 + qc * 2 + cc;
                    int isp = col >> 5, jsp = col & 31;
                    int oy = 2 * isp + av, ox = 2 * jsp + bq;
                    size_t gi = (((size_t)n * OUTC + o) * OH + oy) * OW + ox;
                    float v = acc[mi][j][half * 2 + cc] + bias + s[gi];
                    v = v > 0.f ? v : 0.f;
                    g_gate[gi] = 1.f / (1.f + expf(-v));
                }
            }
        }
    }
}

// ---------------- kernel 6: conv3x3 via tf32 mma, cp.async pipeline ----------------
// Row layout: halo at word 3 and 68, interior 4..67 (16B-aligned), stride 72.
#define PS 744
#define INW (8 * PS)
#define WW_ 4864
__global__ __launch_bounds__(256) void conv_mma_kernel(
    const float* __restrict__ sskip, const float* __restrict__ cw,
    const float* __restrict__ cb) {
    extern __shared__ unsigned dyns[];
    unsigned* inb = dyns;                   // 2 * INW
    unsigned* wb = dyns + 2 * INW;          // 2 * WW_
    float* rs = (float*)(dyns + 2 * INW + 2 * WW_);
    float* rq = rs + 64;

    int n = blockIdx.z;
    int oc0 = blockIdx.y * 64;
    int y0 = blockIdx.x * 8;

    int tid = threadIdx.x;
    int warp = tid >> 5, lane = tid & 31;
    int wn = warp;
    int qr = lane >> 2;
    int qc = lane & 3;

    // halo columns zero for BOTH buffers (positions 3 and 68)
    for (int e = tid; e < 320; e += 256) {
        int bsel = e >= 160;
        int r2 = e - bsel * 160;
        int r = r2 >> 1;
        int icc = r / 10, yy = r - icc * 10;
        inb[bsel * INW + icc * PS + yy * 72 + ((r2 & 1) ? 68 : 3)] = 0u;
    }
    if (tid < 64) { rs[tid] = 0.f; rq[tid] = 0.f; }

    float acc[4][8][4] = {};

    int seg = (tid & 15) * 4;
    int rbase = tid >> 4;

    // ---- issue chunk 0 ----
#pragma unroll
    for (int i = 0; i < 5; i++) {
        int r = rbase + 16 * i;
        int icc = r / 10, yy = r - icc * 10;
        int gy = y0 + yy - 1;
        int ic = icc;
        int gyc = gy < 0 ? 0 : (gy > OH - 1 ? OH - 1 : gy);
        const float* srcp = (ic < OUTC)
            ? &g_gate[(((size_t)n * OUTC + ic) * OH + gyc) * OW + seg]
            : &sskip[(((size_t)n * OUTC + (ic - OUTC)) * OH + gyc) * OW + seg];
        int sz = ((unsigned)gy < (unsigned)OH) ? 16 : 0;
        cpa16z(&inb[icc * PS + yy * 72 + 4 + seg], srcp, sz);
    }
#pragma unroll
    for (int i = 0; i < 5; i++) {
        int e = tid + 256 * i;
        if (e < 1152) {
            int oc = e / 18, f = e - oc * 18;
            cpa16(&wb[oc * 76 + f * 4], &cw[(size_t)(oc0 + oc) * (2 * OUTC * 9) + f * 4]);
        }
    }
    CP_COMMIT();

    int pi = 0;
    for (int c = 0; c < 64; c++) {
        CP_WAIT0();
        __syncthreads();
        if (c < 63) {
            int ic0 = (c + 1) * 8;
            unsigned* ind = inb + (pi ? 0 : INW);
            unsigned* wd = wb + (pi ? 0 : WW_);
#pragma unroll
            for (int i = 0; i < 5; i++) {
                int r = rbase + 16 * i;
                int icc = r / 10, yy = r - icc * 10;
                int gy = y0 + yy - 1;
                int ic = ic0 + icc;
                int gyc = gy < 0 ? 0 : (gy > OH - 1 ? OH - 1 : gy);
                const float* srcp = (ic < OUTC)
                    ? &g_gate[(((size_t)n * OUTC + ic) * OH + gyc) * OW + seg]
                    : &sskip[(((size_t)n * OUTC + (ic - OUTC)) * OH + gyc) * OW + seg];
                int sz = ((unsigned)gy < (unsigned)OH) ? 16 : 0;
                cpa16z(&ind[icc * PS + yy * 72 + 4 + seg], srcp, sz);
            }
#pragma unroll
            for (int i = 0; i < 5; i++) {
                int e = tid + 256 * i;
                if (e < 1152) {
                    int oc = e / 18, f = e - oc * 18;
                    cpa16(&wd[oc * 76 + f * 4], &cw[(size_t)(oc0 + oc) * (2 * OUTC * 9) + ic0 * 9 + f * 4]);
                }
            }
            CP_COMMIT();
        }
        const unsigned* in_s = inb + (pi ? INW : 0);
        const unsigned* w_s = wb + (pi ? WW_ : 0);
#pragma unroll
        for (int ky = 0; ky < 3; ky++) {
            int rowoff = (wn + ky) * 72 + 3;
#pragma unroll
            for (int kx = 0; kx < 3; kx++) {
                int pos = ky * 3 + kx;
                unsigned a[4][4];
#pragma unroll
                for (int mi = 0; mi < 4; mi++) {
                    int ocb = mi * 16 + qr;
                    a[mi][0] = w_s[ocb * 76 + qc * 9 + pos];
                    a[mi][1] = w_s[(ocb + 8) * 76 + qc * 9 + pos];
                    a[mi][2] = w_s[ocb * 76 + (qc + 4) * 9 + pos];
                    a[mi][3] = w_s[(ocb + 8) * 76 + (qc + 4) * 9 + pos];
                }
#pragma unroll
                for (int j = 0; j < 8; j++) {
                    int col = j * 8 + qr + kx;
                    unsigned b[2] = {in_s[qc * PS + rowoff + col],
                                     in_s[(qc + 4) * PS + rowoff + col]};
                    mma_tf32(acc[0][j], a[0], b);
                    mma_tf32(acc[1][j], a[1], b);
                    mma_tf32(acc[2][j], a[2], b);
                    mma_tf32(acc[3][j], a[3], b);
                }
            }
        }
        pi ^= 1;
    }

    // epilogue: bias, store y, BN partial sums
    int row = y0 + wn;
#pragma unroll
    for (int mi = 0; mi < 4; mi++) {
#pragma unroll
        for (int half = 0; half < 2; half++) {
            int ocl = mi * 16 + half * 8 + qr;
            int oc = oc0 + ocl;
            float bias = cb[oc];
            float s0 = 0.f, s1 = 0.f;
#pragma unroll
            for (int j = 0; j < 8; j++) {
#pragma unroll
                for (int cc = 0; cc < 2; cc++) {
                    float v = acc[mi][j][half * 2 + cc] + bias;
                    int col = j * 8 + qc * 2 + cc;
                    g_y[(((size_t)n * OUTC + oc) * OH + row) * OW + col] = v;
                    s0 += v;
                    s1 += v * v;
                }
            }
            s0 += __shfl_xor_sync(0xffffffffu, s0, 1);
            s0 += __shfl_xor_sync(0xffffffffu, s0, 2);
            s1 += __shfl_xor_sync(0xffffffffu, s1, 1);
            s1 += __shfl_xor_sync(0xffffffffu, s1, 2);
            if (qc == 0) {
                atomicAdd(&rs[ocl], s0);
                atomicAdd(&rq[ocl], s1);
            }
        }
    }
    __syncthreads();
    if (tid < 64) {
        atomicAdd(&g_bnsum[oc0 + tid], rs[tid]);
        atomicAdd(&g_bnsq[oc0 + tid], rq[tid]);
    }
}

// ---------------- small kernels ----------------
__global__ void zero_kernel() {
    int t = threadIdx.x;
    g_bnsum[t] = 0.f;
    g_bnsq[t] = 0.f;
}

__global__ void bnstats_kernel(const float* __restrict__ bn_g, const float* __restrict__ bn_b) {
    int c = threadIdx.x;
    float cnt = (float)(BB * OH * OW);
    float mean = g_bnsum[c] / cnt;
    float var = g_bnsq[c] / cnt - mean * mean;
    float inv = rsqrtf(var + 1e-5f);
    float sc = bn_g[c] * inv;
    g_bnscale[c] = sc;
    g_bnshift[c] = bn_b[c] - mean * sc;
}

__global__ void bnorm_kernel(float* __restrict__ out) {
    int i4 = blockIdx.x * blockDim.x + threadIdx.x;
    const int total4 = BB * OUTC * OH * OW / 4;
    if (i4 >= total4) return;
    int base = i4 * 4;
    int oc = (base >> 12) & (OUTC - 1);
    float sc = g_bnscale[oc], sh = g_bnshift[oc];
    float4 v = *(const float4*)&g_y[base];
    float4 r;
    r.x = fmaxf(v.x * sc + sh, 0.f);
    r.y = fmaxf(v.y * sc + sh, 0.f);
    r.z = fmaxf(v.z * sc + sh, 0.f);
    r.w = fmaxf(v.w * sc + sh, 0.f);
    *(float4*)&out[base] = r;
}

// ---------------- launcher ----------------
extern "C" void kernel_launch(void* const* d_in, const int* in_sizes, int n_in,
                              void* d_out, int out_size) {
    const float* x    = (const float*)d_in[0];
    const float* s    = (const float*)d_in[1];
    const float* up_w = (const float*)d_in[2];
    const float* up_b = (const float*)d_in[3];
    const float* wq   = (const float*)d_in[4];
    const float* wkl  = (const float*)d_in[5];
    const float* wkr  = (const float*)d_in[6];
    const float* c1_w = (const float*)d_in[7];
    const float* c1_b = (const float*)d_in[8];
    const float* bn_g = (const float*)d_in[9];
    const float* bn_b = (const float*)d_in[10];
    float* out = (float*)d_out;

    const int conv_smem = (2 * INW + 2 * WW_) * 4 + 128 * 4;  // 87040 bytes
    cudaFuncSetAttribute(conv_mma_kernel,
                         cudaFuncAttributeMaxDynamicSharedMemorySize, conv_smem);
    const int ao_smem = (2 * AOA + 2 * AOB * 2) * 4;          // 76800 bytes
    cudaFuncSetAttribute(attnout_mma_kernel,
                         cudaFuncAttributeMaxDynamicSharedMemorySize, ao_smem);

    proj_mma_kernel<<<dim3(8, 1, NS * 3), 256>>>(x, wq, wkl, wkr);
    sumz_kernel<<<dim3(NS, 2), 128>>>();
    kv_mma_kernel<<<dim3(2, 4, NS * 2), 256>>>(x);
    attnout_mma_kernel<<<dim3(8, 4, NS), 256, ao_smem>>>(x);
    convt_mma_kernel<<<dim3(16, 4, BB), 256>>>(x, up_w, up_b, s);
    zero_kernel<<<1, OUTC>>>();
    conv_mma_kernel<<<dim3(8, 4, BB), 256, conv_smem>>>(s, c1_w, c1_b);
    bnstats_kernel<<<1, OUTC>>>(bn_g, bn_b);
    int total4 = BB * OUTC * OH * OW / 4;
    bnorm_kernel<<<(total4 + 255) / 256, 256>>>(out);
}